// round 8
// baseline (speedup 1.0000x reference)
#include <cuda_runtime.h>
#include <cuda_bf16.h>
#include <math.h>
#include <stdint.h>

#define N_  4
#define T_  4096
#define D_  1024
#define H_  1536
#define M_  (N_*T_)       // 16384 rows
#define G2H (2*H_)        // 3072
#define TC  128           // scan chunk length
#define NC  (T_/TC)       // 32 chunks

// -------- scratch (device globals; no allocation allowed) --------
__device__ __align__(256) float g_gx  [(size_t)M_*G2H];   // GEMM1 out; gate half = gelu(gate)
__device__ __align__(256) float g_xbc [(size_t)M_*H_];    // conv output (fp32)
__device__ __align__(256) float g_alpha[(size_t)M_*H_];
__device__ __align__(256) float g_xs  [(size_t)M_*H_];    // xs, then gelu(gate)*h after scan p3
__device__ __align__(256) float g_cA  [N_*NC*H_];
__device__ __align__(256) float g_cB  [N_*NC*H_];
// prepacked weight bf16 hi/lo planes
__device__ __align__(256) __nv_bfloat16 g_wih[(size_t)G2H*D_];
__device__ __align__(256) __nv_bfloat16 g_wil[(size_t)G2H*D_];
__device__ __align__(256) __nv_bfloat16 g_wgh[(size_t)G2H*H_];  // rows permuted for EPI2
__device__ __align__(256) __nv_bfloat16 g_wgl[(size_t)G2H*H_];
__device__ __align__(256) __nv_bfloat16 g_woh[(size_t)D_*H_];
__device__ __align__(256) __nv_bfloat16 g_wol[(size_t)D_*H_];

// ======================= helpers =======================
__device__ __forceinline__ uint32_t smem_u32(const void* p) {
    uint32_t a;
    asm("{ .reg .u64 t; cvta.to.shared.u64 t, %1; cvt.u32.u64 %0, t; }" : "=r"(a) : "l"(p));
    return a;
}
__device__ __forceinline__ void ldmx4(uint32_t* r, uint32_t a) {
    asm volatile("ldmatrix.sync.aligned.m8n8.x4.shared.b16 {%0,%1,%2,%3}, [%4];"
        : "=r"(r[0]), "=r"(r[1]), "=r"(r[2]), "=r"(r[3]) : "r"(a));
}
__device__ __forceinline__ void mma16816(float* d, const uint32_t* a, const uint32_t* b) {
    asm volatile("mma.sync.aligned.m16n8k16.row.col.f32.bf16.bf16.f32 "
        "{%0,%1,%2,%3}, {%4,%5,%6,%7}, {%8,%9}, {%0,%1,%2,%3};"
        : "+f"(d[0]), "+f"(d[1]), "+f"(d[2]), "+f"(d[3])
        : "r"(a[0]), "r"(a[1]), "r"(a[2]), "r"(a[3]), "r"(b[0]), "r"(b[1]));
}
__device__ __forceinline__ void cpa16(uint32_t dst, const void* src) {
    asm volatile("cp.async.cg.shared.global [%0], [%1], 16;" :: "r"(dst), "l"(src));
}
#define CP_COMMIT() asm volatile("cp.async.commit_group;" ::: "memory")
#define CP_WAIT0()  asm volatile("cp.async.wait_group 0;" ::: "memory")
__device__ __forceinline__ float sigmoidf_(float v) { return 1.f / (1.f + expf(-v)); }
__device__ __forceinline__ void split_bf(float v, __nv_bfloat16& h, __nv_bfloat16& l) {
    h = __float2bfloat16(v);
    l = __float2bfloat16(v - __bfloat162float(h));
}

// ================== bf16x3 mma GEMM ==================
// Block tile 128x128x32, 256 threads (8 warps: 4(m) x 2(n)), warp tile 32x64.
// A: fp32 LDG + split + STS (latency hidden behind compute). B: prepacked bf16
// planes via cp.async (wait after compute). 2-stage, 81920B -> 2 CTAs/SM.
#define BKB    80
#define AH_OFF 0
#define AL_OFF 10240
#define BH_OFF 20480
#define BL_OFF 30720
#define STAGE  40960
#define GEMM_SMEM (2*STAGE)   // 81920

__device__ __forceinline__ void issue_B(uint32_t stg, int tid, int k0, int K,
    const __nv_bfloat16* __restrict__ Bh, const __nv_bfloat16* __restrict__ Bl)
{
    const int seg = tid & 3;
    const int r0 = tid >> 2;        // 0..63
#pragma unroll
    for (int it = 0; it < 2; it++) {
        const int row = r0 + it * 64;
        const size_t go = (size_t)row * K + k0 + seg * 8;
        const uint32_t so = (uint32_t)(row * BKB + seg * 16);
        cpa16(stg + BH_OFF + so, Bh + go);
        cpa16(stg + BL_OFF + so, Bl + go);
    }
}

__device__ __forceinline__ void store_splitA(char* stg, int tid, const float4* r) {
#pragma unroll
    for (int i = 0; i < 4; i++) {
        int idx = i * 256 + tid;
        int row = idx >> 3, c4 = idx & 7;
        float4 f = r[i];
        __nv_bfloat16 h0, l0, h1, l1, h2, l2, h3, l3;
        split_bf(f.x, h0, l0); split_bf(f.y, h1, l1);
        split_bf(f.z, h2, l2); split_bf(f.w, h3, l3);
        uint32_t off = (uint32_t)(row * BKB + c4 * 8);
        __nv_bfloat16 hv[4] = {h0, h1, h2, h3};
        __nv_bfloat16 lv[4] = {l0, l1, l2, l3};
        *(uint2*)(stg + AH_OFF + off) = *(uint2*)hv;
        *(uint2*)(stg + AL_OFF + off) = *(uint2*)lv;
    }
}

__device__ __forceinline__ void compute_kt(float acc[2][8][4], uint32_t sa, uint32_t sbb, int kt) {
    uint32_t ah[2][4], al[2][4], bh[4][4], bl[4][4];
#pragma unroll
    for (int mt = 0; mt < 2; mt++) {
        ldmx4(ah[mt], sa + mt * (16 * BKB) + kt * 32);
        ldmx4(al[mt], sa + AL_OFF + mt * (16 * BKB) + kt * 32);
    }
#pragma unroll
    for (int n2 = 0; n2 < 4; n2++) {
        ldmx4(bh[n2], sbb + n2 * (16 * BKB) + kt * 32);
        ldmx4(bl[n2], sbb + (BL_OFF - BH_OFF) + n2 * (16 * BKB) + kt * 32);
    }
#pragma unroll
    for (int mt = 0; mt < 2; mt++)
#pragma unroll
        for (int nt = 0; nt < 8; nt++) {
            uint32_t* bph = &bh[nt >> 1][(nt & 1) * 2];
            uint32_t* bpl = &bl[nt >> 1][(nt & 1) * 2];
            mma16816(acc[mt][nt], ah[mt], bph);
            mma16816(acc[mt][nt], ah[mt], bpl);
            mma16816(acc[mt][nt], al[mt], bph);
        }
}

// EPI: 0 = plain, 1 = gelu on cols < H_, 2 = fused ew (alpha/xs)
template<int EPI>
__global__ __launch_bounds__(256)
void gemm_mma(const float* __restrict__ A,
              const __nv_bfloat16* __restrict__ Bh, const __nv_bfloat16* __restrict__ Bl,
              float* __restrict__ C,
              const float* __restrict__ xbc, const float* __restrict__ bg,
              const float* __restrict__ fbase,
              float* __restrict__ alpha_o, float* __restrict__ xs_o,
              int K, int ldc)
{
    extern __shared__ char sm[];
    const int tid = threadIdx.x;
    const int lid = tid & 31, wid = tid >> 5;
    const int wm = wid >> 1, wn = wid & 1;
    const int bm = blockIdx.y * 128;
    const int bn = blockIdx.x * 128;

    const int rbase = tid >> 3, c4 = tid & 7;
    const float* Arow[4];
#pragma unroll
    for (int i = 0; i < 4; i++)
        Arow[i] = A + (size_t)(bm + rbase + i * 32) * K + c4 * 4;
    const __nv_bfloat16* Bhb = Bh + (size_t)bn * K;
    const __nv_bfloat16* Blb = Bl + (size_t)bn * K;

    float acc[2][8][4];
#pragma unroll
    for (int i = 0; i < 2; i++)
#pragma unroll
        for (int j = 0; j < 8; j++)
#pragma unroll
            for (int q = 0; q < 4; q++) acc[i][j][q] = 0.f;

    // prologue: chunk 0
    issue_B(smem_u32(sm), tid, 0, K, Bhb, Blb);
    CP_COMMIT();
    float4 ra[4];
#pragma unroll
    for (int i = 0; i < 4; i++) ra[i] = *(const float4*)(Arow[i]);
    store_splitA(sm, tid, ra);
    CP_WAIT0();
    __syncthreads();

    const uint32_t sb = smem_u32(sm);
    const uint32_t a_base = sb + (uint32_t)((wm * 32 + (lid & 15)) * BKB + ((lid >> 4) & 1) * 16);
    const uint32_t b_base = sb + BH_OFF +
        (uint32_t)((wn * 64 + (lid & 7) + ((lid >> 4) & 1) * 8) * BKB + ((lid >> 3) & 1) * 16);

    const int KT = K >> 5;
    for (int c = 0; c < KT; c++) {
        const int cur = c & 1;
        const bool more = (c + 1 < KT);
        if (more) {
            issue_B(sb + ((c + 1) & 1) * STAGE, tid, (c + 1) * 32, K, Bhb, Blb);
            CP_COMMIT();
#pragma unroll
            for (int i = 0; i < 4; i++) ra[i] = *(const float4*)(Arow[i] + (c + 1) * 32);
        }
        const uint32_t sa  = a_base + cur * STAGE;
        const uint32_t sbb = b_base + cur * STAGE;
        compute_kt(acc, sa, sbb, 0);
        compute_kt(acc, sa, sbb, 1);
        if (more) {
            store_splitA(sm + ((c + 1) & 1) * STAGE, tid, ra);
            CP_WAIT0();
        }
        __syncthreads();
    }

    const int r0 = bm + wm * 32 + (lid >> 2);

    if (EPI == 2) {
        // fused ew: output cols interleaved (forget_h, inp_h); permutation baked in W_g pack
        const int hbase = (bn >> 1) + wn * 32 + (lid & 3);
        float sp8[8], bgf[8], bgi[8];
#pragma unroll
        for (int nt = 0; nt < 8; nt++) {
            int h = hbase + nt * 4;
            float fb = fbase[h];
            sp8[nt] = fmaxf(fb, 0.f) + log1pf(expf(-fabsf(fb)));
            bgf[nt] = bg[h]; bgi[nt] = bg[H_ + h];
        }
#pragma unroll
        for (int mt = 0; mt < 2; mt++) {
            int row = r0 + mt * 16;
#pragma unroll
            for (int nt = 0; nt < 8; nt++) {
                int h = hbase + nt * 4;
#pragma unroll
                for (int half = 0; half < 2; half++) {
                    int rr = row + half * 8;
                    float forget = acc[mt][nt][half * 2 + 0] + bgf[nt];
                    float inp    = acc[mt][nt][half * 2 + 1] + bgi[nt];
                    float a = expf(-8.f * sp8[nt] * sigmoidf_(forget));
                    float beta = sqrtf(1.f - a * a + 1e-6f);
                    size_t ix = (size_t)rr * H_ + h;
                    alpha_o[ix] = a;
                    xs_o[ix] = beta * sigmoidf_(inp) * xbc[ix];
                }
            }
        }
        return;
    }

    const bool dg = (EPI == 1) && (bn < H_);
    const int cbase = bn + wn * 64 + (lid & 3) * 2;
#pragma unroll
    for (int mt = 0; mt < 2; mt++) {
        const int row = r0 + mt * 16;
#pragma unroll
        for (int nt = 0; nt < 8; nt++) {
            const int col = cbase + nt * 8;
            float2 v0 = make_float2(acc[mt][nt][0], acc[mt][nt][1]);
            float2 v1 = make_float2(acc[mt][nt][2], acc[mt][nt][3]);
            if (dg) {
                v0.x = 0.5f * v0.x * (1.f + erff(v0.x * 0.70710678118654752f));
                v0.y = 0.5f * v0.y * (1.f + erff(v0.y * 0.70710678118654752f));
                v1.x = 0.5f * v1.x * (1.f + erff(v1.x * 0.70710678118654752f));
                v1.y = 0.5f * v1.y * (1.f + erff(v1.y * 0.70710678118654752f));
            }
            *(float2*)(C + (size_t)row * ldc + col) = v0;
            *(float2*)(C + (size_t)(row + 8) * ldc + col) = v1;
        }
    }
}

// -------- weight packing --------
__global__ void pack2(const float* __restrict__ s, __nv_bfloat16* __restrict__ hi,
                      __nv_bfloat16* __restrict__ lo, long long n4)
{
    long long i = (long long)blockIdx.x * blockDim.x + threadIdx.x;
    if (i >= n4) return;
    float4 f = *(const float4*)(s + i * 4);
    __nv_bfloat16 h[4], l[4];
    split_bf(f.x, h[0], l[0]); split_bf(f.y, h[1], l[1]);
    split_bf(f.z, h[2], l[2]); split_bf(f.w, h[3], l[3]);
    *(uint2*)(hi + i * 4) = *(uint2*)h;
    *(uint2*)(lo + i * 4) = *(uint2*)l;
}

// pack W_g with row permutation: packed row r = src row (r&1)*H_ + (r>>1)
__global__ void pack_wg(const float* __restrict__ s, __nv_bfloat16* __restrict__ hi,
                        __nv_bfloat16* __restrict__ lo)
{
    int idx = blockIdx.x * blockDim.x + threadIdx.x;
    if (idx >= G2H * (H_ / 4)) return;
    int r = idx / (H_ / 4);
    int c = (idx % (H_ / 4)) * 4;
    int sr = (r & 1) * H_ + (r >> 1);
    float4 f = *(const float4*)(s + (size_t)sr * H_ + c);
    __nv_bfloat16 h[4], l[4];
    split_bf(f.x, h[0], l[0]); split_bf(f.y, h[1], l[1]);
    split_bf(f.z, h[2], l[2]); split_bf(f.w, h[3], l[3]);
    *(uint2*)(hi + (size_t)r * H_ + c) = *(uint2*)h;
    *(uint2*)(lo + (size_t)r * H_ + c) = *(uint2*)l;
}

// -------- depthwise causal conv K=4 --------
__global__ void conv_kernel(const float* __restrict__ cw, const float* __restrict__ cb)
{
    long long idx = (long long)blockIdx.x * blockDim.x + threadIdx.x;
    if (idx >= (long long)M_ * H_) return;
    int h = (int)(idx % H_);
    long long m = idx / H_;
    int t = (int)(m % T_);
    long long n = m / T_;
    float acc = cb[h];
    const float* w = cw + h * 4;
#pragma unroll
    for (int k = 0; k < 4; k++) {
        int tt = t - 3 + k;
        if (tt >= 0)
            acc = fmaf(w[k], g_gx[((size_t)(n * T_ + tt)) * G2H + H_ + h], acc);
    }
    g_xbc[idx] = acc;
}

// -------- chunked linear scan --------
__global__ void scan_p1()
{
    int h = blockIdx.x * 128 + threadIdx.x;
    int c = blockIdx.y, n = blockIdx.z;
    size_t base = ((size_t)(n * T_ + c * TC)) * H_ + h;
    float A = 1.f, Bv = 0.f;
#pragma unroll 4
    for (int t = 0; t < TC; t++) {
        float a = g_alpha[base + (size_t)t * H_];
        float x = g_xs   [base + (size_t)t * H_];
        Bv = fmaf(a, Bv, x);
        A *= a;
    }
    int ci = (n * NC + c) * H_ + h;
    g_cA[ci] = A;
    g_cB[ci] = Bv;
}

__global__ void scan_p2()
{
    int h = blockIdx.x * 128 + threadIdx.x;
    int n = blockIdx.y;
    float carry = 0.f;
    for (int c = 0; c < NC; c++) {
        int i = (n * NC + c) * H_ + h;
        float a = g_cA[i], b = g_cB[i];
        g_cB[i] = carry;
        carry = fmaf(a, carry, b);
    }
}

__global__ void scan_p3()
{
    int h = blockIdx.x * 128 + threadIdx.x;
    int c = blockIdx.y, n = blockIdx.z;
    size_t base  = ((size_t)(n * T_ + c * TC)) * H_ + h;
    size_t gbase = ((size_t)(n * T_ + c * TC)) * G2H + h;
    float hp = g_cB[(n * NC + c) * H_ + h];
#pragma unroll 4
    for (int t = 0; t < TC; t++) {
        float a = g_alpha[base + (size_t)t * H_];
        float x = g_xs   [base + (size_t)t * H_];
        hp = fmaf(a, hp, x);
        float g = g_gx[gbase + (size_t)t * G2H];   // gelu(gate)
        g_xs[base + (size_t)t * H_] = hp * g;
    }
}

// -------- launch --------
extern "C" void kernel_launch(void* const* d_in, const int* in_sizes, int n_in,
                              void* d_out, int out_size)
{
    const float* x      = (const float*)d_in[0];
    const float* W_in   = (const float*)d_in[1];
    const float* conv_w = (const float*)d_in[2];
    const float* conv_b = (const float*)d_in[3];
    const float* W_g    = (const float*)d_in[4];
    const float* b_g    = (const float*)d_in[5];
    const float* fbase  = (const float*)d_in[6];
    const float* W_out  = (const float*)d_in[7];
    float* out = (float*)d_out;

    float *gx, *xbc, *alp, *xs;
    __nv_bfloat16 *wih, *wil, *wgh, *wgl, *woh, *wol;
    cudaGetSymbolAddress((void**)&gx,  g_gx);
    cudaGetSymbolAddress((void**)&xbc, g_xbc);
    cudaGetSymbolAddress((void**)&alp, g_alpha);
    cudaGetSymbolAddress((void**)&xs,  g_xs);
    cudaGetSymbolAddress((void**)&wih, g_wih);
    cudaGetSymbolAddress((void**)&wil, g_wil);
    cudaGetSymbolAddress((void**)&wgh, g_wgh);
    cudaGetSymbolAddress((void**)&wgl, g_wgl);
    cudaGetSymbolAddress((void**)&woh, g_woh);
    cudaGetSymbolAddress((void**)&wol, g_wol);

    cudaFuncSetAttribute(gemm_mma<0>, cudaFuncAttributeMaxDynamicSharedMemorySize, GEMM_SMEM);
    cudaFuncSetAttribute(gemm_mma<1>, cudaFuncAttributeMaxDynamicSharedMemorySize, GEMM_SMEM);
    cudaFuncSetAttribute(gemm_mma<2>, cudaFuncAttributeMaxDynamicSharedMemorySize, GEMM_SMEM);

    const long long tot = (long long)M_ * H_;
    const int EB = 256;
    const int eg = (int)((tot + EB - 1) / EB);

    // 0) pack weights
    pack2<<<(G2H*D_/4 + 255)/256, 256>>>(W_in, wih, wil, (long long)G2H*D_/4);
    pack_wg<<<(G2H*(H_/4) + 255)/256, 256>>>(W_g, wgh, wgl);
    pack2<<<(D_*H_/4 + 255)/256, 256>>>(W_out, woh, wol, (long long)D_*H_/4);

    // 1) gx = x @ W_in^T; gelu fused on gate half
    gemm_mma<1><<<dim3(G2H/128, M_/128), 256, GEMM_SMEM>>>(
        x, wih, wil, gx, nullptr, nullptr, nullptr, nullptr, nullptr, D_, G2H);
    // 2) depthwise causal conv
    conv_kernel<<<eg, EB>>>(conv_w, conv_b);
    // 3) fused ew GEMM -> alpha, xs
    gemm_mma<2><<<dim3(G2H/128, M_/128), 256, GEMM_SMEM>>>(
        xbc, wgh, wgl, nullptr, xbc, b_g, fbase, alp, xs, H_, 0);
    // 4) scan
    scan_p1<<<dim3(H_/128, NC, N_), 128>>>();
    scan_p2<<<dim3(H_/128, N_), 128>>>();
    scan_p3<<<dim3(H_/128, NC, N_), 128>>>();
    // 5) out = (gelu(gate)*h) @ W_out^T
    gemm_mma<0><<<dim3(D_/128, M_/128), 256, GEMM_SMEM>>>(
        xs, woh, wol, out, nullptr, nullptr, nullptr, nullptr, nullptr, H_, D_);
}

// round 9
// speedup vs baseline: 1.2457x; 1.2457x over previous
#include <cuda_runtime.h>
#include <cuda_bf16.h>
#include <math.h>
#include <stdint.h>

#define N_  4
#define T_  4096
#define D_  1024
#define H_  1536
#define M_  (N_*T_)       // 16384 rows
#define G2H (2*H_)        // 3072
#define TC  128           // scan chunk length
#define NC  (T_/TC)       // 32 chunks

// -------- scratch (device globals; no allocation allowed) --------
__device__ __align__(256) float g_gx  [(size_t)M_*G2H];   // GEMM1 out; gate half = gelu(gate)
__device__ __align__(256) float g_xbc [(size_t)M_*H_];    // conv output (fp32)
__device__ __align__(256) float g_alpha[(size_t)M_*H_];
__device__ __align__(256) float g_xs  [(size_t)M_*H_];    // xs, then gelu(gate)*h after scan p3
__device__ __align__(256) float g_cA  [N_*NC*H_];
__device__ __align__(256) float g_cB  [N_*NC*H_];
// prepacked weight bf16 hi/lo planes
__device__ __align__(256) __nv_bfloat16 g_wih[(size_t)G2H*D_];
__device__ __align__(256) __nv_bfloat16 g_wil[(size_t)G2H*D_];
__device__ __align__(256) __nv_bfloat16 g_wgh[(size_t)G2H*H_];  // rows permuted for EPI2
__device__ __align__(256) __nv_bfloat16 g_wgl[(size_t)G2H*H_];
__device__ __align__(256) __nv_bfloat16 g_woh[(size_t)D_*H_];
__device__ __align__(256) __nv_bfloat16 g_wol[(size_t)D_*H_];

// ======================= helpers =======================
__device__ __forceinline__ uint32_t smem_u32(const void* p) {
    uint32_t a;
    asm("{ .reg .u64 t; cvta.to.shared.u64 t, %1; cvt.u32.u64 %0, t; }" : "=r"(a) : "l"(p));
    return a;
}
__device__ __forceinline__ void ldmx4(uint32_t* r, uint32_t a) {
    asm volatile("ldmatrix.sync.aligned.m8n8.x4.shared.b16 {%0,%1,%2,%3}, [%4];"
        : "=r"(r[0]), "=r"(r[1]), "=r"(r[2]), "=r"(r[3]) : "r"(a));
}
__device__ __forceinline__ void mma16816(float* d, const uint32_t* a, const uint32_t* b) {
    asm volatile("mma.sync.aligned.m16n8k16.row.col.f32.bf16.bf16.f32 "
        "{%0,%1,%2,%3}, {%4,%5,%6,%7}, {%8,%9}, {%0,%1,%2,%3};"
        : "+f"(d[0]), "+f"(d[1]), "+f"(d[2]), "+f"(d[3])
        : "r"(a[0]), "r"(a[1]), "r"(a[2]), "r"(a[3]), "r"(b[0]), "r"(b[1]));
}
__device__ __forceinline__ void cpa16(uint32_t dst, const void* src) {
    asm volatile("cp.async.cg.shared.global [%0], [%1], 16;" :: "r"(dst), "l"(src));
}
#define CP_COMMIT() asm volatile("cp.async.commit_group;" ::: "memory")
#define CP_WAIT0()  asm volatile("cp.async.wait_group 0;" ::: "memory")
__device__ __forceinline__ float sigmoidf_(float v) { return 1.f / (1.f + expf(-v)); }
__device__ __forceinline__ void split_bf(float v, __nv_bfloat16& h, __nv_bfloat16& l) {
    h = __float2bfloat16(v);
    l = __float2bfloat16(v - __bfloat162float(h));
}

// ================== bf16x3 mma GEMM ==================
// Block tile 128x128x32, 256 threads (8 warps: 4(m) x 2(n)), warp tile 32x64.
// A: fp32 LDG + split + STS. B: prepacked bf16 planes via cp.async.
// __launch_bounds__(256,2) caps regs at 128 -> 2 CTAs/SM (smem 2x81920 fits).
#define BKB    80
#define AH_OFF 0
#define AL_OFF 10240
#define BH_OFF 20480
#define BL_OFF 30720
#define STAGE  40960
#define GEMM_SMEM (2*STAGE)   // 81920

__device__ __forceinline__ void issue_B(uint32_t stg, int tid, int k0, int K,
    const __nv_bfloat16* __restrict__ Bh, const __nv_bfloat16* __restrict__ Bl)
{
    const int seg = tid & 3;
    const int r0 = tid >> 2;        // 0..63
#pragma unroll
    for (int it = 0; it < 2; it++) {
        const int row = r0 + it * 64;
        const size_t go = (size_t)row * K + k0 + seg * 8;
        const uint32_t so = (uint32_t)(row * BKB + seg * 16);
        cpa16(stg + BH_OFF + so, Bh + go);
        cpa16(stg + BL_OFF + so, Bl + go);
    }
}

__device__ __forceinline__ void store_splitA(char* stg, int tid, const float4* r) {
#pragma unroll
    for (int i = 0; i < 4; i++) {
        int idx = i * 256 + tid;
        int row = idx >> 3, c4 = idx & 7;
        float4 f = r[i];
        __nv_bfloat16 h0, l0, h1, l1, h2, l2, h3, l3;
        split_bf(f.x, h0, l0); split_bf(f.y, h1, l1);
        split_bf(f.z, h2, l2); split_bf(f.w, h3, l3);
        uint32_t off = (uint32_t)(row * BKB + c4 * 8);
        __nv_bfloat16 hv[4] = {h0, h1, h2, h3};
        __nv_bfloat16 lv[4] = {l0, l1, l2, l3};
        *(uint2*)(stg + AH_OFF + off) = *(uint2*)hv;
        *(uint2*)(stg + AL_OFF + off) = *(uint2*)lv;
    }
}

__device__ __forceinline__ void compute_kt(float acc[2][8][4], uint32_t sa, uint32_t sbb, int kt) {
    uint32_t ah[2][4], al[2][4], bh[4][4], bl[4][4];
#pragma unroll
    for (int mt = 0; mt < 2; mt++) {
        ldmx4(ah[mt], sa + mt * (16 * BKB) + kt * 32);
        ldmx4(al[mt], sa + AL_OFF + mt * (16 * BKB) + kt * 32);
    }
#pragma unroll
    for (int n2 = 0; n2 < 4; n2++) {
        ldmx4(bh[n2], sbb + n2 * (16 * BKB) + kt * 32);
        ldmx4(bl[n2], sbb + (BL_OFF - BH_OFF) + n2 * (16 * BKB) + kt * 32);
    }
#pragma unroll
    for (int mt = 0; mt < 2; mt++)
#pragma unroll
        for (int nt = 0; nt < 8; nt++) {
            uint32_t* bph = &bh[nt >> 1][(nt & 1) * 2];
            uint32_t* bpl = &bl[nt >> 1][(nt & 1) * 2];
            mma16816(acc[mt][nt], ah[mt], bph);
            mma16816(acc[mt][nt], ah[mt], bpl);
            mma16816(acc[mt][nt], al[mt], bph);
        }
}

// EPI: 0 = plain, 1 = gelu on cols < H_, 2 = fused ew (alpha/xs)
template<int EPI>
__global__ __launch_bounds__(256, 2)
void gemm_mma(const float* __restrict__ A,
              const __nv_bfloat16* __restrict__ Bh, const __nv_bfloat16* __restrict__ Bl,
              float* __restrict__ C,
              const float* __restrict__ xbc, const float* __restrict__ bg,
              const float* __restrict__ fbase,
              float* __restrict__ alpha_o, float* __restrict__ xs_o,
              int K, int ldc)
{
    extern __shared__ char sm[];
    const int tid = threadIdx.x;
    const int lid = tid & 31, wid = tid >> 5;
    const int wm = wid >> 1, wn = wid & 1;
    const int bm = blockIdx.y * 128;
    const int bn = blockIdx.x * 128;

    const int rbase = tid >> 3, c4 = tid & 7;
    const float* Arow[4];
#pragma unroll
    for (int i = 0; i < 4; i++)
        Arow[i] = A + (size_t)(bm + rbase + i * 32) * K + c4 * 4;
    const __nv_bfloat16* Bhb = Bh + (size_t)bn * K;
    const __nv_bfloat16* Blb = Bl + (size_t)bn * K;

    float acc[2][8][4];
#pragma unroll
    for (int i = 0; i < 2; i++)
#pragma unroll
        for (int j = 0; j < 8; j++)
#pragma unroll
            for (int q = 0; q < 4; q++) acc[i][j][q] = 0.f;

    // prologue: chunk 0
    issue_B(smem_u32(sm), tid, 0, K, Bhb, Blb);
    CP_COMMIT();
    float4 ra[4];
#pragma unroll
    for (int i = 0; i < 4; i++) ra[i] = *(const float4*)(Arow[i]);
    store_splitA(sm, tid, ra);
    CP_WAIT0();
    __syncthreads();

    const uint32_t sb = smem_u32(sm);
    const uint32_t a_base = sb + (uint32_t)((wm * 32 + (lid & 15)) * BKB + ((lid >> 4) & 1) * 16);
    const uint32_t b_base = sb + BH_OFF +
        (uint32_t)((wn * 64 + (lid & 7) + ((lid >> 4) & 1) * 8) * BKB + ((lid >> 3) & 1) * 16);

    const int KT = K >> 5;
    for (int c = 0; c < KT; c++) {
        const int cur = c & 1;
        const bool more = (c + 1 < KT);
        if (more) {
            issue_B(sb + ((c + 1) & 1) * STAGE, tid, (c + 1) * 32, K, Bhb, Blb);
            CP_COMMIT();
#pragma unroll
            for (int i = 0; i < 4; i++) ra[i] = *(const float4*)(Arow[i] + (c + 1) * 32);
        }
        const uint32_t sa  = a_base + cur * STAGE;
        const uint32_t sbb = b_base + cur * STAGE;
        compute_kt(acc, sa, sbb, 0);
        compute_kt(acc, sa, sbb, 1);
        if (more) {
            store_splitA(sm + ((c + 1) & 1) * STAGE, tid, ra);
            CP_WAIT0();
        }
        __syncthreads();
    }

    const int r0 = bm + wm * 32 + (lid >> 2);

    if (EPI == 2) {
        // fused ew: output cols interleaved (forget_h, inp_h); permutation baked in W_g pack
        const int hbase = (bn >> 1) + wn * 32 + (lid & 3);
        float sp8[8], bgf[8], bgi[8];
#pragma unroll
        for (int nt = 0; nt < 8; nt++) {
            int h = hbase + nt * 4;
            float fb = fbase[h];
            sp8[nt] = fmaxf(fb, 0.f) + log1pf(expf(-fabsf(fb)));
            bgf[nt] = bg[h]; bgi[nt] = bg[H_ + h];
        }
#pragma unroll
        for (int mt = 0; mt < 2; mt++) {
            int row = r0 + mt * 16;
#pragma unroll
            for (int nt = 0; nt < 8; nt++) {
                int h = hbase + nt * 4;
#pragma unroll
                for (int half = 0; half < 2; half++) {
                    int rr = row + half * 8;
                    float forget = acc[mt][nt][half * 2 + 0] + bgf[nt];
                    float inp    = acc[mt][nt][half * 2 + 1] + bgi[nt];
                    float a = expf(-8.f * sp8[nt] * sigmoidf_(forget));
                    float beta = sqrtf(1.f - a * a + 1e-6f);
                    size_t ix = (size_t)rr * H_ + h;
                    alpha_o[ix] = a;
                    xs_o[ix] = beta * sigmoidf_(inp) * xbc[ix];
                }
            }
        }
        return;
    }

    const bool dg = (EPI == 1) && (bn < H_);
    const int cbase = bn + wn * 64 + (lid & 3) * 2;
#pragma unroll
    for (int mt = 0; mt < 2; mt++) {
        const int row = r0 + mt * 16;
#pragma unroll
        for (int nt = 0; nt < 8; nt++) {
            const int col = cbase + nt * 8;
            float2 v0 = make_float2(acc[mt][nt][0], acc[mt][nt][1]);
            float2 v1 = make_float2(acc[mt][nt][2], acc[mt][nt][3]);
            if (dg) {
                v0.x = 0.5f * v0.x * (1.f + erff(v0.x * 0.70710678118654752f));
                v0.y = 0.5f * v0.y * (1.f + erff(v0.y * 0.70710678118654752f));
                v1.x = 0.5f * v1.x * (1.f + erff(v1.x * 0.70710678118654752f));
                v1.y = 0.5f * v1.y * (1.f + erff(v1.y * 0.70710678118654752f));
            }
            *(float2*)(C + (size_t)row * ldc + col) = v0;
            *(float2*)(C + (size_t)(row + 8) * ldc + col) = v1;
        }
    }
}

// -------- weight packing --------
__global__ void pack2(const float* __restrict__ s, __nv_bfloat16* __restrict__ hi,
                      __nv_bfloat16* __restrict__ lo, long long n4)
{
    long long i = (long long)blockIdx.x * blockDim.x + threadIdx.x;
    if (i >= n4) return;
    float4 f = *(const float4*)(s + i * 4);
    __nv_bfloat16 h[4], l[4];
    split_bf(f.x, h[0], l[0]); split_bf(f.y, h[1], l[1]);
    split_bf(f.z, h[2], l[2]); split_bf(f.w, h[3], l[3]);
    *(uint2*)(hi + i * 4) = *(uint2*)h;
    *(uint2*)(lo + i * 4) = *(uint2*)l;
}

// pack W_g with row permutation: packed row r = src row (r&1)*H_ + (r>>1)
__global__ void pack_wg(const float* __restrict__ s, __nv_bfloat16* __restrict__ hi,
                        __nv_bfloat16* __restrict__ lo)
{
    int idx = blockIdx.x * blockDim.x + threadIdx.x;
    if (idx >= G2H * (H_ / 4)) return;
    int r = idx / (H_ / 4);
    int c = (idx % (H_ / 4)) * 4;
    int sr = (r & 1) * H_ + (r >> 1);
    float4 f = *(const float4*)(s + (size_t)sr * H_ + c);
    __nv_bfloat16 h[4], l[4];
    split_bf(f.x, h[0], l[0]); split_bf(f.y, h[1], l[1]);
    split_bf(f.z, h[2], l[2]); split_bf(f.w, h[3], l[3]);
    *(uint2*)(hi + (size_t)r * H_ + c) = *(uint2*)h;
    *(uint2*)(lo + (size_t)r * H_ + c) = *(uint2*)l;
}

// -------- depthwise causal conv K=4 --------
__global__ void conv_kernel(const float* __restrict__ cw, const float* __restrict__ cb)
{
    long long idx = (long long)blockIdx.x * blockDim.x + threadIdx.x;
    if (idx >= (long long)M_ * H_) return;
    int h = (int)(idx % H_);
    long long m = idx / H_;
    int t = (int)(m % T_);
    long long n = m / T_;
    float acc = cb[h];
    const float* w = cw + h * 4;
#pragma unroll
    for (int k = 0; k < 4; k++) {
        int tt = t - 3 + k;
        if (tt >= 0)
            acc = fmaf(w[k], g_gx[((size_t)(n * T_ + tt)) * G2H + H_ + h], acc);
    }
    g_xbc[idx] = acc;
}

// -------- chunked linear scan --------
__global__ void scan_p1()
{
    int h = blockIdx.x * 128 + threadIdx.x;
    int c = blockIdx.y, n = blockIdx.z;
    size_t base = ((size_t)(n * T_ + c * TC)) * H_ + h;
    float A = 1.f, Bv = 0.f;
#pragma unroll 4
    for (int t = 0; t < TC; t++) {
        float a = g_alpha[base + (size_t)t * H_];
        float x = g_xs   [base + (size_t)t * H_];
        Bv = fmaf(a, Bv, x);
        A *= a;
    }
    int ci = (n * NC + c) * H_ + h;
    g_cA[ci] = A;
    g_cB[ci] = Bv;
}

__global__ void scan_p2()
{
    int h = blockIdx.x * 128 + threadIdx.x;
    int n = blockIdx.y;
    float carry = 0.f;
    for (int c = 0; c < NC; c++) {
        int i = (n * NC + c) * H_ + h;
        float a = g_cA[i], b = g_cB[i];
        g_cB[i] = carry;
        carry = fmaf(a, carry, b);
    }
}

__global__ void scan_p3()
{
    int h = blockIdx.x * 128 + threadIdx.x;
    int c = blockIdx.y, n = blockIdx.z;
    size_t base  = ((size_t)(n * T_ + c * TC)) * H_ + h;
    size_t gbase = ((size_t)(n * T_ + c * TC)) * G2H + h;
    float hp = g_cB[(n * NC + c) * H_ + h];
#pragma unroll 4
    for (int t = 0; t < TC; t++) {
        float a = g_alpha[base + (size_t)t * H_];
        float x = g_xs   [base + (size_t)t * H_];
        hp = fmaf(a, hp, x);
        float g = g_gx[gbase + (size_t)t * G2H];   // gelu(gate)
        g_xs[base + (size_t)t * H_] = hp * g;
    }
}

// -------- launch --------
extern "C" void kernel_launch(void* const* d_in, const int* in_sizes, int n_in,
                              void* d_out, int out_size)
{
    const float* x      = (const float*)d_in[0];
    const float* W_in   = (const float*)d_in[1];
    const float* conv_w = (const float*)d_in[2];
    const float* conv_b = (const float*)d_in[3];
    const float* W_g    = (const float*)d_in[4];
    const float* b_g    = (const float*)d_in[5];
    const float* fbase  = (const float*)d_in[6];
    const float* W_out  = (const float*)d_in[7];
    float* out = (float*)d_out;

    float *gx, *xbc, *alp, *xs;
    __nv_bfloat16 *wih, *wil, *wgh, *wgl, *woh, *wol;
    cudaGetSymbolAddress((void**)&gx,  g_gx);
    cudaGetSymbolAddress((void**)&xbc, g_xbc);
    cudaGetSymbolAddress((void**)&alp, g_alpha);
    cudaGetSymbolAddress((void**)&xs,  g_xs);
    cudaGetSymbolAddress((void**)&wih, g_wih);
    cudaGetSymbolAddress((void**)&wil, g_wil);
    cudaGetSymbolAddress((void**)&wgh, g_wgh);
    cudaGetSymbolAddress((void**)&wgl, g_wgl);
    cudaGetSymbolAddress((void**)&woh, g_woh);
    cudaGetSymbolAddress((void**)&wol, g_wol);

    cudaFuncSetAttribute(gemm_mma<0>, cudaFuncAttributeMaxDynamicSharedMemorySize, GEMM_SMEM);
    cudaFuncSetAttribute(gemm_mma<1>, cudaFuncAttributeMaxDynamicSharedMemorySize, GEMM_SMEM);
    cudaFuncSetAttribute(gemm_mma<2>, cudaFuncAttributeMaxDynamicSharedMemorySize, GEMM_SMEM);

    const long long tot = (long long)M_ * H_;
    const int EB = 256;
    const int eg = (int)((tot + EB - 1) / EB);

    // 0) pack weights
    pack2<<<(G2H*D_/4 + 255)/256, 256>>>(W_in, wih, wil, (long long)G2H*D_/4);
    pack_wg<<<(G2H*(H_/4) + 255)/256, 256>>>(W_g, wgh, wgl);
    pack2<<<(D_*H_/4 + 255)/256, 256>>>(W_out, woh, wol, (long long)D_*H_/4);

    // 1) gx = x @ W_in^T; gelu fused on gate half
    gemm_mma<1><<<dim3(G2H/128, M_/128), 256, GEMM_SMEM>>>(
        x, wih, wil, gx, nullptr, nullptr, nullptr, nullptr, nullptr, D_, G2H);
    // 2) depthwise causal conv
    conv_kernel<<<eg, EB>>>(conv_w, conv_b);
    // 3) fused ew GEMM -> alpha, xs
    gemm_mma<2><<<dim3(G2H/128, M_/128), 256, GEMM_SMEM>>>(
        xbc, wgh, wgl, nullptr, xbc, b_g, fbase, alp, xs, H_, 0);
    // 4) scan
    scan_p1<<<dim3(H_/128, NC, N_), 128>>>();
    scan_p2<<<dim3(H_/128, N_), 128>>>();
    scan_p3<<<dim3(H_/128, NC, N_), 128>>>();
    // 5) out = (gelu(gate)*h) @ W_out^T
    gemm_mma<0><<<dim3(D_/128, M_/128), 256, GEMM_SMEM>>>(
        xs, woh, wol, out, nullptr, nullptr, nullptr, nullptr, nullptr, H_, D_);
}

// round 10
// speedup vs baseline: 1.3458x; 1.0804x over previous
#include <cuda_runtime.h>
#include <cuda_bf16.h>
#include <math.h>
#include <stdint.h>

#define N_  4
#define T_  4096
#define D_  1024
#define H_  1536
#define M_  (N_*T_)       // 16384 rows
#define G2H (2*H_)        // 3072
#define TC  128           // scan chunk length
#define NC  (T_/TC)       // 32 chunks

// -------- scratch (device globals; no allocation allowed) --------
__device__ __align__(256) float g_gx  [(size_t)M_*G2H];   // GEMM1 out; gate half = gelu(gate)
__device__ __align__(256) float g_alpha[(size_t)M_*H_];
__device__ __align__(256) float g_xs  [(size_t)M_*H_];
__device__ __align__(256) float g_cA  [N_*NC*H_];
__device__ __align__(256) float g_cB  [N_*NC*H_];
// activation bf16 hi/lo planes
__device__ __align__(256) __nv_bfloat16 g_xh [(size_t)M_*D_];
__device__ __align__(256) __nv_bfloat16 g_xl [(size_t)M_*D_];
__device__ __align__(256) __nv_bfloat16 g_xbh[(size_t)M_*H_];   // conv out planes
__device__ __align__(256) __nv_bfloat16 g_xbl[(size_t)M_*H_];
__device__ __align__(256) __nv_bfloat16 g_yh [(size_t)M_*H_];   // gelu(gate)*h planes
__device__ __align__(256) __nv_bfloat16 g_yl [(size_t)M_*H_];
// weight bf16 hi/lo planes
__device__ __align__(256) __nv_bfloat16 g_wih[(size_t)G2H*D_];
__device__ __align__(256) __nv_bfloat16 g_wil[(size_t)G2H*D_];
__device__ __align__(256) __nv_bfloat16 g_wgh[(size_t)G2H*H_];  // rows permuted for EPI2
__device__ __align__(256) __nv_bfloat16 g_wgl[(size_t)G2H*H_];
__device__ __align__(256) __nv_bfloat16 g_woh[(size_t)D_*H_];
__device__ __align__(256) __nv_bfloat16 g_wol[(size_t)D_*H_];

// ======================= helpers =======================
__device__ __forceinline__ uint32_t smem_u32(const void* p) {
    uint32_t a;
    asm("{ .reg .u64 t; cvta.to.shared.u64 t, %1; cvt.u32.u64 %0, t; }" : "=r"(a) : "l"(p));
    return a;
}
__device__ __forceinline__ void ldmx4(uint32_t* r, uint32_t a) {
    asm volatile("ldmatrix.sync.aligned.m8n8.x4.shared.b16 {%0,%1,%2,%3}, [%4];"
        : "=r"(r[0]), "=r"(r[1]), "=r"(r[2]), "=r"(r[3]) : "r"(a));
}
__device__ __forceinline__ void mma16816(float* d, const uint32_t* a, const uint32_t* b) {
    asm volatile("mma.sync.aligned.m16n8k16.row.col.f32.bf16.bf16.f32 "
        "{%0,%1,%2,%3}, {%4,%5,%6,%7}, {%8,%9}, {%0,%1,%2,%3};"
        : "+f"(d[0]), "+f"(d[1]), "+f"(d[2]), "+f"(d[3])
        : "r"(a[0]), "r"(a[1]), "r"(a[2]), "r"(a[3]), "r"(b[0]), "r"(b[1]));
}
__device__ __forceinline__ void cpa16(uint32_t dst, const void* src) {
    asm volatile("cp.async.cg.shared.global [%0], [%1], 16;" :: "r"(dst), "l"(src));
}
#define CP_COMMIT()     asm volatile("cp.async.commit_group;" ::: "memory")
#define CP_WAIT(NN)     asm volatile("cp.async.wait_group %0;" :: "n"(NN) : "memory")
__device__ __forceinline__ float sigmoidf_(float v) { return 1.f / (1.f + expf(-v)); }
__device__ __forceinline__ void split_bf(float v, __nv_bfloat16& h, __nv_bfloat16& l) {
    h = __float2bfloat16(v);
    l = __float2bfloat16(v - __bfloat162float(h));
}

// ================== bf16x3 mma GEMM (all cp.async, 3-stage, swizzled) ==================
// Block tile 128x128x32, 256 threads (8 warps: 4(m) x 2(n)), warp tile 32x64.
// 64B smem rows with XOR swizzle (row mod 16 -> 16B column twist). No cvt/STS in loop.
#define PL_A_H 0
#define PL_A_L 8192
#define PL_B_H 16384
#define PL_B_L 24576
#define STAGE  32768
#define GEMM_SMEM (3*STAGE)   // 98304

__device__ __forceinline__ int swz16(int row) {   // 16B-unit column twist for a row
    return ((row & 3) ^ ((row >> 2) & 3));
}

__device__ __forceinline__ void issue_chunk(
    uint32_t stg, int tid, int k0, int K,
    const __nv_bfloat16* __restrict__ Ah, const __nv_bfloat16* __restrict__ Al,
    const __nv_bfloat16* __restrict__ Bh, const __nv_bfloat16* __restrict__ Bl)
{
    const int col = tid & 3;                     // 16B column within 64B row
#pragma unroll
    for (int it = 0; it < 2; it++) {
        const int row = (tid + it * 256) >> 2;   // 0..127
        const uint32_t so = (uint32_t)(row * 64 + ((col ^ swz16(row)) << 4));
        const size_t go = (size_t)row * K + k0 + col * 8;
        cpa16(stg + PL_A_H + so, Ah + go);
        cpa16(stg + PL_A_L + so, Al + go);
        cpa16(stg + PL_B_H + so, Bh + go);
        cpa16(stg + PL_B_L + so, Bl + go);
    }
}

// aB/bB: smem byte base for this thread's A/B row (plane H), ax/bx: precomputed col twist
__device__ __forceinline__ void compute_kt(float acc[2][8][4],
    uint32_t aB, uint32_t bB, uint32_t ax, uint32_t bx, int kt)
{
    const uint32_t kc = (uint32_t)(kt << 5);
    uint32_t ah[2][4], al[2][4], bh[4][4], bl[4][4];
#pragma unroll
    for (int mt = 0; mt < 2; mt++) {
        ldmx4(ah[mt], aB + mt * 1024 + (kc ^ ax));
        ldmx4(al[mt], aB + PL_A_L + mt * 1024 + (kc ^ ax));
    }
#pragma unroll
    for (int n2 = 0; n2 < 4; n2++) {
        ldmx4(bh[n2], bB + n2 * 1024 + (kc ^ bx));
        ldmx4(bl[n2], bB + (PL_B_L - PL_B_H) + n2 * 1024 + (kc ^ bx));
    }
#pragma unroll
    for (int mt = 0; mt < 2; mt++)
#pragma unroll
        for (int nt = 0; nt < 8; nt++) {
            uint32_t* bph = &bh[nt >> 1][(nt & 1) * 2];
            uint32_t* bpl = &bl[nt >> 1][(nt & 1) * 2];
            mma16816(acc[mt][nt], ah[mt], bph);
            mma16816(acc[mt][nt], ah[mt], bpl);
            mma16816(acc[mt][nt], al[mt], bph);
        }
}

// EPI: 0 = plain, 1 = gelu on cols < H_, 2 = fused ew (alpha/xs)
template<int EPI>
__global__ __launch_bounds__(256, 2)
void gemm_mma(const __nv_bfloat16* __restrict__ Ah, const __nv_bfloat16* __restrict__ Al,
              const __nv_bfloat16* __restrict__ Bh, const __nv_bfloat16* __restrict__ Bl,
              float* __restrict__ C,
              const __nv_bfloat16* __restrict__ xbh, const __nv_bfloat16* __restrict__ xbl,
              const float* __restrict__ bg, const float* __restrict__ fbase,
              float* __restrict__ alpha_o, float* __restrict__ xs_o,
              int K, int ldc)
{
    extern __shared__ char sm[];
    const int tid = threadIdx.x;
    const int lid = tid & 31, wid = tid >> 5;
    const int wm = wid >> 1, wn = wid & 1;
    const int bm = blockIdx.y * 128;
    const int bn = blockIdx.x * 128;

    const __nv_bfloat16* Ahb = Ah + (size_t)bm * K;
    const __nv_bfloat16* Alb = Al + (size_t)bm * K;
    const __nv_bfloat16* Bhb = Bh + (size_t)bn * K;
    const __nv_bfloat16* Blb = Bl + (size_t)bn * K;

    float acc[2][8][4];
#pragma unroll
    for (int i = 0; i < 2; i++)
#pragma unroll
        for (int j = 0; j < 8; j++)
#pragma unroll
            for (int q = 0; q < 4; q++) acc[i][j][q] = 0.f;

    const uint32_t sb = smem_u32(sm);
    // per-thread ldmatrix row bases + column twists (invariant across mt/n2/kt)
    const int arow = wm * 32 + (lid & 15);
    const int brow = wn * 64 + (lid & 7) + ((lid >> 4) & 1) * 8;
    const uint32_t ax = (uint32_t)((((lid >> 4) & 1) << 4) ^ (swz16(arow) << 4));
    const uint32_t bx = (uint32_t)((((lid >> 3) & 1) << 4) ^ (swz16(brow) << 4));
    const uint32_t aB0 = sb + (uint32_t)(arow * 64);
    const uint32_t bB0 = sb + PL_B_H + (uint32_t)(brow * 64);

    const int KT = K >> 5;
    // prologue: stages 0,1
    issue_chunk(sb, tid, 0, K, Ahb, Alb, Bhb, Blb);
    CP_COMMIT();
    issue_chunk(sb + STAGE, tid, 32, K, Ahb, Alb, Bhb, Blb);
    CP_COMMIT();

    int stg = 0;
    for (int c = 0; c < KT; c++) {
        if (c + 1 < KT) { CP_WAIT(1); } else { CP_WAIT(0); }
        __syncthreads();
        if (c + 2 < KT) {
            int ns = stg + 2; if (ns >= 3) ns -= 3;
            issue_chunk(sb + ns * STAGE, tid, (c + 2) * 32, K, Ahb, Alb, Bhb, Blb);
            CP_COMMIT();
        }
        const uint32_t so = (uint32_t)(stg * STAGE);
        compute_kt(acc, aB0 + so, bB0 + so, ax, bx, 0);
        compute_kt(acc, aB0 + so, bB0 + so, ax, bx, 1);
        if (++stg == 3) stg = 0;
    }

    const int r0 = bm + wm * 32 + (lid >> 2);

    if (EPI == 2) {
        // fused ew: output cols interleaved (forget_h, inp_h); permutation baked in W_g pack
        const int hbase = (bn >> 1) + wn * 32 + (lid & 3);
        float sp8[8], bgf[8], bgi[8];
#pragma unroll
        for (int nt = 0; nt < 8; nt++) {
            int h = hbase + nt * 4;
            float fb = fbase[h];
            sp8[nt] = fmaxf(fb, 0.f) + log1pf(expf(-fabsf(fb)));
            bgf[nt] = bg[h]; bgi[nt] = bg[H_ + h];
        }
#pragma unroll
        for (int mt = 0; mt < 2; mt++) {
            int row = r0 + mt * 16;
#pragma unroll
            for (int nt = 0; nt < 8; nt++) {
                int h = hbase + nt * 4;
#pragma unroll
                for (int half = 0; half < 2; half++) {
                    int rr = row + half * 8;
                    float forget = acc[mt][nt][half * 2 + 0] + bgf[nt];
                    float inp    = acc[mt][nt][half * 2 + 1] + bgi[nt];
                    float a = expf(-8.f * sp8[nt] * sigmoidf_(forget));
                    float beta = sqrtf(1.f - a * a + 1e-6f);
                    size_t ix = (size_t)rr * H_ + h;
                    float xb = __bfloat162float(xbh[ix]) + __bfloat162float(xbl[ix]);
                    alpha_o[ix] = a;
                    xs_o[ix] = beta * sigmoidf_(inp) * xb;
                }
            }
        }
        return;
    }

    const bool dg = (EPI == 1) && (bn < H_);
    const int cbase = bn + wn * 64 + (lid & 3) * 2;
#pragma unroll
    for (int mt = 0; mt < 2; mt++) {
        const int row = r0 + mt * 16;
#pragma unroll
        for (int nt = 0; nt < 8; nt++) {
            const int col = cbase + nt * 8;
            float2 v0 = make_float2(acc[mt][nt][0], acc[mt][nt][1]);
            float2 v1 = make_float2(acc[mt][nt][2], acc[mt][nt][3]);
            if (dg) {
                v0.x = 0.5f * v0.x * (1.f + erff(v0.x * 0.70710678118654752f));
                v0.y = 0.5f * v0.y * (1.f + erff(v0.y * 0.70710678118654752f));
                v1.x = 0.5f * v1.x * (1.f + erff(v1.x * 0.70710678118654752f));
                v1.y = 0.5f * v1.y * (1.f + erff(v1.y * 0.70710678118654752f));
            }
            *(float2*)(C + (size_t)row * ldc + col) = v0;
            *(float2*)(C + (size_t)(row + 8) * ldc + col) = v1;
        }
    }
}

// -------- packing --------
__global__ void pack2(const float* __restrict__ s, __nv_bfloat16* __restrict__ hi,
                      __nv_bfloat16* __restrict__ lo, long long n4)
{
    long long i = (long long)blockIdx.x * blockDim.x + threadIdx.x;
    if (i >= n4) return;
    float4 f = *(const float4*)(s + i * 4);
    __nv_bfloat16 h[4], l[4];
    split_bf(f.x, h[0], l[0]); split_bf(f.y, h[1], l[1]);
    split_bf(f.z, h[2], l[2]); split_bf(f.w, h[3], l[3]);
    *(uint2*)(hi + i * 4) = *(uint2*)h;
    *(uint2*)(lo + i * 4) = *(uint2*)l;
}

// pack W_g with row permutation: packed row r = src row (r&1)*H_ + (r>>1)
__global__ void pack_wg(const float* __restrict__ s, __nv_bfloat16* __restrict__ hi,
                        __nv_bfloat16* __restrict__ lo)
{
    int idx = blockIdx.x * blockDim.x + threadIdx.x;
    if (idx >= G2H * (H_ / 4)) return;
    int r = idx / (H_ / 4);
    int c = (idx % (H_ / 4)) * 4;
    int sr = (r & 1) * H_ + (r >> 1);
    float4 f = *(const float4*)(s + (size_t)sr * H_ + c);
    __nv_bfloat16 h[4], l[4];
    split_bf(f.x, h[0], l[0]); split_bf(f.y, h[1], l[1]);
    split_bf(f.z, h[2], l[2]); split_bf(f.w, h[3], l[3]);
    *(uint2*)(hi + (size_t)r * H_ + c) = *(uint2*)h;
    *(uint2*)(lo + (size_t)r * H_ + c) = *(uint2*)l;
}

// -------- depthwise causal conv K=4 -> bf16 planes --------
__global__ void conv_kernel(const float* __restrict__ cw, const float* __restrict__ cb)
{
    long long idx = (long long)blockIdx.x * blockDim.x + threadIdx.x;
    if (idx >= (long long)M_ * H_) return;
    int h = (int)(idx % H_);
    long long m = idx / H_;
    int t = (int)(m % T_);
    long long n = m / T_;
    float acc = cb[h];
    const float* w = cw + h * 4;
#pragma unroll
    for (int k = 0; k < 4; k++) {
        int tt = t - 3 + k;
        if (tt >= 0)
            acc = fmaf(w[k], g_gx[((size_t)(n * T_ + tt)) * G2H + H_ + h], acc);
    }
    __nv_bfloat16 hi, lo;
    split_bf(acc, hi, lo);
    g_xbh[idx] = hi;
    g_xbl[idx] = lo;
}

// -------- chunked linear scan --------
__global__ void scan_p1()
{
    int h = blockIdx.x * 128 + threadIdx.x;
    int c = blockIdx.y, n = blockIdx.z;
    size_t base = ((size_t)(n * T_ + c * TC)) * H_ + h;
    float A = 1.f, Bv = 0.f;
#pragma unroll 4
    for (int t = 0; t < TC; t++) {
        float a = g_alpha[base + (size_t)t * H_];
        float x = g_xs   [base + (size_t)t * H_];
        Bv = fmaf(a, Bv, x);
        A *= a;
    }
    int ci = (n * NC + c) * H_ + h;
    g_cA[ci] = A;
    g_cB[ci] = Bv;
}

__global__ void scan_p2()
{
    int h = blockIdx.x * 128 + threadIdx.x;
    int n = blockIdx.y;
    float carry = 0.f;
    for (int c = 0; c < NC; c++) {
        int i = (n * NC + c) * H_ + h;
        float a = g_cA[i], b = g_cB[i];
        g_cB[i] = carry;
        carry = fmaf(a, carry, b);
    }
}

__global__ void scan_p3()   // replay; write (gelu(gate)*h) as bf16 planes
{
    int h = blockIdx.x * 128 + threadIdx.x;
    int c = blockIdx.y, n = blockIdx.z;
    size_t base  = ((size_t)(n * T_ + c * TC)) * H_ + h;
    size_t gbase = ((size_t)(n * T_ + c * TC)) * G2H + h;
    float hp = g_cB[(n * NC + c) * H_ + h];
#pragma unroll 4
    for (int t = 0; t < TC; t++) {
        float a = g_alpha[base + (size_t)t * H_];
        float x = g_xs   [base + (size_t)t * H_];
        hp = fmaf(a, hp, x);
        float g = g_gx[gbase + (size_t)t * G2H];   // gelu(gate)
        float v = hp * g;
        __nv_bfloat16 hi, lo;
        split_bf(v, hi, lo);
        g_yh[base + (size_t)t * H_] = hi;
        g_yl[base + (size_t)t * H_] = lo;
    }
}

// -------- launch --------
extern "C" void kernel_launch(void* const* d_in, const int* in_sizes, int n_in,
                              void* d_out, int out_size)
{
    const float* x      = (const float*)d_in[0];
    const float* W_in   = (const float*)d_in[1];
    const float* conv_w = (const float*)d_in[2];
    const float* conv_b = (const float*)d_in[3];
    const float* W_g    = (const float*)d_in[4];
    const float* b_g    = (const float*)d_in[5];
    const float* fbase  = (const float*)d_in[6];
    const float* W_out  = (const float*)d_in[7];
    float* out = (float*)d_out;

    float *gx, *alp, *xs;
    __nv_bfloat16 *xh, *xl, *xbh, *xbl, *yh, *yl, *wih, *wil, *wgh, *wgl, *woh, *wol;
    cudaGetSymbolAddress((void**)&gx,  g_gx);
    cudaGetSymbolAddress((void**)&alp, g_alpha);
    cudaGetSymbolAddress((void**)&xs,  g_xs);
    cudaGetSymbolAddress((void**)&xh,  g_xh);
    cudaGetSymbolAddress((void**)&xl,  g_xl);
    cudaGetSymbolAddress((void**)&xbh, g_xbh);
    cudaGetSymbolAddress((void**)&xbl, g_xbl);
    cudaGetSymbolAddress((void**)&yh,  g_yh);
    cudaGetSymbolAddress((void**)&yl,  g_yl);
    cudaGetSymbolAddress((void**)&wih, g_wih);
    cudaGetSymbolAddress((void**)&wil, g_wil);
    cudaGetSymbolAddress((void**)&wgh, g_wgh);
    cudaGetSymbolAddress((void**)&wgl, g_wgl);
    cudaGetSymbolAddress((void**)&woh, g_woh);
    cudaGetSymbolAddress((void**)&wol, g_wol);

    cudaFuncSetAttribute(gemm_mma<0>, cudaFuncAttributeMaxDynamicSharedMemorySize, GEMM_SMEM);
    cudaFuncSetAttribute(gemm_mma<1>, cudaFuncAttributeMaxDynamicSharedMemorySize, GEMM_SMEM);
    cudaFuncSetAttribute(gemm_mma<2>, cudaFuncAttributeMaxDynamicSharedMemorySize, GEMM_SMEM);

    const long long tot = (long long)M_ * H_;
    const int EB = 256;
    const int eg = (int)((tot + EB - 1) / EB);

    // 0) pack x + weights to bf16 hi/lo planes
    pack2<<<(int)(((long long)M_*D_/4 + 255)/256), 256>>>(x, xh, xl, (long long)M_*D_/4);
    pack2<<<(G2H*D_/4 + 255)/256, 256>>>(W_in, wih, wil, (long long)G2H*D_/4);
    pack_wg<<<(G2H*(H_/4) + 255)/256, 256>>>(W_g, wgh, wgl);
    pack2<<<(D_*H_/4 + 255)/256, 256>>>(W_out, woh, wol, (long long)D_*H_/4);

    // 1) gx = x @ W_in^T; gelu fused on gate half
    gemm_mma<1><<<dim3(G2H/128, M_/128), 256, GEMM_SMEM>>>(
        xh, xl, wih, wil, gx, nullptr, nullptr, nullptr, nullptr, nullptr, nullptr, D_, G2H);
    // 2) depthwise causal conv -> xb planes
    conv_kernel<<<eg, EB>>>(conv_w, conv_b);
    // 3) fused ew GEMM -> alpha, xs
    gemm_mma<2><<<dim3(G2H/128, M_/128), 256, GEMM_SMEM>>>(
        xbh, xbl, wgh, wgl, nullptr, xbh, xbl, b_g, fbase, alp, xs, H_, 0);
    // 4) scan
    scan_p1<<<dim3(H_/128, NC, N_), 128>>>();
    scan_p2<<<dim3(H_/128, N_), 128>>>();
    scan_p3<<<dim3(H_/128, NC, N_), 128>>>();
    // 5) out = (gelu(gate)*h) @ W_out^T
    gemm_mma<0><<<dim3(D_/128, M_/128), 256, GEMM_SMEM>>>(
        yh, yl, woh, wol, out, nullptr, nullptr, nullptr, nullptr, nullptr, nullptr, H_, D_);
}

// round 11
// speedup vs baseline: 1.3891x; 1.0321x over previous
#include <cuda_runtime.h>
#include <cuda_bf16.h>
#include <math.h>
#include <stdint.h>

#define N_  4
#define T_  4096
#define D_  1024
#define H_  1536
#define M_  (N_*T_)       // 16384 rows
#define G2H (2*H_)        // 3072
#define TC  128           // scan chunk length
#define NC  (T_/TC)       // 32 chunks

// -------- scratch (device globals; no allocation allowed) --------
__device__ __align__(256) float g_gx  [(size_t)M_*G2H];   // GEMM1 out; gate half = gelu(gate)
__device__ __align__(256) float g_alpha[(size_t)M_*H_];
__device__ __align__(256) float g_xs  [(size_t)M_*H_];
__device__ __align__(256) float g_cA  [N_*NC*H_];
__device__ __align__(256) float g_cB  [N_*NC*H_];
// activation bf16 hi/lo planes
__device__ __align__(256) __nv_bfloat16 g_xh [(size_t)M_*D_];
__device__ __align__(256) __nv_bfloat16 g_xl [(size_t)M_*D_];
__device__ __align__(256) __nv_bfloat16 g_xbh[(size_t)M_*H_];   // conv out planes
__device__ __align__(256) __nv_bfloat16 g_xbl[(size_t)M_*H_];
__device__ __align__(256) __nv_bfloat16 g_yh [(size_t)M_*H_];   // gelu(gate)*h planes
__device__ __align__(256) __nv_bfloat16 g_yl [(size_t)M_*H_];
// weight bf16 hi/lo planes
__device__ __align__(256) __nv_bfloat16 g_wih[(size_t)G2H*D_];
__device__ __align__(256) __nv_bfloat16 g_wil[(size_t)G2H*D_];
__device__ __align__(256) __nv_bfloat16 g_wgh[(size_t)G2H*H_];  // rows permuted for EPI2
__device__ __align__(256) __nv_bfloat16 g_wgl[(size_t)G2H*H_];
__device__ __align__(256) __nv_bfloat16 g_woh[(size_t)D_*H_];
__device__ __align__(256) __nv_bfloat16 g_wol[(size_t)D_*H_];

// ======================= helpers =======================
__device__ __forceinline__ uint32_t smem_u32(const void* p) {
    uint32_t a;
    asm("{ .reg .u64 t; cvta.to.shared.u64 t, %1; cvt.u32.u64 %0, t; }" : "=r"(a) : "l"(p));
    return a;
}
__device__ __forceinline__ void ldmx4(uint32_t* r, uint32_t a) {
    asm volatile("ldmatrix.sync.aligned.m8n8.x4.shared.b16 {%0,%1,%2,%3}, [%4];"
        : "=r"(r[0]), "=r"(r[1]), "=r"(r[2]), "=r"(r[3]) : "r"(a));
}
__device__ __forceinline__ void mma16816(float* d, const uint32_t* a, const uint32_t* b) {
    asm volatile("mma.sync.aligned.m16n8k16.row.col.f32.bf16.bf16.f32 "
        "{%0,%1,%2,%3}, {%4,%5,%6,%7}, {%8,%9}, {%0,%1,%2,%3};"
        : "+f"(d[0]), "+f"(d[1]), "+f"(d[2]), "+f"(d[3])
        : "r"(a[0]), "r"(a[1]), "r"(a[2]), "r"(a[3]), "r"(b[0]), "r"(b[1]));
}
__device__ __forceinline__ void cpa16(uint32_t dst, const void* src) {
    asm volatile("cp.async.cg.shared.global [%0], [%1], 16;" :: "r"(dst), "l"(src));
}
#define CP_COMMIT()     asm volatile("cp.async.commit_group;" ::: "memory")
#define CP_WAIT(NN)     asm volatile("cp.async.wait_group %0;" :: "n"(NN) : "memory")
__device__ __forceinline__ float sigmoidf_(float v) { return 1.f / (1.f + expf(-v)); }
__device__ __forceinline__ void split_bf(float v, __nv_bfloat16& h, __nv_bfloat16& l) {
    h = __float2bfloat16(v);
    l = __float2bfloat16(v - __bfloat162float(h));
}

// ================== bf16x3 mma GEMM (all cp.async, 3-stage, swizzled) ==================
// Block tile 128x128x32, 256 threads (8 warps: 4(m) x 2(n)), warp tile 32x64.
// 64B smem rows with XOR swizzle. No cvt/STS in mainloop.
#define PL_A_H 0
#define PL_A_L 8192
#define PL_B_H 16384
#define PL_B_L 24576
#define STAGE  32768
#define GEMM_SMEM (3*STAGE)   // 98304

__device__ __forceinline__ int swz16(int row) {
    return ((row & 3) ^ ((row >> 2) & 3));
}

__device__ __forceinline__ void issue_chunk(
    uint32_t stg, int tid, int k0, int K,
    const __nv_bfloat16* __restrict__ Ah, const __nv_bfloat16* __restrict__ Al,
    const __nv_bfloat16* __restrict__ Bh, const __nv_bfloat16* __restrict__ Bl)
{
    const int col = tid & 3;
#pragma unroll
    for (int it = 0; it < 2; it++) {
        const int row = (tid + it * 256) >> 2;
        const uint32_t so = (uint32_t)(row * 64 + ((col ^ swz16(row)) << 4));
        const size_t go = (size_t)row * K + k0 + col * 8;
        cpa16(stg + PL_A_H + so, Ah + go);
        cpa16(stg + PL_A_L + so, Al + go);
        cpa16(stg + PL_B_H + so, Bh + go);
        cpa16(stg + PL_B_L + so, Bl + go);
    }
}

__device__ __forceinline__ void compute_kt(float acc[2][8][4],
    uint32_t aB, uint32_t bB, uint32_t ax, uint32_t bx, int kt)
{
    const uint32_t kc = (uint32_t)(kt << 5);
    uint32_t ah[2][4], al[2][4], bh[4][4], bl[4][4];
#pragma unroll
    for (int mt = 0; mt < 2; mt++) {
        ldmx4(ah[mt], aB + mt * 1024 + (kc ^ ax));
        ldmx4(al[mt], aB + PL_A_L + mt * 1024 + (kc ^ ax));
    }
#pragma unroll
    for (int n2 = 0; n2 < 4; n2++) {
        ldmx4(bh[n2], bB + n2 * 1024 + (kc ^ bx));
        ldmx4(bl[n2], bB + (PL_B_L - PL_B_H) + n2 * 1024 + (kc ^ bx));
    }
#pragma unroll
    for (int mt = 0; mt < 2; mt++)
#pragma unroll
        for (int nt = 0; nt < 8; nt++) {
            uint32_t* bph = &bh[nt >> 1][(nt & 1) * 2];
            uint32_t* bpl = &bl[nt >> 1][(nt & 1) * 2];
            mma16816(acc[mt][nt], ah[mt], bph);
            mma16816(acc[mt][nt], ah[mt], bpl);
            mma16816(acc[mt][nt], al[mt], bph);
        }
}

// EPI: 0 = plain, 1 = gelu on cols < H_, 2 = fused ew (alpha/xs, smem-staged stores)
template<int EPI>
__global__ __launch_bounds__(256, 2)
void gemm_mma(const __nv_bfloat16* __restrict__ Ah, const __nv_bfloat16* __restrict__ Al,
              const __nv_bfloat16* __restrict__ Bh, const __nv_bfloat16* __restrict__ Bl,
              float* __restrict__ C,
              const __nv_bfloat16* __restrict__ xbh, const __nv_bfloat16* __restrict__ xbl,
              const float* __restrict__ bg, const float* __restrict__ fbase,
              float* __restrict__ alpha_o, float* __restrict__ xs_o,
              int K, int ldc)
{
    extern __shared__ char sm[];
    const int tid = threadIdx.x;
    const int lid = tid & 31, wid = tid >> 5;
    const int wm = wid >> 1, wn = wid & 1;
    const int bm = blockIdx.y * 128;
    const int bn = blockIdx.x * 128;

    const __nv_bfloat16* Ahb = Ah + (size_t)bm * K;
    const __nv_bfloat16* Alb = Al + (size_t)bm * K;
    const __nv_bfloat16* Bhb = Bh + (size_t)bn * K;
    const __nv_bfloat16* Blb = Bl + (size_t)bn * K;

    float acc[2][8][4];
#pragma unroll
    for (int i = 0; i < 2; i++)
#pragma unroll
        for (int j = 0; j < 8; j++)
#pragma unroll
            for (int q = 0; q < 4; q++) acc[i][j][q] = 0.f;

    const uint32_t sb = smem_u32(sm);
    const int arow = wm * 32 + (lid & 15);
    const int brow = wn * 64 + (lid & 7) + ((lid >> 4) & 1) * 8;
    const uint32_t ax = (uint32_t)((((lid >> 4) & 1) << 4) ^ (swz16(arow) << 4));
    const uint32_t bx = (uint32_t)((((lid >> 3) & 1) << 4) ^ (swz16(brow) << 4));
    const uint32_t aB0 = sb + (uint32_t)(arow * 64);
    const uint32_t bB0 = sb + PL_B_H + (uint32_t)(brow * 64);

    const int KT = K >> 5;
    issue_chunk(sb, tid, 0, K, Ahb, Alb, Bhb, Blb);
    CP_COMMIT();
    issue_chunk(sb + STAGE, tid, 32, K, Ahb, Alb, Bhb, Blb);
    CP_COMMIT();

    int stg = 0;
    for (int c = 0; c < KT; c++) {
        if (c + 1 < KT) { CP_WAIT(1); } else { CP_WAIT(0); }
        __syncthreads();
        if (c + 2 < KT) {
            int ns = stg + 2; if (ns >= 3) ns -= 3;
            issue_chunk(sb + ns * STAGE, tid, (c + 2) * 32, K, Ahb, Alb, Bhb, Blb);
            CP_COMMIT();
        }
        const uint32_t so = (uint32_t)(stg * STAGE);
        compute_kt(acc, aB0 + so, bB0 + so, ax, bx, 0);
        compute_kt(acc, aB0 + so, bB0 + so, ax, bx, 1);
        if (++stg == 3) stg = 0;
    }

    const int r0 = bm + wm * 32 + (lid >> 2);

    if (EPI == 2) {
        // fused ew. Compute alpha/xs in-place over acc, then stage stores via smem
        // (row stride 68 floats -> conflict-free scattered writes, coalesced reads).
        const int hloc = wn * 32 + (lid & 3);      // local h within 64-wide tile
        const int h0 = (bn >> 1);
        float sp8[8], bgf[8], bgi[8];
#pragma unroll
        for (int nt = 0; nt < 8; nt++) {
            int h = h0 + hloc + nt * 4;
            float fb = fbase[h];
            sp8[nt] = fmaxf(fb, 0.f) + log1pf(expf(-fabsf(fb)));
            bgf[nt] = bg[h]; bgi[nt] = bg[H_ + h];
        }
        const int rloc0 = wm * 32 + (lid >> 2);
#pragma unroll
        for (int mt = 0; mt < 2; mt++)
#pragma unroll
            for (int nt = 0; nt < 8; nt++)
#pragma unroll
                for (int half = 0; half < 2; half++) {
                    int rl = rloc0 + mt * 16 + half * 8;
                    float forget = acc[mt][nt][half * 2 + 0] + bgf[nt];
                    float inp    = acc[mt][nt][half * 2 + 1] + bgi[nt];
                    float a = expf(-8.f * sp8[nt] * sigmoidf_(forget));
                    float beta = sqrtf(1.f - a * a + 1e-6f);
                    size_t ix = (size_t)(bm + rl) * H_ + h0 + hloc + nt * 4;
                    float xb = __bfloat162float(xbh[ix]) + __bfloat162float(xbl[ix]);
                    acc[mt][nt][half * 2 + 0] = a;                          // alpha
                    acc[mt][nt][half * 2 + 1] = beta * sigmoidf_(inp) * xb; // xs
                }
        float* st = (float*)sm;
        __syncthreads();   // mainloop smem reads finished on all threads
#pragma unroll
        for (int pass = 0; pass < 2; pass++) {   // 0: alpha, 1: xs
#pragma unroll
            for (int mt = 0; mt < 2; mt++)
#pragma unroll
                for (int nt = 0; nt < 8; nt++)
#pragma unroll
                    for (int half = 0; half < 2; half++) {
                        int rl = rloc0 + mt * 16 + half * 8;
                        st[rl * 68 + hloc + nt * 4] = acc[mt][nt][half * 2 + pass];
                    }
            __syncthreads();
            float* dst = pass ? xs_o : alpha_o;
#pragma unroll
            for (int it = 0; it < 8; it++) {
                int idx = it * 256 + tid;
                int row = idx >> 4, cc = (idx & 15) * 4;
                float4 v = *(float4*)&st[row * 68 + cc];
                *(float4*)&dst[(size_t)(bm + row) * H_ + h0 + cc] = v;
            }
            __syncthreads();
        }
        return;
    }

    const bool dg = (EPI == 1) && (bn < H_);
    const int cbase = bn + wn * 64 + (lid & 3) * 2;
#pragma unroll
    for (int mt = 0; mt < 2; mt++) {
        const int row = r0 + mt * 16;
#pragma unroll
        for (int nt = 0; nt < 8; nt++) {
            const int col = cbase + nt * 8;
            float2 v0 = make_float2(acc[mt][nt][0], acc[mt][nt][1]);
            float2 v1 = make_float2(acc[mt][nt][2], acc[mt][nt][3]);
            if (dg) {
                v0.x = 0.5f * v0.x * (1.f + erff(v0.x * 0.70710678118654752f));
                v0.y = 0.5f * v0.y * (1.f + erff(v0.y * 0.70710678118654752f));
                v1.x = 0.5f * v1.x * (1.f + erff(v1.x * 0.70710678118654752f));
                v1.y = 0.5f * v1.y * (1.f + erff(v1.y * 0.70710678118654752f));
            }
            *(float2*)(C + (size_t)row * ldc + col) = v0;
            *(float2*)(C + (size_t)(row + 8) * ldc + col) = v1;
        }
    }
}

// -------- packing --------
__global__ void pack2(const float* __restrict__ s, __nv_bfloat16* __restrict__ hi,
                      __nv_bfloat16* __restrict__ lo, long long n4)
{
    long long i = (long long)blockIdx.x * blockDim.x + threadIdx.x;
    if (i >= n4) return;
    float4 f = *(const float4*)(s + i * 4);
    __nv_bfloat16 h[4], l[4];
    split_bf(f.x, h[0], l[0]); split_bf(f.y, h[1], l[1]);
    split_bf(f.z, h[2], l[2]); split_bf(f.w, h[3], l[3]);
    *(uint2*)(hi + i * 4) = *(uint2*)h;
    *(uint2*)(lo + i * 4) = *(uint2*)l;
}

// pack W_g with row permutation: packed row r = src row (r&1)*H_ + (r>>1)
__global__ void pack_wg(const float* __restrict__ s, __nv_bfloat16* __restrict__ hi,
                        __nv_bfloat16* __restrict__ lo)
{
    int idx = blockIdx.x * blockDim.x + threadIdx.x;
    if (idx >= G2H * (H_ / 4)) return;
    int r = idx / (H_ / 4);
    int c = (idx % (H_ / 4)) * 4;
    int sr = (r & 1) * H_ + (r >> 1);
    float4 f = *(const float4*)(s + (size_t)sr * H_ + c);
    __nv_bfloat16 h[4], l[4];
    split_bf(f.x, h[0], l[0]); split_bf(f.y, h[1], l[1]);
    split_bf(f.z, h[2], l[2]); split_bf(f.w, h[3], l[3]);
    *(uint2*)(hi + (size_t)r * H_ + c) = *(uint2*)h;
    *(uint2*)(lo + (size_t)r * H_ + c) = *(uint2*)l;
}

// -------- depthwise causal conv K=4, 4-t blocking -> bf16 planes --------
__global__ void conv_kernel(const float* __restrict__ cw, const float* __restrict__ cb)
{
    long long idx = (long long)blockIdx.x * blockDim.x + threadIdx.x;
    if (idx >= (long long)(M_ / 4) * H_) return;
    int h = (int)(idx % H_);
    long long q = idx / H_;                 // over n*T_/4 + tq
    int tq = (int)(q % (T_ / 4));
    long long n = q / (T_ / 4);
    const int t0 = tq * 4;
    const long long rowbase = (n * T_ + t0);

    float v[7];
#pragma unroll
    for (int j = 0; j < 7; j++) {
        int tt = t0 - 3 + j;
        v[j] = (tt >= 0) ? g_gx[(size_t)(n * T_ + tt) * G2H + H_ + h] : 0.f;
    }
    float w0 = cw[h * 4 + 0], w1 = cw[h * 4 + 1], w2 = cw[h * 4 + 2], w3 = cw[h * 4 + 3];
    float b = cb[h];
#pragma unroll
    for (int r = 0; r < 4; r++) {
        float acc = b;
        acc = fmaf(w0, v[r + 0], acc);
        acc = fmaf(w1, v[r + 1], acc);
        acc = fmaf(w2, v[r + 2], acc);
        acc = fmaf(w3, v[r + 3], acc);
        __nv_bfloat16 hi, lo;
        split_bf(acc, hi, lo);
        size_t ox = (size_t)(rowbase + r) * H_ + h;
        g_xbh[ox] = hi;
        g_xbl[ox] = lo;
    }
}

// -------- chunked linear scan --------
__global__ void scan_p1()
{
    int h = blockIdx.x * 128 + threadIdx.x;
    int c = blockIdx.y, n = blockIdx.z;
    size_t base = ((size_t)(n * T_ + c * TC)) * H_ + h;
    float A = 1.f, Bv = 0.f;
#pragma unroll 4
    for (int t = 0; t < TC; t++) {
        float a = g_alpha[base + (size_t)t * H_];
        float x = g_xs   [base + (size_t)t * H_];
        Bv = fmaf(a, Bv, x);
        A *= a;
    }
    int ci = (n * NC + c) * H_ + h;
    g_cA[ci] = A;
    g_cB[ci] = Bv;
}

__global__ void scan_p2()
{
    int h = blockIdx.x * 128 + threadIdx.x;
    int n = blockIdx.y;
    float carry = 0.f;
    for (int c = 0; c < NC; c++) {
        int i = (n * NC + c) * H_ + h;
        float a = g_cA[i], b = g_cB[i];
        g_cB[i] = carry;
        carry = fmaf(a, carry, b);
    }
}

__global__ void scan_p3()   // replay; write (gelu(gate)*h) as bf16 planes
{
    int h = blockIdx.x * 128 + threadIdx.x;
    int c = blockIdx.y, n = blockIdx.z;
    size_t base  = ((size_t)(n * T_ + c * TC)) * H_ + h;
    size_t gbase = ((size_t)(n * T_ + c * TC)) * G2H + h;
    float hp = g_cB[(n * NC + c) * H_ + h];
#pragma unroll 4
    for (int t = 0; t < TC; t++) {
        float a = g_alpha[base + (size_t)t * H_];
        float x = g_xs   [base + (size_t)t * H_];
        hp = fmaf(a, hp, x);
        float g = g_gx[gbase + (size_t)t * G2H];   // gelu(gate)
        float v = hp * g;
        __nv_bfloat16 hi, lo;
        split_bf(v, hi, lo);
        g_yh[base + (size_t)t * H_] = hi;
        g_yl[base + (size_t)t * H_] = lo;
    }
}

// -------- launch --------
extern "C" void kernel_launch(void* const* d_in, const int* in_sizes, int n_in,
                              void* d_out, int out_size)
{
    const float* x      = (const float*)d_in[0];
    const float* W_in   = (const float*)d_in[1];
    const float* conv_w = (const float*)d_in[2];
    const float* conv_b = (const float*)d_in[3];
    const float* W_g    = (const float*)d_in[4];
    const float* b_g    = (const float*)d_in[5];
    const float* fbase  = (const float*)d_in[6];
    const float* W_out  = (const float*)d_in[7];
    float* out = (float*)d_out;

    float *gx, *alp, *xs;
    __nv_bfloat16 *xh, *xl, *xbh, *xbl, *yh, *yl, *wih, *wil, *wgh, *wgl, *woh, *wol;
    cudaGetSymbolAddress((void**)&gx,  g_gx);
    cudaGetSymbolAddress((void**)&alp, g_alpha);
    cudaGetSymbolAddress((void**)&xs,  g_xs);
    cudaGetSymbolAddress((void**)&xh,  g_xh);
    cudaGetSymbolAddress((void**)&xl,  g_xl);
    cudaGetSymbolAddress((void**)&xbh, g_xbh);
    cudaGetSymbolAddress((void**)&xbl, g_xbl);
    cudaGetSymbolAddress((void**)&yh,  g_yh);
    cudaGetSymbolAddress((void**)&yl,  g_yl);
    cudaGetSymbolAddress((void**)&wih, g_wih);
    cudaGetSymbolAddress((void**)&wil, g_wil);
    cudaGetSymbolAddress((void**)&wgh, g_wgh);
    cudaGetSymbolAddress((void**)&wgl, g_wgl);
    cudaGetSymbolAddress((void**)&woh, g_woh);
    cudaGetSymbolAddress((void**)&wol, g_wol);

    cudaFuncSetAttribute(gemm_mma<0>, cudaFuncAttributeMaxDynamicSharedMemorySize, GEMM_SMEM);
    cudaFuncSetAttribute(gemm_mma<1>, cudaFuncAttributeMaxDynamicSharedMemorySize, GEMM_SMEM);
    cudaFuncSetAttribute(gemm_mma<2>, cudaFuncAttributeMaxDynamicSharedMemorySize, GEMM_SMEM);

    // 0) pack x + weights to bf16 hi/lo planes
    pack2<<<(int)(((long long)M_*D_/4 + 255)/256), 256>>>(x, xh, xl, (long long)M_*D_/4);
    pack2<<<(G2H*D_/4 + 255)/256, 256>>>(W_in, wih, wil, (long long)G2H*D_/4);
    pack_wg<<<(G2H*(H_/4) + 255)/256, 256>>>(W_g, wgh, wgl);
    pack2<<<(D_*H_/4 + 255)/256, 256>>>(W_out, woh, wol, (long long)D_*H_/4);

    // 1) gx = x @ W_in^T; gelu fused on gate half
    gemm_mma<1><<<dim3(G2H/128, M_/128), 256, GEMM_SMEM>>>(
        xh, xl, wih, wil, gx, nullptr, nullptr, nullptr, nullptr, nullptr, nullptr, D_, G2H);
    // 2) depthwise causal conv -> xb planes (4-t blocking)
    conv_kernel<<<(int)(((long long)(M_/4)*H_ + 255)/256), 256>>>(conv_w, conv_b);
    // 3) fused ew GEMM -> alpha, xs (smem-staged epilogue)
    gemm_mma<2><<<dim3(G2H/128, M_/128), 256, GEMM_SMEM>>>(
        xbh, xbl, wgh, wgl, nullptr, xbh, xbl, b_g, fbase, alp, xs, H_, 0);
    // 4) scan
    scan_p1<<<dim3(H_/128, NC, N_), 128>>>();
    scan_p2<<<dim3(H_/128, N_), 128>>>();
    scan_p3<<<dim3(H_/128, NC, N_), 128>>>();
    // 5) out = (gelu(gate)*h) @ W_out^T
    gemm_mma<0><<<dim3(D_/128, M_/128), 256, GEMM_SMEM>>>(
        yh, yl, woh, wol, out, nullptr, nullptr, nullptr, nullptr, nullptr, nullptr, H_, D_);
}

// round 12
// speedup vs baseline: 1.4907x; 1.0732x over previous
#include <cuda_runtime.h>
#include <cuda_bf16.h>
#include <math.h>
#include <stdint.h>

#define N_  4
#define T_  4096
#define D_  1024
#define H_  1536
#define M_  (N_*T_)       // 16384 rows
#define G2H (2*H_)        // 3072
#define TC  128           // scan chunk length == GEMM M-tile
#define NC  (T_/TC)       // 32 chunks

// -------- scratch (device globals; no allocation allowed) --------
__device__ __align__(256) float g_gx  [(size_t)M_*G2H];   // GEMM1 out; gate half = gelu(gate)
__device__ __align__(256) float g_alpha[(size_t)M_*H_];
__device__ __align__(256) float g_xs  [(size_t)M_*H_];
__device__ __align__(256) float g_cA  [N_*NC*H_];
__device__ __align__(256) float g_cB  [N_*NC*H_];
// activation bf16 hi/lo planes
__device__ __align__(256) __nv_bfloat16 g_xh [(size_t)M_*D_];
__device__ __align__(256) __nv_bfloat16 g_xl [(size_t)M_*D_];
__device__ __align__(256) __nv_bfloat16 g_xbh[(size_t)M_*H_];   // conv out planes
__device__ __align__(256) __nv_bfloat16 g_xbl[(size_t)M_*H_];
__device__ __align__(256) __nv_bfloat16 g_yh [(size_t)M_*H_];   // gelu(gate)*h planes
__device__ __align__(256) __nv_bfloat16 g_yl [(size_t)M_*H_];
// weight bf16 hi/lo planes
__device__ __align__(256) __nv_bfloat16 g_wih[(size_t)G2H*D_];
__device__ __align__(256) __nv_bfloat16 g_wil[(size_t)G2H*D_];
__device__ __align__(256) __nv_bfloat16 g_wgh[(size_t)G2H*H_];  // rows permuted for EPI2
__device__ __align__(256) __nv_bfloat16 g_wgl[(size_t)G2H*H_];
__device__ __align__(256) __nv_bfloat16 g_woh[(size_t)D_*H_];
__device__ __align__(256) __nv_bfloat16 g_wol[(size_t)D_*H_];

// ======================= helpers =======================
__device__ __forceinline__ uint32_t smem_u32(const void* p) {
    uint32_t a;
    asm("{ .reg .u64 t; cvta.to.shared.u64 t, %1; cvt.u32.u64 %0, t; }" : "=r"(a) : "l"(p));
    return a;
}
__device__ __forceinline__ void ldmx4(uint32_t* r, uint32_t a) {
    asm volatile("ldmatrix.sync.aligned.m8n8.x4.shared.b16 {%0,%1,%2,%3}, [%4];"
        : "=r"(r[0]), "=r"(r[1]), "=r"(r[2]), "=r"(r[3]) : "r"(a));
}
__device__ __forceinline__ void mma16816(float* d, const uint32_t* a, const uint32_t* b) {
    asm volatile("mma.sync.aligned.m16n8k16.row.col.f32.bf16.bf16.f32 "
        "{%0,%1,%2,%3}, {%4,%5,%6,%7}, {%8,%9}, {%0,%1,%2,%3};"
        : "+f"(d[0]), "+f"(d[1]), "+f"(d[2]), "+f"(d[3])
        : "r"(a[0]), "r"(a[1]), "r"(a[2]), "r"(a[3]), "r"(b[0]), "r"(b[1]));
}
__device__ __forceinline__ void cpa16(uint32_t dst, const void* src) {
    asm volatile("cp.async.cg.shared.global [%0], [%1], 16;" :: "r"(dst), "l"(src));
}
#define CP_COMMIT()     asm volatile("cp.async.commit_group;" ::: "memory")
#define CP_WAIT(NN)     asm volatile("cp.async.wait_group %0;" :: "n"(NN) : "memory")
__device__ __forceinline__ float sigmoidf_(float v) { return 1.f / (1.f + expf(-v)); }
__device__ __forceinline__ void split_bf(float v, __nv_bfloat16& h, __nv_bfloat16& l) {
    h = __float2bfloat16(v);
    l = __float2bfloat16(v - __bfloat162float(h));
}

// ================== bf16x3 mma GEMM (all cp.async, 3-stage, swizzled) ==================
// Block tile 128x128x32, 256 threads (8 warps: 4(m) x 2(n)), warp tile 32x64.
// 64B smem rows with XOR swizzle. No cvt/STS in mainloop.
#define PL_A_H 0
#define PL_A_L 8192
#define PL_B_H 16384
#define PL_B_L 24576
#define STAGE  32768
#define GEMM_SMEM (3*STAGE)   // 98304

__device__ __forceinline__ int swz16(int row) {
    return ((row & 3) ^ ((row >> 2) & 3));
}

__device__ __forceinline__ void issue_chunk(
    uint32_t stg, int tid, int k0, int K,
    const __nv_bfloat16* __restrict__ Ah, const __nv_bfloat16* __restrict__ Al,
    const __nv_bfloat16* __restrict__ Bh, const __nv_bfloat16* __restrict__ Bl)
{
    const int col = tid & 3;
#pragma unroll
    for (int it = 0; it < 2; it++) {
        const int row = (tid + it * 256) >> 2;
        const uint32_t so = (uint32_t)(row * 64 + ((col ^ swz16(row)) << 4));
        const size_t go = (size_t)row * K + k0 + col * 8;
        cpa16(stg + PL_A_H + so, Ah + go);
        cpa16(stg + PL_A_L + so, Al + go);
        cpa16(stg + PL_B_H + so, Bh + go);
        cpa16(stg + PL_B_L + so, Bl + go);
    }
}

__device__ __forceinline__ void compute_kt(float acc[2][8][4],
    uint32_t aB, uint32_t bB, uint32_t ax, uint32_t bx, int kt)
{
    const uint32_t kc = (uint32_t)(kt << 5);
    uint32_t ah[2][4], al[2][4], bh[4][4], bl[4][4];
#pragma unroll
    for (int mt = 0; mt < 2; mt++) {
        ldmx4(ah[mt], aB + mt * 1024 + (kc ^ ax));
        ldmx4(al[mt], aB + PL_A_L + mt * 1024 + (kc ^ ax));
    }
#pragma unroll
    for (int n2 = 0; n2 < 4; n2++) {
        ldmx4(bh[n2], bB + n2 * 1024 + (kc ^ bx));
        ldmx4(bl[n2], bB + (PL_B_L - PL_B_H) + n2 * 1024 + (kc ^ bx));
    }
#pragma unroll
    for (int mt = 0; mt < 2; mt++)
#pragma unroll
        for (int nt = 0; nt < 8; nt++) {
            uint32_t* bph = &bh[nt >> 1][(nt & 1) * 2];
            uint32_t* bpl = &bl[nt >> 1][(nt & 1) * 2];
            mma16816(acc[mt][nt], ah[mt], bph);
            mma16816(acc[mt][nt], ah[mt], bpl);
            mma16816(acc[mt][nt], al[mt], bph);
        }
}

// EPI: 0 = plain, 1 = gelu on cols < H_, 2 = fused ew + chunk-scan reduction
template<int EPI>
__global__ __launch_bounds__(256, 2)
void gemm_mma(const __nv_bfloat16* __restrict__ Ah, const __nv_bfloat16* __restrict__ Al,
              const __nv_bfloat16* __restrict__ Bh, const __nv_bfloat16* __restrict__ Bl,
              float* __restrict__ C,
              const __nv_bfloat16* __restrict__ xbh, const __nv_bfloat16* __restrict__ xbl,
              const float* __restrict__ bg, const float* __restrict__ fbase,
              float* __restrict__ alpha_o, float* __restrict__ xs_o,
              int K, int ldc)
{
    extern __shared__ char sm[];
    const int tid = threadIdx.x;
    const int lid = tid & 31, wid = tid >> 5;
    const int wm = wid >> 1, wn = wid & 1;
    const int bm = blockIdx.y * 128;
    const int bn = blockIdx.x * 128;

    const __nv_bfloat16* Ahb = Ah + (size_t)bm * K;
    const __nv_bfloat16* Alb = Al + (size_t)bm * K;
    const __nv_bfloat16* Bhb = Bh + (size_t)bn * K;
    const __nv_bfloat16* Blb = Bl + (size_t)bn * K;

    float acc[2][8][4];
#pragma unroll
    for (int i = 0; i < 2; i++)
#pragma unroll
        for (int j = 0; j < 8; j++)
#pragma unroll
            for (int q = 0; q < 4; q++) acc[i][j][q] = 0.f;

    const uint32_t sb = smem_u32(sm);
    const int arow = wm * 32 + (lid & 15);
    const int brow = wn * 64 + (lid & 7) + ((lid >> 4) & 1) * 8;
    const uint32_t ax = (uint32_t)((((lid >> 4) & 1) << 4) ^ (swz16(arow) << 4));
    const uint32_t bx = (uint32_t)((((lid >> 3) & 1) << 4) ^ (swz16(brow) << 4));
    const uint32_t aB0 = sb + (uint32_t)(arow * 64);
    const uint32_t bB0 = sb + PL_B_H + (uint32_t)(brow * 64);

    const int KT = K >> 5;
    issue_chunk(sb, tid, 0, K, Ahb, Alb, Bhb, Blb);
    CP_COMMIT();
    issue_chunk(sb + STAGE, tid, 32, K, Ahb, Alb, Bhb, Blb);
    CP_COMMIT();

    int stg = 0;
    for (int c = 0; c < KT; c++) {
        if (c + 1 < KT) { CP_WAIT(1); } else { CP_WAIT(0); }
        __syncthreads();
        const uint32_t so = (uint32_t)(stg * STAGE);
        compute_kt(acc, aB0 + so, bB0 + so, ax, bx, 0);
        if (c + 2 < KT) {
            int ns = stg + 2; if (ns >= 3) ns -= 3;
            issue_chunk(sb + ns * STAGE, tid, (c + 2) * 32, K, Ahb, Alb, Bhb, Blb);
            CP_COMMIT();
        }
        compute_kt(acc, aB0 + so, bB0 + so, ax, bx, 1);
        if (++stg == 3) stg = 0;
    }

    const int r0 = bm + wm * 32 + (lid >> 2);

    if (EPI == 2) {
        // fused ew + chunk-scan. Stage alpha AND xs tiles in smem simultaneously
        // (2 x 128x68 floats = 69632B <= 98304B), coalesced global stores, then
        // 64 threads compute the per-chunk scan reduction (g_cA/g_cB) in-place.
        const int hloc = wn * 32 + (lid & 3);
        const int h0 = (bn >> 1);
        float sp8[8], bgf[8], bgi[8];
#pragma unroll
        for (int nt = 0; nt < 8; nt++) {
            int h = h0 + hloc + nt * 4;
            float fb = fbase[h];
            sp8[nt] = fmaxf(fb, 0.f) + log1pf(expf(-fabsf(fb)));
            bgf[nt] = bg[h]; bgi[nt] = bg[H_ + h];
        }
        const int rloc0 = wm * 32 + (lid >> 2);
#pragma unroll
        for (int mt = 0; mt < 2; mt++)
#pragma unroll
            for (int nt = 0; nt < 8; nt++)
#pragma unroll
                for (int half = 0; half < 2; half++) {
                    int rl = rloc0 + mt * 16 + half * 8;
                    float forget = acc[mt][nt][half * 2 + 0] + bgf[nt];
                    float inp    = acc[mt][nt][half * 2 + 1] + bgi[nt];
                    float a = expf(-8.f * sp8[nt] * sigmoidf_(forget));
                    float beta = sqrtf(1.f - a * a + 1e-6f);
                    size_t ix = (size_t)(bm + rl) * H_ + h0 + hloc + nt * 4;
                    float xb = __bfloat162float(xbh[ix]) + __bfloat162float(xbl[ix]);
                    acc[mt][nt][half * 2 + 0] = a;
                    acc[mt][nt][half * 2 + 1] = beta * sigmoidf_(inp) * xb;
                }
        float* st_a = (float*)sm;
        float* st_x = (float*)sm + 128 * 68;
        __syncthreads();   // mainloop smem reads finished on all threads
#pragma unroll
        for (int mt = 0; mt < 2; mt++)
#pragma unroll
            for (int nt = 0; nt < 8; nt++)
#pragma unroll
                for (int half = 0; half < 2; half++) {
                    int rl = rloc0 + mt * 16 + half * 8;
                    st_a[rl * 68 + hloc + nt * 4] = acc[mt][nt][half * 2 + 0];
                    st_x[rl * 68 + hloc + nt * 4] = acc[mt][nt][half * 2 + 1];
                }
        __syncthreads();
        // coalesced stores for both tiles
#pragma unroll
        for (int it = 0; it < 8; it++) {
            int idx = it * 256 + tid;
            int row = idx >> 4, cc = (idx & 15) * 4;
            float4 va = *(float4*)&st_a[row * 68 + cc];
            float4 vx = *(float4*)&st_x[row * 68 + cc];
            *(float4*)&alpha_o[(size_t)(bm + row) * H_ + h0 + cc] = va;
            *(float4*)&xs_o   [(size_t)(bm + row) * H_ + h0 + cc] = vx;
        }
        // chunk-scan reduction: this tile is exactly chunk c of batch n, h0..h0+63
        if (tid < 64) {
            float A = 1.f, Bv = 0.f;
#pragma unroll 4
            for (int t = 0; t < 128; t++) {
                float a = st_a[t * 68 + tid];
                float xv = st_x[t * 68 + tid];
                Bv = fmaf(a, Bv, xv);
                A *= a;
            }
            int n = bm >> 12;                 // bm / T_
            int cch = (bm & (T_ - 1)) >> 7;   // chunk index
            int ci = (n * NC + cch) * H_ + h0 + tid;
            g_cA[ci] = A;
            g_cB[ci] = Bv;
        }
        return;
    }

    const bool dg = (EPI == 1) && (bn < H_);
    const int cbase = bn + wn * 64 + (lid & 3) * 2;
#pragma unroll
    for (int mt = 0; mt < 2; mt++) {
        const int row = r0 + mt * 16;
#pragma unroll
        for (int nt = 0; nt < 8; nt++) {
            const int col = cbase + nt * 8;
            float2 v0 = make_float2(acc[mt][nt][0], acc[mt][nt][1]);
            float2 v1 = make_float2(acc[mt][nt][2], acc[mt][nt][3]);
            if (dg) {
                v0.x = 0.5f * v0.x * (1.f + erff(v0.x * 0.70710678118654752f));
                v0.y = 0.5f * v0.y * (1.f + erff(v0.y * 0.70710678118654752f));
                v1.x = 0.5f * v1.x * (1.f + erff(v1.x * 0.70710678118654752f));
                v1.y = 0.5f * v1.y * (1.f + erff(v1.y * 0.70710678118654752f));
            }
            *(float2*)(C + (size_t)row * ldc + col) = v0;
            *(float2*)(C + (size_t)(row + 8) * ldc + col) = v1;
        }
    }
}

// -------- packing --------
__global__ void pack2(const float* __restrict__ s, __nv_bfloat16* __restrict__ hi,
                      __nv_bfloat16* __restrict__ lo, long long n4)
{
    long long i = (long long)blockIdx.x * blockDim.x + threadIdx.x;
    if (i >= n4) return;
    float4 f = *(const float4*)(s + i * 4);
    __nv_bfloat16 h[4], l[4];
    split_bf(f.x, h[0], l[0]); split_bf(f.y, h[1], l[1]);
    split_bf(f.z, h[2], l[2]); split_bf(f.w, h[3], l[3]);
    *(uint2*)(hi + i * 4) = *(uint2*)h;
    *(uint2*)(lo + i * 4) = *(uint2*)l;
}

// pack W_g with row permutation: packed row r = src row (r&1)*H_ + (r>>1)
__global__ void pack_wg(const float* __restrict__ s, __nv_bfloat16* __restrict__ hi,
                        __nv_bfloat16* __restrict__ lo)
{
    int idx = blockIdx.x * blockDim.x + threadIdx.x;
    if (idx >= G2H * (H_ / 4)) return;
    int r = idx / (H_ / 4);
    int c = (idx % (H_ / 4)) * 4;
    int sr = (r & 1) * H_ + (r >> 1);
    float4 f = *(const float4*)(s + (size_t)sr * H_ + c);
    __nv_bfloat16 h[4], l[4];
    split_bf(f.x, h[0], l[0]); split_bf(f.y, h[1], l[1]);
    split_bf(f.z, h[2], l[2]); split_bf(f.w, h[3], l[3]);
    *(uint2*)(hi + (size_t)r * H_ + c) = *(uint2*)h;
    *(uint2*)(lo + (size_t)r * H_ + c) = *(uint2*)l;
}

// -------- depthwise causal conv K=4, 4-t blocking -> bf16 planes --------
__global__ void conv_kernel(const float* __restrict__ cw, const float* __restrict__ cb)
{
    long long idx = (long long)blockIdx.x * blockDim.x + threadIdx.x;
    if (idx >= (long long)(M_ / 4) * H_) return;
    int h = (int)(idx % H_);
    long long q = idx / H_;
    int tq = (int)(q % (T_ / 4));
    long long n = q / (T_ / 4);
    const int t0 = tq * 4;
    const long long rowbase = (n * T_ + t0);

    float v[7];
#pragma unroll
    for (int j = 0; j < 7; j++) {
        int tt = t0 - 3 + j;
        v[j] = (tt >= 0) ? g_gx[(size_t)(n * T_ + tt) * G2H + H_ + h] : 0.f;
    }
    float w0 = cw[h * 4 + 0], w1 = cw[h * 4 + 1], w2 = cw[h * 4 + 2], w3 = cw[h * 4 + 3];
    float b = cb[h];
#pragma unroll
    for (int r = 0; r < 4; r++) {
        float acc = b;
        acc = fmaf(w0, v[r + 0], acc);
        acc = fmaf(w1, v[r + 1], acc);
        acc = fmaf(w2, v[r + 2], acc);
        acc = fmaf(w3, v[r + 3], acc);
        __nv_bfloat16 hi, lo;
        split_bf(acc, hi, lo);
        size_t ox = (size_t)(rowbase + r) * H_ + h;
        g_xbh[ox] = hi;
        g_xbl[ox] = lo;
    }
}

// -------- remaining scan phases (p1 fused into GEMM2 epilogue) --------
__global__ void scan_p2()
{
    int h = blockIdx.x * 128 + threadIdx.x;
    int n = blockIdx.y;
    float carry = 0.f;
    for (int c = 0; c < NC; c++) {
        int i = (n * NC + c) * H_ + h;
        float a = g_cA[i], b = g_cB[i];
        g_cB[i] = carry;
        carry = fmaf(a, carry, b);
    }
}

__global__ void scan_p3()   // replay; write (gelu(gate)*h) as bf16 planes
{
    int h = blockIdx.x * 128 + threadIdx.x;
    int c = blockIdx.y, n = blockIdx.z;
    size_t base  = ((size_t)(n * T_ + c * TC)) * H_ + h;
    size_t gbase = ((size_t)(n * T_ + c * TC)) * G2H + h;
    float hp = g_cB[(n * NC + c) * H_ + h];
#pragma unroll 4
    for (int t = 0; t < TC; t++) {
        float a = g_alpha[base + (size_t)t * H_];
        float x = g_xs   [base + (size_t)t * H_];
        hp = fmaf(a, hp, x);
        float g = g_gx[gbase + (size_t)t * G2H];   // gelu(gate)
        float v = hp * g;
        __nv_bfloat16 hi, lo;
        split_bf(v, hi, lo);
        g_yh[base + (size_t)t * H_] = hi;
        g_yl[base + (size_t)t * H_] = lo;
    }
}

// -------- launch --------
extern "C" void kernel_launch(void* const* d_in, const int* in_sizes, int n_in,
                              void* d_out, int out_size)
{
    const float* x      = (const float*)d_in[0];
    const float* W_in   = (const float*)d_in[1];
    const float* conv_w = (const float*)d_in[2];
    const float* conv_b = (const float*)d_in[3];
    const float* W_g    = (const float*)d_in[4];
    const float* b_g    = (const float*)d_in[5];
    const float* fbase  = (const float*)d_in[6];
    const float* W_out  = (const float*)d_in[7];
    float* out = (float*)d_out;

    float *gx, *alp, *xs;
    __nv_bfloat16 *xh, *xl, *xbh, *xbl, *yh, *yl, *wih, *wil, *wgh, *wgl, *woh, *wol;
    cudaGetSymbolAddress((void**)&gx,  g_gx);
    cudaGetSymbolAddress((void**)&alp, g_alpha);
    cudaGetSymbolAddress((void**)&xs,  g_xs);
    cudaGetSymbolAddress((void**)&xh,  g_xh);
    cudaGetSymbolAddress((void**)&xl,  g_xl);
    cudaGetSymbolAddress((void**)&xbh, g_xbh);
    cudaGetSymbolAddress((void**)&xbl, g_xbl);
    cudaGetSymbolAddress((void**)&yh,  g_yh);
    cudaGetSymbolAddress((void**)&yl,  g_yl);
    cudaGetSymbolAddress((void**)&wih, g_wih);
    cudaGetSymbolAddress((void**)&wil, g_wil);
    cudaGetSymbolAddress((void**)&wgh, g_wgh);
    cudaGetSymbolAddress((void**)&wgl, g_wgl);
    cudaGetSymbolAddress((void**)&woh, g_woh);
    cudaGetSymbolAddress((void**)&wol, g_wol);

    cudaFuncSetAttribute(gemm_mma<0>, cudaFuncAttributeMaxDynamicSharedMemorySize, GEMM_SMEM);
    cudaFuncSetAttribute(gemm_mma<1>, cudaFuncAttributeMaxDynamicSharedMemorySize, GEMM_SMEM);
    cudaFuncSetAttribute(gemm_mma<2>, cudaFuncAttributeMaxDynamicSharedMemorySize, GEMM_SMEM);

    // 0) pack x + weights to bf16 hi/lo planes
    pack2<<<(int)(((long long)M_*D_/4 + 255)/256), 256>>>(x, xh, xl, (long long)M_*D_/4);
    pack2<<<(G2H*D_/4 + 255)/256, 256>>>(W_in, wih, wil, (long long)G2H*D_/4);
    pack_wg<<<(G2H*(H_/4) + 255)/256, 256>>>(W_g, wgh, wgl);
    pack2<<<(D_*H_/4 + 255)/256, 256>>>(W_out, woh, wol, (long long)D_*H_/4);

    // 1) gx = x @ W_in^T; gelu fused on gate half
    gemm_mma<1><<<dim3(G2H/128, M_/128), 256, GEMM_SMEM>>>(
        xh, xl, wih, wil, gx, nullptr, nullptr, nullptr, nullptr, nullptr, nullptr, D_, G2H);
    // 2) depthwise causal conv -> xb planes (4-t blocking)
    conv_kernel<<<(int)(((long long)(M_/4)*H_ + 255)/256), 256>>>(conv_w, conv_b);
    // 3) fused ew GEMM -> alpha, xs, AND per-chunk scan reduction (g_cA/g_cB)
    gemm_mma<2><<<dim3(G2H/128, M_/128), 256, GEMM_SMEM>>>(
        xbh, xbl, wgh, wgl, nullptr, xbh, xbl, b_g, fbase, alp, xs, H_, 0);
    // 4) scan: carry propagation + replay (p1 fused into GEMM2)
    scan_p2<<<dim3(H_/128, N_), 128>>>();
    scan_p3<<<dim3(H_/128, NC, N_), 128>>>();
    // 5) out = (gelu(gate)*h) @ W_out^T
    gemm_mma<0><<<dim3(D_/128, M_/128), 256, GEMM_SMEM>>>(
        yh, yl, woh, wol, out, nullptr, nullptr, nullptr, nullptr, nullptr, nullptr, H_, D_);
}

// round 13
// speedup vs baseline: 1.5062x; 1.0104x over previous
#include <cuda_runtime.h>
#include <cuda_bf16.h>
#include <math.h>
#include <stdint.h>

#define N_  4
#define T_  4096
#define D_  1024
#define H_  1536
#define M_  (N_*T_)       // 16384 rows
#define G2H (2*H_)        // 3072
#define TC  128           // scan chunk length == GEMM M-tile
#define NC  (T_/TC)       // 32 chunks

// -------- scratch (device globals; no allocation allowed) --------
__device__ __align__(256) float g_gx  [(size_t)M_*G2H];   // gate half = gelu(gate); B-half: 6 boundary rows/tile only
__device__ __align__(256) float g_alpha[(size_t)M_*H_];
__device__ __align__(256) float g_xs  [(size_t)M_*H_];
__device__ __align__(256) float g_cA  [N_*NC*H_];
__device__ __align__(256) float g_cB  [N_*NC*H_];
// activation bf16 hi/lo planes
__device__ __align__(256) __nv_bfloat16 g_xh [(size_t)M_*D_];
__device__ __align__(256) __nv_bfloat16 g_xl [(size_t)M_*D_];
__device__ __align__(256) __nv_bfloat16 g_xbh[(size_t)M_*H_];   // conv out planes
__device__ __align__(256) __nv_bfloat16 g_xbl[(size_t)M_*H_];
__device__ __align__(256) __nv_bfloat16 g_yh [(size_t)M_*H_];   // gelu(gate)*h planes
__device__ __align__(256) __nv_bfloat16 g_yl [(size_t)M_*H_];
// weight bf16 hi/lo planes
__device__ __align__(256) __nv_bfloat16 g_wih[(size_t)G2H*D_];
__device__ __align__(256) __nv_bfloat16 g_wil[(size_t)G2H*D_];
__device__ __align__(256) __nv_bfloat16 g_wgh[(size_t)G2H*H_];  // rows permuted for EPI2
__device__ __align__(256) __nv_bfloat16 g_wgl[(size_t)G2H*H_];
__device__ __align__(256) __nv_bfloat16 g_woh[(size_t)D_*H_];
__device__ __align__(256) __nv_bfloat16 g_wol[(size_t)D_*H_];

// ======================= helpers =======================
__device__ __forceinline__ uint32_t smem_u32(const void* p) {
    uint32_t a;
    asm("{ .reg .u64 t; cvta.to.shared.u64 t, %1; cvt.u32.u64 %0, t; }" : "=r"(a) : "l"(p));
    return a;
}
__device__ __forceinline__ void ldmx4(uint32_t* r, uint32_t a) {
    asm volatile("ldmatrix.sync.aligned.m8n8.x4.shared.b16 {%0,%1,%2,%3}, [%4];"
        : "=r"(r[0]), "=r"(r[1]), "=r"(r[2]), "=r"(r[3]) : "r"(a));
}
__device__ __forceinline__ void mma16816(float* d, const uint32_t* a, const uint32_t* b) {
    asm volatile("mma.sync.aligned.m16n8k16.row.col.f32.bf16.bf16.f32 "
        "{%0,%1,%2,%3}, {%4,%5,%6,%7}, {%8,%9}, {%0,%1,%2,%3};"
        : "+f"(d[0]), "+f"(d[1]), "+f"(d[2]), "+f"(d[3])
        : "r"(a[0]), "r"(a[1]), "r"(a[2]), "r"(a[3]), "r"(b[0]), "r"(b[1]));
}
__device__ __forceinline__ void cpa16(uint32_t dst, const void* src) {
    asm volatile("cp.async.cg.shared.global [%0], [%1], 16;" :: "r"(dst), "l"(src));
}
#define CP_COMMIT()     asm volatile("cp.async.commit_group;" ::: "memory")
#define CP_WAIT(NN)     asm volatile("cp.async.wait_group %0;" :: "n"(NN) : "memory")
__device__ __forceinline__ float sigmoidf_(float v) { return 1.f / (1.f + expf(-v)); }
__device__ __forceinline__ void split_bf(float v, __nv_bfloat16& h, __nv_bfloat16& l) {
    h = __float2bfloat16(v);
    l = __float2bfloat16(v - __bfloat162float(h));
}

// ================== bf16x3 mma GEMM (all cp.async, 3-stage, swizzled) ==================
// Block tile 128x128x32, 256 threads (8 warps: 4(m) x 2(n)), warp tile 32x64.
// 64B smem rows with XOR swizzle. No cvt/STS in mainloop.
#define PL_A_H 0
#define PL_A_L 8192
#define PL_B_H 16384
#define PL_B_L 24576
#define STAGE  32768
#define GEMM_SMEM (3*STAGE)   // 98304

__device__ __forceinline__ int swz16(int row) {
    return ((row & 3) ^ ((row >> 2) & 3));
}

__device__ __forceinline__ void issue_chunk(
    uint32_t stg, int tid, int k0, int K,
    const __nv_bfloat16* __restrict__ Ah, const __nv_bfloat16* __restrict__ Al,
    const __nv_bfloat16* __restrict__ Bh, const __nv_bfloat16* __restrict__ Bl)
{
    const int col = tid & 3;
#pragma unroll
    for (int it = 0; it < 2; it++) {
        const int row = (tid + it * 256) >> 2;
        const uint32_t so = (uint32_t)(row * 64 + ((col ^ swz16(row)) << 4));
        const size_t go = (size_t)row * K + k0 + col * 8;
        cpa16(stg + PL_A_H + so, Ah + go);
        cpa16(stg + PL_A_L + so, Al + go);
        cpa16(stg + PL_B_H + so, Bh + go);
        cpa16(stg + PL_B_L + so, Bl + go);
    }
}

__device__ __forceinline__ void compute_kt(float acc[2][8][4],
    uint32_t aB, uint32_t bB, uint32_t ax, uint32_t bx, int kt)
{
    const uint32_t kc = (uint32_t)(kt << 5);
    uint32_t ah[2][4], al[2][4], bh[4][4], bl[4][4];
#pragma unroll
    for (int mt = 0; mt < 2; mt++) {
        ldmx4(ah[mt], aB + mt * 1024 + (kc ^ ax));
        ldmx4(al[mt], aB + PL_A_L + mt * 1024 + (kc ^ ax));
    }
#pragma unroll
    for (int n2 = 0; n2 < 4; n2++) {
        ldmx4(bh[n2], bB + n2 * 1024 + (kc ^ bx));
        ldmx4(bl[n2], bB + (PL_B_L - PL_B_H) + n2 * 1024 + (kc ^ bx));
    }
#pragma unroll
    for (int mt = 0; mt < 2; mt++)
#pragma unroll
        for (int nt = 0; nt < 8; nt++) {
            uint32_t* bph = &bh[nt >> 1][(nt & 1) * 2];
            uint32_t* bpl = &bl[nt >> 1][(nt & 1) * 2];
            mma16816(acc[mt][nt], ah[mt], bph);
            mma16816(acc[mt][nt], ah[mt], bpl);
            mma16816(acc[mt][nt], al[mt], bph);
        }
}

// EPI: 0 = plain, 1 = GEMM1 (gate: gelu store; B-half: fused causal conv), 2 = fused ew + chunk-scan
template<int EPI>
__global__ __launch_bounds__(256, 2)
void gemm_mma(const __nv_bfloat16* __restrict__ Ah, const __nv_bfloat16* __restrict__ Al,
              const __nv_bfloat16* __restrict__ Bh, const __nv_bfloat16* __restrict__ Bl,
              float* __restrict__ C,
              const __nv_bfloat16* __restrict__ xbh, const __nv_bfloat16* __restrict__ xbl,
              const float* __restrict__ bg, const float* __restrict__ fbase,
              float* __restrict__ alpha_o, float* __restrict__ xs_o,
              const float* __restrict__ cw_, const float* __restrict__ cb_,
              __nv_bfloat16* __restrict__ oxh, __nv_bfloat16* __restrict__ oxl,
              int K, int ldc)
{
    extern __shared__ char sm[];
    const int tid = threadIdx.x;
    const int lid = tid & 31, wid = tid >> 5;
    const int wm = wid >> 1, wn = wid & 1;
    const int bm = blockIdx.y * 128;
    const int bn = blockIdx.x * 128;

    const __nv_bfloat16* Ahb = Ah + (size_t)bm * K;
    const __nv_bfloat16* Alb = Al + (size_t)bm * K;
    const __nv_bfloat16* Bhb = Bh + (size_t)bn * K;
    const __nv_bfloat16* Blb = Bl + (size_t)bn * K;

    float acc[2][8][4];
#pragma unroll
    for (int i = 0; i < 2; i++)
#pragma unroll
        for (int j = 0; j < 8; j++)
#pragma unroll
            for (int q = 0; q < 4; q++) acc[i][j][q] = 0.f;

    const uint32_t sb = smem_u32(sm);
    const int arow = wm * 32 + (lid & 15);
    const int brow = wn * 64 + (lid & 7) + ((lid >> 4) & 1) * 8;
    const uint32_t ax = (uint32_t)((((lid >> 4) & 1) << 4) ^ (swz16(arow) << 4));
    const uint32_t bx = (uint32_t)((((lid >> 3) & 1) << 4) ^ (swz16(brow) << 4));
    const uint32_t aB0 = sb + (uint32_t)(arow * 64);
    const uint32_t bB0 = sb + PL_B_H + (uint32_t)(brow * 64);

    const int KT = K >> 5;
    issue_chunk(sb, tid, 0, K, Ahb, Alb, Bhb, Blb);
    CP_COMMIT();
    issue_chunk(sb + STAGE, tid, 32, K, Ahb, Alb, Bhb, Blb);
    CP_COMMIT();

    int stg = 0;
    for (int c = 0; c < KT; c++) {
        if (c + 1 < KT) { CP_WAIT(1); } else { CP_WAIT(0); }
        __syncthreads();
        const uint32_t so = (uint32_t)(stg * STAGE);
        compute_kt(acc, aB0 + so, bB0 + so, ax, bx, 0);
        if (c + 2 < KT) {
            int ns = stg + 2; if (ns >= 3) ns -= 3;
            issue_chunk(sb + ns * STAGE, tid, (c + 2) * 32, K, Ahb, Alb, Bhb, Blb);
            CP_COMMIT();
        }
        compute_kt(acc, aB0 + so, bB0 + so, ax, bx, 1);
        if (++stg == 3) stg = 0;
    }

    const int r0 = bm + wm * 32 + (lid >> 2);

    if (EPI == 2) {
        // fused ew + chunk-scan (as R12)
        const int hloc = wn * 32 + (lid & 3);
        const int h0 = (bn >> 1);
        float sp8[8], bgf[8], bgi[8];
#pragma unroll
        for (int nt = 0; nt < 8; nt++) {
            int h = h0 + hloc + nt * 4;
            float fb = fbase[h];
            sp8[nt] = fmaxf(fb, 0.f) + log1pf(expf(-fabsf(fb)));
            bgf[nt] = bg[h]; bgi[nt] = bg[H_ + h];
        }
        const int rloc0 = wm * 32 + (lid >> 2);
#pragma unroll
        for (int mt = 0; mt < 2; mt++)
#pragma unroll
            for (int nt = 0; nt < 8; nt++)
#pragma unroll
                for (int half = 0; half < 2; half++) {
                    int rl = rloc0 + mt * 16 + half * 8;
                    float forget = acc[mt][nt][half * 2 + 0] + bgf[nt];
                    float inp    = acc[mt][nt][half * 2 + 1] + bgi[nt];
                    float a = expf(-8.f * sp8[nt] * sigmoidf_(forget));
                    float beta = sqrtf(1.f - a * a + 1e-6f);
                    size_t ix = (size_t)(bm + rl) * H_ + h0 + hloc + nt * 4;
                    float xb = __bfloat162float(xbh[ix]) + __bfloat162float(xbl[ix]);
                    acc[mt][nt][half * 2 + 0] = a;
                    acc[mt][nt][half * 2 + 1] = beta * sigmoidf_(inp) * xb;
                }
        float* st_a = (float*)sm;
        float* st_x = (float*)sm + 128 * 68;
        __syncthreads();
#pragma unroll
        for (int mt = 0; mt < 2; mt++)
#pragma unroll
            for (int nt = 0; nt < 8; nt++)
#pragma unroll
                for (int half = 0; half < 2; half++) {
                    int rl = rloc0 + mt * 16 + half * 8;
                    st_a[rl * 68 + hloc + nt * 4] = acc[mt][nt][half * 2 + 0];
                    st_x[rl * 68 + hloc + nt * 4] = acc[mt][nt][half * 2 + 1];
                }
        __syncthreads();
#pragma unroll
        for (int it = 0; it < 8; it++) {
            int idx = it * 256 + tid;
            int row = idx >> 4, cc = (idx & 15) * 4;
            float4 va = *(float4*)&st_a[row * 68 + cc];
            float4 vx = *(float4*)&st_x[row * 68 + cc];
            *(float4*)&alpha_o[(size_t)(bm + row) * H_ + h0 + cc] = va;
            *(float4*)&xs_o   [(size_t)(bm + row) * H_ + h0 + cc] = vx;
        }
        if (tid < 64) {
            float A = 1.f, Bv = 0.f;
#pragma unroll 4
            for (int t = 0; t < 128; t++) {
                float a = st_a[t * 68 + tid];
                float xv = st_x[t * 68 + tid];
                Bv = fmaf(a, Bv, xv);
                A *= a;
            }
            int n = bm >> 12;
            int cch = (bm & (T_ - 1)) >> 7;
            int ci = (n * NC + cch) * H_ + h0 + tid;
            g_cA[ci] = A;
            g_cB[ci] = Bv;
        }
        return;
    }

    if (EPI == 1 && bn >= H_) {
        // fused depthwise causal conv (B-half of GEMM1). Tile = 128 consecutive t
        // of one batch x 128 h. Stage tile in smem, conv rows 3..127 locally;
        // rows 0..2 handled by conv_boundary; store only 6 boundary rows of raw gx.
        float* st = (float*)sm;
        const int rl0 = wm * 32 + (lid >> 2);
        const int cl0 = wn * 64 + (lid & 3) * 2;
        __syncthreads();   // mainloop smem reads done
#pragma unroll
        for (int mt = 0; mt < 2; mt++)
#pragma unroll
            for (int nt = 0; nt < 8; nt++)
#pragma unroll
                for (int half = 0; half < 2; half++) {
                    int rl = rl0 + mt * 16 + half * 8;
                    int cl = cl0 + nt * 8;
                    st[rl * 132 + cl]     = acc[mt][nt][half * 2 + 0];
                    st[rl * 132 + cl + 1] = acc[mt][nt][half * 2 + 1];
                }
        __syncthreads();
        const int hb = bn - H_;
        // raw gx stores for boundary rows {0,1,2,125,126,127}
        {
            int i = tid;
#pragma unroll
            for (int it = 0; it < 3; it++, i += 256) {
                int ri = i >> 7;
                int cc = i & 127;
                int row = (ri < 3) ? ri : (122 + ri);
                C[(size_t)(bm + row) * ldc + H_ + hb + cc] = st[row * 132 + cc];
            }
        }
        // conv interior rows 3..127
        const int c = tid & 127;
        const int h = hb + c;
        const float w0 = cw_[h * 4 + 0], w1 = cw_[h * 4 + 1];
        const float w2 = cw_[h * 4 + 2], w3 = cw_[h * 4 + 3];
        const float bb = cb_[h];
        for (int r = 3 + (tid >> 7); r < 128; r += 2) {
            float a = bb;
            a = fmaf(w0, st[(r - 3) * 132 + c], a);
            a = fmaf(w1, st[(r - 2) * 132 + c], a);
            a = fmaf(w2, st[(r - 1) * 132 + c], a);
            a = fmaf(w3, st[(r - 0) * 132 + c], a);
            __nv_bfloat16 hi, lo;
            split_bf(a, hi, lo);
            size_t ox = (size_t)(bm + r) * H_ + h;
            oxh[ox] = hi;
            oxl[ox] = lo;
        }
        return;
    }

    // EPI0 plain / EPI1 gate half (gelu)
    const bool dg = (EPI == 1);
    const int cbase = bn + wn * 64 + (lid & 3) * 2;
#pragma unroll
    for (int mt = 0; mt < 2; mt++) {
        const int row = r0 + mt * 16;
#pragma unroll
        for (int nt = 0; nt < 8; nt++) {
            const int col = cbase + nt * 8;
            float2 v0 = make_float2(acc[mt][nt][0], acc[mt][nt][1]);
            float2 v1 = make_float2(acc[mt][nt][2], acc[mt][nt][3]);
            if (dg) {
                v0.x = 0.5f * v0.x * (1.f + erff(v0.x * 0.70710678118654752f));
                v0.y = 0.5f * v0.y * (1.f + erff(v0.y * 0.70710678118654752f));
                v1.x = 0.5f * v1.x * (1.f + erff(v1.x * 0.70710678118654752f));
                v1.y = 0.5f * v1.y * (1.f + erff(v1.y * 0.70710678118654752f));
            }
            *(float2*)(C + (size_t)row * ldc + col) = v0;
            *(float2*)(C + (size_t)(row + 8) * ldc + col) = v1;
        }
    }
}

// -------- conv boundary rows (0..2 of each 128-row tile) --------
__global__ void conv_boundary(const float* __restrict__ cw, const float* __restrict__ cb)
{
    int idx = blockIdx.x * blockDim.x + threadIdx.x;
    if (idx >= (M_ / 128) * 3 * H_) return;
    int h = idx % H_;
    int q = idx / H_;
    int r = q % 3;
    int tile = q / 3;
    int m = tile * 128 + r;
    int n = m / T_, t = m % T_;
    float a = cb[h];
#pragma unroll
    for (int k = 0; k < 4; k++) {
        int tt = t - 3 + k;
        if (tt >= 0)
            a = fmaf(cw[h * 4 + k], g_gx[(size_t)(n * T_ + tt) * G2H + H_ + h], a);
    }
    __nv_bfloat16 hi, lo;
    split_bf(a, hi, lo);
    g_xbh[(size_t)m * H_ + h] = hi;
    g_xbl[(size_t)m * H_ + h] = lo;
}

// -------- packing --------
__global__ void pack2(const float* __restrict__ s, __nv_bfloat16* __restrict__ hi,
                      __nv_bfloat16* __restrict__ lo, long long n4)
{
    long long i = (long long)blockIdx.x * blockDim.x + threadIdx.x;
    if (i >= n4) return;
    float4 f = *(const float4*)(s + i * 4);
    __nv_bfloat16 h[4], l[4];
    split_bf(f.x, h[0], l[0]); split_bf(f.y, h[1], l[1]);
    split_bf(f.z, h[2], l[2]); split_bf(f.w, h[3], l[3]);
    *(uint2*)(hi + i * 4) = *(uint2*)h;
    *(uint2*)(lo + i * 4) = *(uint2*)l;
}

// pack W_g with row permutation: packed row r = src row (r&1)*H_ + (r>>1)
__global__ void pack_wg(const float* __restrict__ s, __nv_bfloat16* __restrict__ hi,
                        __nv_bfloat16* __restrict__ lo)
{
    int idx = blockIdx.x * blockDim.x + threadIdx.x;
    if (idx >= G2H * (H_ / 4)) return;
    int r = idx / (H_ / 4);
    int c = (idx % (H_ / 4)) * 4;
    int sr = (r & 1) * H_ + (r >> 1);
    float4 f = *(const float4*)(s + (size_t)sr * H_ + c);
    __nv_bfloat16 h[4], l[4];
    split_bf(f.x, h[0], l[0]); split_bf(f.y, h[1], l[1]);
    split_bf(f.z, h[2], l[2]); split_bf(f.w, h[3], l[3]);
    *(uint2*)(hi + (size_t)r * H_ + c) = *(uint2*)h;
    *(uint2*)(lo + (size_t)r * H_ + c) = *(uint2*)l;
}

// -------- remaining scan phases (p1 fused into GEMM2 epilogue) --------
__global__ void scan_p2()
{
    int h = blockIdx.x * 128 + threadIdx.x;
    int n = blockIdx.y;
    float carry = 0.f;
    for (int c = 0; c < NC; c++) {
        int i = (n * NC + c) * H_ + h;
        float a = g_cA[i], b = g_cB[i];
        g_cB[i] = carry;
        carry = fmaf(a, carry, b);
    }
}

__global__ void scan_p3()   // replay; write (gelu(gate)*h) as bf16 planes
{
    int h = blockIdx.x * 128 + threadIdx.x;
    int c = blockIdx.y, n = blockIdx.z;
    size_t base  = ((size_t)(n * T_ + c * TC)) * H_ + h;
    size_t gbase = ((size_t)(n * T_ + c * TC)) * G2H + h;
    float hp = g_cB[(n * NC + c) * H_ + h];
#pragma unroll 4
    for (int t = 0; t < TC; t++) {
        float a = g_alpha[base + (size_t)t * H_];
        float x = g_xs   [base + (size_t)t * H_];
        hp = fmaf(a, hp, x);
        float g = g_gx[gbase + (size_t)t * G2H];   // gelu(gate)
        float v = hp * g;
        __nv_bfloat16 hi, lo;
        split_bf(v, hi, lo);
        g_yh[base + (size_t)t * H_] = hi;
        g_yl[base + (size_t)t * H_] = lo;
    }
}

// -------- launch --------
extern "C" void kernel_launch(void* const* d_in, const int* in_sizes, int n_in,
                              void* d_out, int out_size)
{
    const float* x      = (const float*)d_in[0];
    const float* W_in   = (const float*)d_in[1];
    const float* conv_w = (const float*)d_in[2];
    const float* conv_b = (const float*)d_in[3];
    const float* W_g    = (const float*)d_in[4];
    const float* b_g    = (const float*)d_in[5];
    const float* fbase  = (const float*)d_in[6];
    const float* W_out  = (const float*)d_in[7];
    float* out = (float*)d_out;

    float *gx, *alp, *xs;
    __nv_bfloat16 *xh, *xl, *xbh, *xbl, *yh, *yl, *wih, *wil, *wgh, *wgl, *woh, *wol;
    cudaGetSymbolAddress((void**)&gx,  g_gx);
    cudaGetSymbolAddress((void**)&alp, g_alpha);
    cudaGetSymbolAddress((void**)&xs,  g_xs);
    cudaGetSymbolAddress((void**)&xh,  g_xh);
    cudaGetSymbolAddress((void**)&xl,  g_xl);
    cudaGetSymbolAddress((void**)&xbh, g_xbh);
    cudaGetSymbolAddress((void**)&xbl, g_xbl);
    cudaGetSymbolAddress((void**)&yh,  g_yh);
    cudaGetSymbolAddress((void**)&yl,  g_yl);
    cudaGetSymbolAddress((void**)&wih, g_wih);
    cudaGetSymbolAddress((void**)&wil, g_wil);
    cudaGetSymbolAddress((void**)&wgh, g_wgh);
    cudaGetSymbolAddress((void**)&wgl, g_wgl);
    cudaGetSymbolAddress((void**)&woh, g_woh);
    cudaGetSymbolAddress((void**)&wol, g_wol);

    cudaFuncSetAttribute(gemm_mma<0>, cudaFuncAttributeMaxDynamicSharedMemorySize, GEMM_SMEM);
    cudaFuncSetAttribute(gemm_mma<1>, cudaFuncAttributeMaxDynamicSharedMemorySize, GEMM_SMEM);
    cudaFuncSetAttribute(gemm_mma<2>, cudaFuncAttributeMaxDynamicSharedMemorySize, GEMM_SMEM);

    // 0) pack x + weights to bf16 hi/lo planes
    pack2<<<(int)(((long long)M_*D_/4 + 255)/256), 256>>>(x, xh, xl, (long long)M_*D_/4);
    pack2<<<(G2H*D_/4 + 255)/256, 256>>>(W_in, wih, wil, (long long)G2H*D_/4);
    pack_wg<<<(G2H*(H_/4) + 255)/256, 256>>>(W_g, wgh, wgl);
    pack2<<<(D_*H_/4 + 255)/256, 256>>>(W_out, woh, wol, (long long)D_*H_/4);

    // 1) gx = x @ W_in^T; gate half: gelu; B-half: fused causal conv -> xb planes
    gemm_mma<1><<<dim3(G2H/128, M_/128), 256, GEMM_SMEM>>>(
        xh, xl, wih, wil, gx, nullptr, nullptr, nullptr, nullptr, nullptr, nullptr,
        conv_w, conv_b, xbh, xbl, D_, G2H);
    // 1b) conv boundary rows (first 3 of each 128-row tile)
    conv_boundary<<<((M_/128)*3*H_ + 255)/256, 256>>>(conv_w, conv_b);
    // 2) fused ew GEMM -> alpha, xs, AND per-chunk scan reduction
    gemm_mma<2><<<dim3(G2H/128, M_/128), 256, GEMM_SMEM>>>(
        xbh, xbl, wgh, wgl, nullptr, xbh, xbl, b_g, fbase, alp, xs,
        nullptr, nullptr, nullptr, nullptr, H_, 0);
    // 3) scan: carry propagation + replay
    scan_p2<<<dim3(H_/128, N_), 128>>>();
    scan_p3<<<dim3(H_/128, NC, N_), 128>>>();
    // 4) out = (gelu(gate)*h) @ W_out^T
    gemm_mma<0><<<dim3(D_/128, M_/128), 256, GEMM_SMEM>>>(
        yh, yl, woh, wol, out, nullptr, nullptr, nullptr, nullptr, nullptr, nullptr,
        nullptr, nullptr, nullptr, nullptr, H_, D_);
}

// round 14
// speedup vs baseline: 1.5462x; 1.0266x over previous
#include <cuda_runtime.h>
#include <cuda_bf16.h>
#include <math.h>
#include <stdint.h>

#define N_  4
#define T_  4096
#define D_  1024
#define H_  1536
#define M_  (N_*T_)       // 16384 rows
#define G2H (2*H_)        // 3072
#define TC  128           // scan chunk length == GEMM M-tile
#define NC  (T_/TC)       // 32 chunks

// -------- scratch (device globals; no allocation allowed) --------
__device__ __align__(256) float g_gx  [(size_t)M_*G2H];   // gate half = gelu(gate); B-half: boundary rows only
__device__ __align__(256) float g_alpha[(size_t)M_*H_];
__device__ __align__(256) float g_xs  [(size_t)M_*H_];
__device__ __align__(256) float g_cA  [N_*NC*H_];
__device__ __align__(256) float g_cB  [N_*NC*H_];
// activation bf16 hi/lo planes
__device__ __align__(256) __nv_bfloat16 g_xh [(size_t)M_*D_];
__device__ __align__(256) __nv_bfloat16 g_xl [(size_t)M_*D_];
__device__ __align__(256) __nv_bfloat16 g_xbh[(size_t)M_*H_];
__device__ __align__(256) __nv_bfloat16 g_xbl[(size_t)M_*H_];
__device__ __align__(256) __nv_bfloat16 g_yh [(size_t)M_*H_];
__device__ __align__(256) __nv_bfloat16 g_yl [(size_t)M_*H_];
// weight bf16 hi/lo planes
__device__ __align__(256) __nv_bfloat16 g_wih[(size_t)G2H*D_];
__device__ __align__(256) __nv_bfloat16 g_wil[(size_t)G2H*D_];
__device__ __align__(256) __nv_bfloat16 g_wgh[(size_t)G2H*H_];  // rows permuted for EPI2
__device__ __align__(256) __nv_bfloat16 g_wgl[(size_t)G2H*H_];
__device__ __align__(256) __nv_bfloat16 g_woh[(size_t)D_*H_];
__device__ __align__(256) __nv_bfloat16 g_wol[(size_t)D_*H_];

// ======================= helpers =======================
__device__ __forceinline__ uint32_t smem_u32(const void* p) {
    uint32_t a;
    asm("{ .reg .u64 t; cvta.to.shared.u64 t, %1; cvt.u32.u64 %0, t; }" : "=r"(a) : "l"(p));
    return a;
}
__device__ __forceinline__ void ldmx4(uint32_t* r, uint32_t a) {
    asm volatile("ldmatrix.sync.aligned.m8n8.x4.shared.b16 {%0,%1,%2,%3}, [%4];"
        : "=r"(r[0]), "=r"(r[1]), "=r"(r[2]), "=r"(r[3]) : "r"(a));
}
__device__ __forceinline__ void mma16816(float* d, const uint32_t* a, const uint32_t* b) {
    asm volatile("mma.sync.aligned.m16n8k16.row.col.f32.bf16.bf16.f32 "
        "{%0,%1,%2,%3}, {%4,%5,%6,%7}, {%8,%9}, {%0,%1,%2,%3};"
        : "+f"(d[0]), "+f"(d[1]), "+f"(d[2]), "+f"(d[3])
        : "r"(a[0]), "r"(a[1]), "r"(a[2]), "r"(a[3]), "r"(b[0]), "r"(b[1]));
}
__device__ __forceinline__ void cpa16(uint32_t dst, const void* src) {
    asm volatile("cp.async.cg.shared.global [%0], [%1], 16;" :: "r"(dst), "l"(src));
}
#define CP_COMMIT()     asm volatile("cp.async.commit_group;" ::: "memory")
#define CP_WAIT(NN)     asm volatile("cp.async.wait_group %0;" :: "n"(NN) : "memory")
__device__ __forceinline__ float sigmoidf_(float v) { return 1.f / (1.f + expf(-v)); }
__device__ __forceinline__ void split_bf(float v, __nv_bfloat16& h, __nv_bfloat16& l) {
    h = __float2bfloat16(v);
    l = __float2bfloat16(v - __bfloat162float(h));
}

// ================== bf16x3 mma GEMM (all cp.async, 3-stage, swizzled) ==================
#define PL_A_H 0
#define PL_A_L 8192
#define PL_B_H 16384
#define PL_B_L 24576
#define STAGE  32768
#define GEMM_SMEM (3*STAGE)   // 98304

__device__ __forceinline__ int swz16(int row) {
    return ((row & 3) ^ ((row >> 2) & 3));
}

// persistent per-thread load pointers, advanced by +32 elements per chunk
struct LoadPtrs {
    const __nv_bfloat16 *a0, *a1, *b0, *b1;   // hi-plane ptrs for it=0/1 rows
    const __nv_bfloat16 *la0, *la1, *lb0, *lb1;
    uint32_t so0, so1;                         // smem offsets (stage-relative)
};

__device__ __forceinline__ LoadPtrs make_ptrs(int tid, int K,
    const __nv_bfloat16* Ah, const __nv_bfloat16* Al,
    const __nv_bfloat16* Bh, const __nv_bfloat16* Bl)
{
    LoadPtrs p;
    const int col = tid & 3;
    const int r0 = tid >> 2, r1 = (tid + 256) >> 2;
    const size_t g0 = (size_t)r0 * K + col * 8;
    const size_t g1 = (size_t)r1 * K + col * 8;
    p.a0 = Ah + g0;  p.a1 = Ah + g1;
    p.la0 = Al + g0; p.la1 = Al + g1;
    p.b0 = Bh + g0;  p.b1 = Bh + g1;
    p.lb0 = Bl + g0; p.lb1 = Bl + g1;
    p.so0 = (uint32_t)(r0 * 64 + ((col ^ swz16(r0)) << 4));
    p.so1 = (uint32_t)(r1 * 64 + ((col ^ swz16(r1)) << 4));
    return p;
}

__device__ __forceinline__ void issue_chunk(uint32_t stg, LoadPtrs& p) {
    cpa16(stg + PL_A_H + p.so0, p.a0);
    cpa16(stg + PL_A_L + p.so0, p.la0);
    cpa16(stg + PL_B_H + p.so0, p.b0);
    cpa16(stg + PL_B_L + p.so0, p.lb0);
    cpa16(stg + PL_A_H + p.so1, p.a1);
    cpa16(stg + PL_A_L + p.so1, p.la1);
    cpa16(stg + PL_B_H + p.so1, p.b1);
    cpa16(stg + PL_B_L + p.so1, p.lb1);
    p.a0 += 32; p.a1 += 32; p.la0 += 32; p.la1 += 32;
    p.b0 += 32; p.b1 += 32; p.lb0 += 32; p.lb1 += 32;
}

__device__ __forceinline__ void compute_kt(float acc[2][8][4],
    uint32_t aB, uint32_t bB, uint32_t ax, uint32_t bx, int kt)
{
    const uint32_t kc = (uint32_t)(kt << 5);
    uint32_t ah[2][4], al[2][4], bh[4][4], bl[4][4];
#pragma unroll
    for (int mt = 0; mt < 2; mt++) {
        ldmx4(ah[mt], aB + mt * 1024 + (kc ^ ax));
        ldmx4(al[mt], aB + PL_A_L + mt * 1024 + (kc ^ ax));
    }
#pragma unroll
    for (int n2 = 0; n2 < 4; n2++) {
        ldmx4(bh[n2], bB + n2 * 1024 + (kc ^ bx));
        ldmx4(bl[n2], bB + (PL_B_L - PL_B_H) + n2 * 1024 + (kc ^ bx));
    }
#pragma unroll
    for (int mt = 0; mt < 2; mt++)
#pragma unroll
        for (int nt = 0; nt < 8; nt++) {
            uint32_t* bph = &bh[nt >> 1][(nt & 1) * 2];
            uint32_t* bpl = &bl[nt >> 1][(nt & 1) * 2];
            mma16816(acc[mt][nt], ah[mt], bph);
            mma16816(acc[mt][nt], ah[mt], bpl);
            mma16816(acc[mt][nt], al[mt], bph);
        }
}

// EPI: 0 = plain, 1 = GEMM1 (gate: gelu; B-half: fused conv), 2 = fused ew + chunk-scan
template<int EPI>
__global__ __launch_bounds__(256, 2)
void gemm_mma(const __nv_bfloat16* __restrict__ Ah, const __nv_bfloat16* __restrict__ Al,
              const __nv_bfloat16* __restrict__ Bh, const __nv_bfloat16* __restrict__ Bl,
              float* __restrict__ C,
              const __nv_bfloat16* __restrict__ xbh, const __nv_bfloat16* __restrict__ xbl,
              const float* __restrict__ bg, const float* __restrict__ fbase,
              float* __restrict__ alpha_o, float* __restrict__ xs_o,
              const float* __restrict__ cw_, const float* __restrict__ cb_,
              __nv_bfloat16* __restrict__ oxh, __nv_bfloat16* __restrict__ oxl,
              int K, int ldc)
{
    extern __shared__ char sm[];
    const int tid = threadIdx.x;
    const int lid = tid & 31, wid = tid >> 5;
    const int wm = wid >> 1, wn = wid & 1;
    const int bm = blockIdx.y * 128;
    const int bn = blockIdx.x * 128;

    LoadPtrs lp = make_ptrs(tid, K,
        Ah + (size_t)bm * K, Al + (size_t)bm * K,
        Bh + (size_t)bn * K, Bl + (size_t)bn * K);

    float acc[2][8][4];
#pragma unroll
    for (int i = 0; i < 2; i++)
#pragma unroll
        for (int j = 0; j < 8; j++)
#pragma unroll
            for (int q = 0; q < 4; q++) acc[i][j][q] = 0.f;

    const uint32_t sb = smem_u32(sm);
    const int arow = wm * 32 + (lid & 15);
    const int brow = wn * 64 + (lid & 7) + ((lid >> 4) & 1) * 8;
    const uint32_t ax = (uint32_t)((((lid >> 4) & 1) << 4) ^ (swz16(arow) << 4));
    const uint32_t bx = (uint32_t)((((lid >> 3) & 1) << 4) ^ (swz16(brow) << 4));
    const uint32_t aB0 = sb + (uint32_t)(arow * 64);
    const uint32_t bB0 = sb + PL_B_H + (uint32_t)(brow * 64);

    const int KT = K >> 5;
    issue_chunk(sb, lp);
    CP_COMMIT();
    issue_chunk(sb + STAGE, lp);
    CP_COMMIT();

    int stg = 0;
    for (int c = 0; c < KT; c++) {
        if (c + 1 < KT) { CP_WAIT(1); } else { CP_WAIT(0); }
        __syncthreads();
        const uint32_t so = (uint32_t)(stg * STAGE);
        compute_kt(acc, aB0 + so, bB0 + so, ax, bx, 0);
        if (c + 2 < KT) {
            int ns = stg + 2; if (ns >= 3) ns -= 3;
            issue_chunk(sb + ns * STAGE, lp);
            CP_COMMIT();
        }
        compute_kt(acc, aB0 + so, bB0 + so, ax, bx, 1);
        if (++stg == 3) stg = 0;
    }

    const int r0 = bm + wm * 32 + (lid >> 2);

    if (EPI == 2) {
        const int hloc = wn * 32 + (lid & 3);
        const int h0 = (bn >> 1);
        float sp8[8], bgf[8], bgi[8];
#pragma unroll
        for (int nt = 0; nt < 8; nt++) {
            int h = h0 + hloc + nt * 4;
            float fb = fbase[h];
            sp8[nt] = fmaxf(fb, 0.f) + log1pf(expf(-fabsf(fb)));
            bgf[nt] = bg[h]; bgi[nt] = bg[H_ + h];
        }
        const int rloc0 = wm * 32 + (lid >> 2);
#pragma unroll
        for (int mt = 0; mt < 2; mt++)
#pragma unroll
            for (int nt = 0; nt < 8; nt++)
#pragma unroll
                for (int half = 0; half < 2; half++) {
                    int rl = rloc0 + mt * 16 + half * 8;
                    float forget = acc[mt][nt][half * 2 + 0] + bgf[nt];
                    float inp    = acc[mt][nt][half * 2 + 1] + bgi[nt];
                    float a = expf(-8.f * sp8[nt] * sigmoidf_(forget));
                    float beta = sqrtf(1.f - a * a + 1e-6f);
                    size_t ix = (size_t)(bm + rl) * H_ + h0 + hloc + nt * 4;
                    float xb = __bfloat162float(xbh[ix]) + __bfloat162float(xbl[ix]);
                    acc[mt][nt][half * 2 + 0] = a;
                    acc[mt][nt][half * 2 + 1] = beta * sigmoidf_(inp) * xb;
                }
        float* st_a = (float*)sm;
        float* st_x = (float*)sm + 128 * 68;
        __syncthreads();
#pragma unroll
        for (int mt = 0; mt < 2; mt++)
#pragma unroll
            for (int nt = 0; nt < 8; nt++)
#pragma unroll
                for (int half = 0; half < 2; half++) {
                    int rl = rloc0 + mt * 16 + half * 8;
                    st_a[rl * 68 + hloc + nt * 4] = acc[mt][nt][half * 2 + 0];
                    st_x[rl * 68 + hloc + nt * 4] = acc[mt][nt][half * 2 + 1];
                }
        __syncthreads();
#pragma unroll
        for (int it = 0; it < 8; it++) {
            int idx = it * 256 + tid;
            int row = idx >> 4, cc = (idx & 15) * 4;
            float4 va = *(float4*)&st_a[row * 68 + cc];
            float4 vx = *(float4*)&st_x[row * 68 + cc];
            *(float4*)&alpha_o[(size_t)(bm + row) * H_ + h0 + cc] = va;
            *(float4*)&xs_o   [(size_t)(bm + row) * H_ + h0 + cc] = vx;
        }
        if (tid < 64) {
            float A = 1.f, Bv = 0.f;
#pragma unroll 4
            for (int t = 0; t < 128; t++) {
                float a = st_a[t * 68 + tid];
                float xv = st_x[t * 68 + tid];
                Bv = fmaf(a, Bv, xv);
                A *= a;
            }
            int n = bm >> 12;
            int cch = (bm & (T_ - 1)) >> 7;
            int ci = (n * NC + cch) * H_ + h0 + tid;
            g_cA[ci] = A;
            g_cB[ci] = Bv;
        }
        return;
    }

    if (EPI == 1 && bn >= H_) {
        float* st = (float*)sm;
        const int rl0 = wm * 32 + (lid >> 2);
        const int cl0 = wn * 64 + (lid & 3) * 2;
        __syncthreads();
#pragma unroll
        for (int mt = 0; mt < 2; mt++)
#pragma unroll
            for (int nt = 0; nt < 8; nt++)
#pragma unroll
                for (int half = 0; half < 2; half++) {
                    int rl = rl0 + mt * 16 + half * 8;
                    int cl = cl0 + nt * 8;
                    st[rl * 132 + cl]     = acc[mt][nt][half * 2 + 0];
                    st[rl * 132 + cl + 1] = acc[mt][nt][half * 2 + 1];
                }
        __syncthreads();
        const int hb = bn - H_;
        {
            int i = tid;
#pragma unroll
            for (int it = 0; it < 3; it++, i += 256) {
                int ri = i >> 7;
                int cc = i & 127;
                int row = (ri < 3) ? ri : (122 + ri);
                C[(size_t)(bm + row) * ldc + H_ + hb + cc] = st[row * 132 + cc];
            }
        }
        const int c = tid & 127;
        const int h = hb + c;
        const float w0 = cw_[h * 4 + 0], w1 = cw_[h * 4 + 1];
        const float w2 = cw_[h * 4 + 2], w3 = cw_[h * 4 + 3];
        const float bb = cb_[h];
        for (int r = 3 + (tid >> 7); r < 128; r += 2) {
            float a = bb;
            a = fmaf(w0, st[(r - 3) * 132 + c], a);
            a = fmaf(w1, st[(r - 2) * 132 + c], a);
            a = fmaf(w2, st[(r - 1) * 132 + c], a);
            a = fmaf(w3, st[(r - 0) * 132 + c], a);
            __nv_bfloat16 hi, lo;
            split_bf(a, hi, lo);
            size_t ox = (size_t)(bm + r) * H_ + h;
            oxh[ox] = hi;
            oxl[ox] = lo;
        }
        return;
    }

    const bool dg = (EPI == 1);
    const int cbase = bn + wn * 64 + (lid & 3) * 2;
#pragma unroll
    for (int mt = 0; mt < 2; mt++) {
        const int row = r0 + mt * 16;
#pragma unroll
        for (int nt = 0; nt < 8; nt++) {
            const int col = cbase + nt * 8;
            float2 v0 = make_float2(acc[mt][nt][0], acc[mt][nt][1]);
            float2 v1 = make_float2(acc[mt][nt][2], acc[mt][nt][3]);
            if (dg) {
                v0.x = 0.5f * v0.x * (1.f + erff(v0.x * 0.70710678118654752f));
                v0.y = 0.5f * v0.y * (1.f + erff(v0.y * 0.70710678118654752f));
                v1.x = 0.5f * v1.x * (1.f + erff(v1.x * 0.70710678118654752f));
                v1.y = 0.5f * v1.y * (1.f + erff(v1.y * 0.70710678118654752f));
            }
            *(float2*)(C + (size_t)row * ldc + col) = v0;
            *(float2*)(C + (size_t)(row + 8) * ldc + col) = v1;
        }
    }
}

// -------- conv boundary rows --------
__global__ void conv_boundary(const float* __restrict__ cw, const float* __restrict__ cb)
{
    int idx = blockIdx.x * blockDim.x + threadIdx.x;
    if (idx >= (M_ / 128) * 3 * H_) return;
    int h = idx % H_;
    int q = idx / H_;
    int r = q % 3;
    int tile = q / 3;
    int m = tile * 128 + r;
    int n = m / T_, t = m % T_;
    float a = cb[h];
#pragma unroll
    for (int k = 0; k < 4; k++) {
        int tt = t - 3 + k;
        if (tt >= 0)
            a = fmaf(cw[h * 4 + k], g_gx[(size_t)(n * T_ + tt) * G2H + H_ + h], a);
    }
    __nv_bfloat16 hi, lo;
    split_bf(a, hi, lo);
    g_xbh[(size_t)m * H_ + h] = hi;
    g_xbl[(size_t)m * H_ + h] = lo;
}

// -------- unified pack kernel: 4 sections, ILP 2 --------
// sec 0: x (M*D), sec 1: W_in (G2H*D), sec 2: W_g permuted (G2H*H), sec 3: W_out (D*H)
#define PK_X   ((long long)M_*D_/8)
#define PK_WI  ((long long)G2H*D_/8)
#define PK_WG  ((long long)G2H*H_/8)
#define PK_WO  ((long long)D_*H_/8)
__global__ void pack_all(const float* __restrict__ x, const float* __restrict__ wi,
                         const float* __restrict__ wg, const float* __restrict__ wo)
{
    long long i = (long long)blockIdx.x * blockDim.x + threadIdx.x;   // unit = 8 floats
    const float* s; __nv_bfloat16 *hi, *lo; long long off8;
    bool permute = false;
    if (i < PK_X) { s = x; hi = g_xh; lo = g_xl; off8 = i; }
    else if ((i -= PK_X) < PK_WI) { s = wi; hi = g_wih; lo = g_wil; off8 = i; }
    else if ((i -= PK_WI) < PK_WG) { s = wg; hi = g_wgh; lo = g_wgl; off8 = i; permute = true; }
    else if ((i -= PK_WG) < PK_WO) { s = wo; hi = g_woh; lo = g_wol; off8 = i; }
    else return;

    long long dste = off8 * 8;
    long long srce;
    if (permute) {
        // dst row r (width H_) = src row (r&1)*H_ + (r>>1)
        long long r = dste / H_;
        long long cc = dste - r * H_;
        srce = ((r & 1) * H_ + (r >> 1)) * (long long)H_ + cc;
    } else srce = dste;

#pragma unroll
    for (int half = 0; half < 2; half++) {
        float4 f = *(const float4*)(s + srce + half * 4);
        __nv_bfloat16 h[4], l[4];
        split_bf(f.x, h[0], l[0]); split_bf(f.y, h[1], l[1]);
        split_bf(f.z, h[2], l[2]); split_bf(f.w, h[3], l[3]);
        *(uint2*)(hi + dste + half * 4) = *(uint2*)h;
        *(uint2*)(lo + dste + half * 4) = *(uint2*)l;
    }
}

// -------- remaining scan phases --------
__global__ void scan_p2()
{
    int h = blockIdx.x * 128 + threadIdx.x;
    int n = blockIdx.y;
    float carry = 0.f;
    for (int c = 0; c < NC; c++) {
        int i = (n * NC + c) * H_ + h;
        float a = g_cA[i], b = g_cB[i];
        g_cB[i] = carry;
        carry = fmaf(a, carry, b);
    }
}

__global__ void scan_p3()
{
    int h = blockIdx.x * 128 + threadIdx.x;
    int c = blockIdx.y, n = blockIdx.z;
    size_t base  = ((size_t)(n * T_ + c * TC)) * H_ + h;
    size_t gbase = ((size_t)(n * T_ + c * TC)) * G2H + h;
    float hp = g_cB[(n * NC + c) * H_ + h];
#pragma unroll 4
    for (int t = 0; t < TC; t++) {
        float a = g_alpha[base + (size_t)t * H_];
        float x = g_xs   [base + (size_t)t * H_];
        hp = fmaf(a, hp, x);
        float g = g_gx[gbase + (size_t)t * G2H];
        float v = hp * g;
        __nv_bfloat16 hi, lo;
        split_bf(v, hi, lo);
        g_yh[base + (size_t)t * H_] = hi;
        g_yl[base + (size_t)t * H_] = lo;
    }
}

// -------- launch --------
extern "C" void kernel_launch(void* const* d_in, const int* in_sizes, int n_in,
                              void* d_out, int out_size)
{
    const float* x      = (const float*)d_in[0];
    const float* W_in   = (const float*)d_in[1];
    const float* conv_w = (const float*)d_in[2];
    const float* conv_b = (const float*)d_in[3];
    const float* W_g    = (const float*)d_in[4];
    const float* b_g    = (const float*)d_in[5];
    const float* fbase  = (const float*)d_in[6];
    const float* W_out  = (const float*)d_in[7];
    float* out = (float*)d_out;

    float *gx, *alp, *xs;
    __nv_bfloat16 *xh, *xl, *xbh, *xbl, *yh, *yl, *wih, *wil, *wgh, *wgl, *woh, *wol;
    cudaGetSymbolAddress((void**)&gx,  g_gx);
    cudaGetSymbolAddress((void**)&alp, g_alpha);
    cudaGetSymbolAddress((void**)&xs,  g_xs);
    cudaGetSymbolAddress((void**)&xh,  g_xh);
    cudaGetSymbolAddress((void**)&xl,  g_xl);
    cudaGetSymbolAddress((void**)&xbh, g_xbh);
    cudaGetSymbolAddress((void**)&xbl, g_xbl);
    cudaGetSymbolAddress((void**)&yh,  g_yh);
    cudaGetSymbolAddress((void**)&yl,  g_yl);
    cudaGetSymbolAddress((void**)&wih, g_wih);
    cudaGetSymbolAddress((void**)&wil, g_wil);
    cudaGetSymbolAddress((void**)&wgh, g_wgh);
    cudaGetSymbolAddress((void**)&wgl, g_wgl);
    cudaGetSymbolAddress((void**)&woh, g_woh);
    cudaGetSymbolAddress((void**)&wol, g_wol);

    cudaFuncSetAttribute(gemm_mma<0>, cudaFuncAttributeMaxDynamicSharedMemorySize, GEMM_SMEM);
    cudaFuncSetAttribute(gemm_mma<1>, cudaFuncAttributeMaxDynamicSharedMemorySize, GEMM_SMEM);
    cudaFuncSetAttribute(gemm_mma<2>, cudaFuncAttributeMaxDynamicSharedMemorySize, GEMM_SMEM);

    // 0) pack x + weights (single kernel)
    {
        long long total = PK_X + PK_WI + PK_WG + PK_WO;
        pack_all<<<(int)((total + 255) / 256), 256>>>(x, W_in, W_g, W_out);
    }
    // 1) gx = x @ W_in^T; gate: gelu; B-half: fused conv -> xb planes
    gemm_mma<1><<<dim3(G2H/128, M_/128), 256, GEMM_SMEM>>>(
        xh, xl, wih, wil, gx, nullptr, nullptr, nullptr, nullptr, nullptr, nullptr,
        conv_w, conv_b, xbh, xbl, D_, G2H);
    // 1b) conv boundary rows
    conv_boundary<<<((M_/128)*3*H_ + 255)/256, 256>>>(conv_w, conv_b);
    // 2) fused ew GEMM -> alpha, xs, chunk-scan reduction
    gemm_mma<2><<<dim3(G2H/128, M_/128), 256, GEMM_SMEM>>>(
        xbh, xbl, wgh, wgl, nullptr, xbh, xbl, b_g, fbase, alp, xs,
        nullptr, nullptr, nullptr, nullptr, H_, 0);
    // 3) scan: carry propagation + replay
    scan_p2<<<dim3(H_/128, N_), 128>>>();
    scan_p3<<<dim3(H_/128, NC, N_), 128>>>();
    // 4) out = (gelu(gate)*h) @ W_out^T
    gemm_mma<0><<<dim3(D_/128, M_/128), 256, GEMM_SMEM>>>(
        yh, yl, woh, wol, out, nullptr, nullptr, nullptr, nullptr, nullptr, nullptr,
        nullptr, nullptr, nullptr, nullptr, H_, D_);
}

// round 15
// speedup vs baseline: 1.5646x; 1.0119x over previous
#include <cuda_runtime.h>
#include <cuda_bf16.h>
#include <math.h>
#include <stdint.h>

#define N_  4
#define T_  4096
#define D_  1024
#define H_  1536
#define M_  (N_*T_)       // 16384 rows
#define G2H (2*H_)        // 3072
#define TC  128           // scan chunk length == GEMM M-tile
#define NC  (T_/TC)       // 32 chunks

// -------- scratch (device globals; no allocation allowed) --------
__device__ __align__(256) float g_gx  [(size_t)M_*G2H];   // gate half = gelu(gate); B-half: boundary rows only
__device__ __align__(256) float g_alpha[(size_t)M_*H_];
__device__ __align__(256) float g_xs  [(size_t)M_*H_];
__device__ __align__(256) float g_cA  [N_*NC*H_];
__device__ __align__(256) float g_cB  [N_*NC*H_];
// activation bf16 hi/lo planes
__device__ __align__(256) __nv_bfloat16 g_xh [(size_t)M_*D_];
__device__ __align__(256) __nv_bfloat16 g_xl [(size_t)M_*D_];
__device__ __align__(256) __nv_bfloat16 g_xbh[(size_t)M_*H_];
__device__ __align__(256) __nv_bfloat16 g_xbl[(size_t)M_*H_];
__device__ __align__(256) __nv_bfloat16 g_yh [(size_t)M_*H_];
__device__ __align__(256) __nv_bfloat16 g_yl [(size_t)M_*H_];
// weight bf16 hi/lo planes
__device__ __align__(256) __nv_bfloat16 g_wih[(size_t)G2H*D_];
__device__ __align__(256) __nv_bfloat16 g_wil[(size_t)G2H*D_];
__device__ __align__(256) __nv_bfloat16 g_wgh[(size_t)G2H*H_];  // rows permuted for EPI2
__device__ __align__(256) __nv_bfloat16 g_wgl[(size_t)G2H*H_];
__device__ __align__(256) __nv_bfloat16 g_woh[(size_t)D_*H_];
__device__ __align__(256) __nv_bfloat16 g_wol[(size_t)D_*H_];

// ======================= helpers =======================
__device__ __forceinline__ uint32_t smem_u32(const void* p) {
    uint32_t a;
    asm("{ .reg .u64 t; cvta.to.shared.u64 t, %1; cvt.u32.u64 %0, t; }" : "=r"(a) : "l"(p));
    return a;
}
__device__ __forceinline__ void ldmx4(uint32_t* r, uint32_t a) {
    asm volatile("ldmatrix.sync.aligned.m8n8.x4.shared.b16 {%0,%1,%2,%3}, [%4];"
        : "=r"(r[0]), "=r"(r[1]), "=r"(r[2]), "=r"(r[3]) : "r"(a));
}
__device__ __forceinline__ void mma16816(float* d, const uint32_t* a, const uint32_t* b) {
    asm volatile("mma.sync.aligned.m16n8k16.row.col.f32.bf16.bf16.f32 "
        "{%0,%1,%2,%3}, {%4,%5,%6,%7}, {%8,%9}, {%0,%1,%2,%3};"
        : "+f"(d[0]), "+f"(d[1]), "+f"(d[2]), "+f"(d[3])
        : "r"(a[0]), "r"(a[1]), "r"(a[2]), "r"(a[3]), "r"(b[0]), "r"(b[1]));
}
__device__ __forceinline__ void cpa16(uint32_t dst, const void* src) {
    asm volatile("cp.async.cg.shared.global [%0], [%1], 16;" :: "r"(dst), "l"(src));
}
#define CP_COMMIT()     asm volatile("cp.async.commit_group;" ::: "memory")
#define CP_WAIT(NN)     asm volatile("cp.async.wait_group %0;" :: "n"(NN) : "memory")
__device__ __forceinline__ float sigmoidf_(float v) { return 1.f / (1.f + expf(-v)); }
__device__ __forceinline__ void split_bf(float v, __nv_bfloat16& h, __nv_bfloat16& l) {
    h = __float2bfloat16(v);
    l = __float2bfloat16(v - __bfloat162float(h));
}

// ================== bf16x3 mma GEMM (all cp.async, 3-stage, swizzled) ==================
#define PL_A_H 0
#define PL_A_L 8192
#define PL_B_H 16384
#define PL_B_L 24576
#define STAGE  32768
#define GEMM_SMEM (3*STAGE)   // 98304

__device__ __forceinline__ int swz16(int row) {
    return ((row & 3) ^ ((row >> 2) & 3));
}

// persistent per-thread load pointers, advanced by +32 elements per chunk
struct LoadPtrs {
    const __nv_bfloat16 *a0, *a1, *b0, *b1;
    const __nv_bfloat16 *la0, *la1, *lb0, *lb1;
    uint32_t so0, so1;
};

__device__ __forceinline__ LoadPtrs make_ptrs(int tid, int K,
    const __nv_bfloat16* Ah, const __nv_bfloat16* Al,
    const __nv_bfloat16* Bh, const __nv_bfloat16* Bl)
{
    LoadPtrs p;
    const int col = tid & 3;
    const int r0 = tid >> 2, r1 = (tid + 256) >> 2;
    const size_t g0 = (size_t)r0 * K + col * 8;
    const size_t g1 = (size_t)r1 * K + col * 8;
    p.a0 = Ah + g0;  p.a1 = Ah + g1;
    p.la0 = Al + g0; p.la1 = Al + g1;
    p.b0 = Bh + g0;  p.b1 = Bh + g1;
    p.lb0 = Bl + g0; p.lb1 = Bl + g1;
    p.so0 = (uint32_t)(r0 * 64 + ((col ^ swz16(r0)) << 4));
    p.so1 = (uint32_t)(r1 * 64 + ((col ^ swz16(r1)) << 4));
    return p;
}

__device__ __forceinline__ void issue_chunk(uint32_t stg, LoadPtrs& p) {
    cpa16(stg + PL_A_H + p.so0, p.a0);
    cpa16(stg + PL_A_L + p.so0, p.la0);
    cpa16(stg + PL_B_H + p.so0, p.b0);
    cpa16(stg + PL_B_L + p.so0, p.lb0);
    cpa16(stg + PL_A_H + p.so1, p.a1);
    cpa16(stg + PL_A_L + p.so1, p.la1);
    cpa16(stg + PL_B_H + p.so1, p.b1);
    cpa16(stg + PL_B_L + p.so1, p.lb1);
    p.a0 += 32; p.a1 += 32; p.la0 += 32; p.la1 += 32;
    p.b0 += 32; p.b1 += 32; p.lb0 += 32; p.lb1 += 32;
}

// split-B scheduling: A + B-half0 loads -> MMA nt0..3 -> B-half1 loads (latency
// hidden under prior MMAs) -> MMA nt4..7. Halves live fragment registers too.
__device__ __forceinline__ void compute_kt(float acc[2][8][4],
    uint32_t aB, uint32_t bB, uint32_t ax, uint32_t bx, int kt)
{
    const uint32_t kc = (uint32_t)(kt << 5);
    uint32_t ah[2][4], al[2][4];
#pragma unroll
    for (int mt = 0; mt < 2; mt++) {
        ldmx4(ah[mt], aB + mt * 1024 + (kc ^ ax));
        ldmx4(al[mt], aB + PL_A_L + mt * 1024 + (kc ^ ax));
    }
    {
        uint32_t bh[2][4], bl[2][4];
#pragma unroll
        for (int n2 = 0; n2 < 2; n2++) {
            ldmx4(bh[n2], bB + n2 * 1024 + (kc ^ bx));
            ldmx4(bl[n2], bB + (PL_B_L - PL_B_H) + n2 * 1024 + (kc ^ bx));
        }
#pragma unroll
        for (int mt = 0; mt < 2; mt++)
#pragma unroll
            for (int nt = 0; nt < 4; nt++) {
                uint32_t* bph = &bh[nt >> 1][(nt & 1) * 2];
                uint32_t* bpl = &bl[nt >> 1][(nt & 1) * 2];
                mma16816(acc[mt][nt], ah[mt], bph);
                mma16816(acc[mt][nt], ah[mt], bpl);
                mma16816(acc[mt][nt], al[mt], bph);
            }
    }
    {
        uint32_t bh[2][4], bl[2][4];
#pragma unroll
        for (int n2 = 0; n2 < 2; n2++) {
            ldmx4(bh[n2], bB + (n2 + 2) * 1024 + (kc ^ bx));
            ldmx4(bl[n2], bB + (PL_B_L - PL_B_H) + (n2 + 2) * 1024 + (kc ^ bx));
        }
#pragma unroll
        for (int mt = 0; mt < 2; mt++)
#pragma unroll
            for (int nt = 4; nt < 8; nt++) {
                uint32_t* bph = &bh[(nt - 4) >> 1][(nt & 1) * 2];
                uint32_t* bpl = &bl[(nt - 4) >> 1][(nt & 1) * 2];
                mma16816(acc[mt][nt], ah[mt], bph);
                mma16816(acc[mt][nt], ah[mt], bpl);
                mma16816(acc[mt][nt], al[mt], bph);
            }
    }
}

// EPI: 0 = plain, 1 = GEMM1 (gate: gelu; B-half: fused conv), 2 = fused ew + chunk-scan
template<int EPI>
__global__ __launch_bounds__(256, 2)
void gemm_mma(const __nv_bfloat16* __restrict__ Ah, const __nv_bfloat16* __restrict__ Al,
              const __nv_bfloat16* __restrict__ Bh, const __nv_bfloat16* __restrict__ Bl,
              float* __restrict__ C,
              const __nv_bfloat16* __restrict__ xbh, const __nv_bfloat16* __restrict__ xbl,
              const float* __restrict__ bg, const float* __restrict__ fbase,
              float* __restrict__ alpha_o, float* __restrict__ xs_o,
              const float* __restrict__ cw_, const float* __restrict__ cb_,
              __nv_bfloat16* __restrict__ oxh, __nv_bfloat16* __restrict__ oxl,
              int K, int ldc)
{
    extern __shared__ char sm[];
    const int tid = threadIdx.x;
    const int lid = tid & 31, wid = tid >> 5;
    const int wm = wid >> 1, wn = wid & 1;
    const int bm = blockIdx.y * 128;
    const int bn = blockIdx.x * 128;

    LoadPtrs lp = make_ptrs(tid, K,
        Ah + (size_t)bm * K, Al + (size_t)bm * K,
        Bh + (size_t)bn * K, Bl + (size_t)bn * K);

    float acc[2][8][4];
#pragma unroll
    for (int i = 0; i < 2; i++)
#pragma unroll
        for (int j = 0; j < 8; j++)
#pragma unroll
            for (int q = 0; q < 4; q++) acc[i][j][q] = 0.f;

    const uint32_t sb = smem_u32(sm);
    const int arow = wm * 32 + (lid & 15);
    const int brow = wn * 64 + (lid & 7) + ((lid >> 4) & 1) * 8;
    const uint32_t ax = (uint32_t)((((lid >> 4) & 1) << 4) ^ (swz16(arow) << 4));
    const uint32_t bx = (uint32_t)((((lid >> 3) & 1) << 4) ^ (swz16(brow) << 4));
    const uint32_t aB0 = sb + (uint32_t)(arow * 64);
    const uint32_t bB0 = sb + PL_B_H + (uint32_t)(brow * 64);

    const int KT = K >> 5;
    issue_chunk(sb, lp);
    CP_COMMIT();
    issue_chunk(sb + STAGE, lp);
    CP_COMMIT();

    int stg = 0;
    for (int c = 0; c < KT; c++) {
        if (c + 1 < KT) { CP_WAIT(1); } else { CP_WAIT(0); }
        __syncthreads();
        const uint32_t so = (uint32_t)(stg * STAGE);
        compute_kt(acc, aB0 + so, bB0 + so, ax, bx, 0);
        if (c + 2 < KT) {
            int ns = stg + 2; if (ns >= 3) ns -= 3;
            issue_chunk(sb + ns * STAGE, lp);
            CP_COMMIT();
        }
        compute_kt(acc, aB0 + so, bB0 + so, ax, bx, 1);
        if (++stg == 3) stg = 0;
    }

    const int r0 = bm + wm * 32 + (lid >> 2);

    if (EPI == 2) {
        const int hloc = wn * 32 + (lid & 3);
        const int h0 = (bn >> 1);
        float sp8[8], bgf[8], bgi[8];
#pragma unroll
        for (int nt = 0; nt < 8; nt++) {
            int h = h0 + hloc + nt * 4;
            float fb = fbase[h];
            sp8[nt] = fmaxf(fb, 0.f) + log1pf(expf(-fabsf(fb)));
            bgf[nt] = bg[h]; bgi[nt] = bg[H_ + h];
        }
        const int rloc0 = wm * 32 + (lid >> 2);
#pragma unroll
        for (int mt = 0; mt < 2; mt++)
#pragma unroll
            for (int nt = 0; nt < 8; nt++)
#pragma unroll
                for (int half = 0; half < 2; half++) {
                    int rl = rloc0 + mt * 16 + half * 8;
                    float forget = acc[mt][nt][half * 2 + 0] + bgf[nt];
                    float inp    = acc[mt][nt][half * 2 + 1] + bgi[nt];
                    float a = expf(-8.f * sp8[nt] * sigmoidf_(forget));
                    float beta = sqrtf(1.f - a * a + 1e-6f);
                    size_t ix = (size_t)(bm + rl) * H_ + h0 + hloc + nt * 4;
                    float xb = __bfloat162float(xbh[ix]) + __bfloat162float(xbl[ix]);
                    acc[mt][nt][half * 2 + 0] = a;
                    acc[mt][nt][half * 2 + 1] = beta * sigmoidf_(inp) * xb;
                }
        float* st_a = (float*)sm;
        float* st_x = (float*)sm + 128 * 68;
        __syncthreads();
#pragma unroll
        for (int mt = 0; mt < 2; mt++)
#pragma unroll
            for (int nt = 0; nt < 8; nt++)
#pragma unroll
                for (int half = 0; half < 2; half++) {
                    int rl = rloc0 + mt * 16 + half * 8;
                    st_a[rl * 68 + hloc + nt * 4] = acc[mt][nt][half * 2 + 0];
                    st_x[rl * 68 + hloc + nt * 4] = acc[mt][nt][half * 2 + 1];
                }
        __syncthreads();
#pragma unroll
        for (int it = 0; it < 8; it++) {
            int idx = it * 256 + tid;
            int row = idx >> 4, cc = (idx & 15) * 4;
            float4 va = *(float4*)&st_a[row * 68 + cc];
            float4 vx = *(float4*)&st_x[row * 68 + cc];
            *(float4*)&alpha_o[(size_t)(bm + row) * H_ + h0 + cc] = va;
            *(float4*)&xs_o   [(size_t)(bm + row) * H_ + h0 + cc] = vx;
        }
        if (tid < 64) {
            float A = 1.f, Bv = 0.f;
#pragma unroll 4
            for (int t = 0; t < 128; t++) {
                float a = st_a[t * 68 + tid];
                float xv = st_x[t * 68 + tid];
                Bv = fmaf(a, Bv, xv);
                A *= a;
            }
            int n = bm >> 12;
            int cch = (bm & (T_ - 1)) >> 7;
            int ci = (n * NC + cch) * H_ + h0 + tid;
            g_cA[ci] = A;
            g_cB[ci] = Bv;
        }
        return;
    }

    if (EPI == 1 && bn >= H_) {
        float* st = (float*)sm;
        const int rl0 = wm * 32 + (lid >> 2);
        const int cl0 = wn * 64 + (lid & 3) * 2;
        __syncthreads();
#pragma unroll
        for (int mt = 0; mt < 2; mt++)
#pragma unroll
            for (int nt = 0; nt < 8; nt++)
#pragma unroll
                for (int half = 0; half < 2; half++) {
                    int rl = rl0 + mt * 16 + half * 8;
                    int cl = cl0 + nt * 8;
                    st[rl * 132 + cl]     = acc[mt][nt][half * 2 + 0];
                    st[rl * 132 + cl + 1] = acc[mt][nt][half * 2 + 1];
                }
        __syncthreads();
        const int hb = bn - H_;
        {
            int i = tid;
#pragma unroll
            for (int it = 0; it < 3; it++, i += 256) {
                int ri = i >> 7;
                int cc = i & 127;
                int row = (ri < 3) ? ri : (122 + ri);
                C[(size_t)(bm + row) * ldc + H_ + hb + cc] = st[row * 132 + cc];
            }
        }
        const int c = tid & 127;
        const int h = hb + c;
        const float w0 = cw_[h * 4 + 0], w1 = cw_[h * 4 + 1];
        const float w2 = cw_[h * 4 + 2], w3 = cw_[h * 4 + 3];
        const float bb = cb_[h];
        for (int r = 3 + (tid >> 7); r < 128; r += 2) {
            float a = bb;
            a = fmaf(w0, st[(r - 3) * 132 + c], a);
            a = fmaf(w1, st[(r - 2) * 132 + c], a);
            a = fmaf(w2, st[(r - 1) * 132 + c], a);
            a = fmaf(w3, st[(r - 0) * 132 + c], a);
            __nv_bfloat16 hi, lo;
            split_bf(a, hi, lo);
            size_t ox = (size_t)(bm + r) * H_ + h;
            oxh[ox] = hi;
            oxl[ox] = lo;
        }
        return;
    }

    const bool dg = (EPI == 1);
    const int cbase = bn + wn * 64 + (lid & 3) * 2;
#pragma unroll
    for (int mt = 0; mt < 2; mt++) {
        const int row = r0 + mt * 16;
#pragma unroll
        for (int nt = 0; nt < 8; nt++) {
            const int col = cbase + nt * 8;
            float2 v0 = make_float2(acc[mt][nt][0], acc[mt][nt][1]);
            float2 v1 = make_float2(acc[mt][nt][2], acc[mt][nt][3]);
            if (dg) {
                v0.x = 0.5f * v0.x * (1.f + erff(v0.x * 0.70710678118654752f));
                v0.y = 0.5f * v0.y * (1.f + erff(v0.y * 0.70710678118654752f));
                v1.x = 0.5f * v1.x * (1.f + erff(v1.x * 0.70710678118654752f));
                v1.y = 0.5f * v1.y * (1.f + erff(v1.y * 0.70710678118654752f));
            }
            *(float2*)(C + (size_t)row * ldc + col) = v0;
            *(float2*)(C + (size_t)(row + 8) * ldc + col) = v1;
        }
    }
}

// -------- conv boundary rows --------
__global__ void conv_boundary(const float* __restrict__ cw, const float* __restrict__ cb)
{
    int idx = blockIdx.x * blockDim.x + threadIdx.x;
    if (idx >= (M_ / 128) * 3 * H_) return;
    int h = idx % H_;
    int q = idx / H_;
    int r = q % 3;
    int tile = q / 3;
    int m = tile * 128 + r;
    int n = m / T_, t = m % T_;
    float a = cb[h];
#pragma unroll
    for (int k = 0; k < 4; k++) {
        int tt = t - 3 + k;
        if (tt >= 0)
            a = fmaf(cw[h * 4 + k], g_gx[(size_t)(n * T_ + tt) * G2H + H_ + h], a);
    }
    __nv_bfloat16 hi, lo;
    split_bf(a, hi, lo);
    g_xbh[(size_t)m * H_ + h] = hi;
    g_xbl[(size_t)m * H_ + h] = lo;
}

// -------- unified pack kernel --------
#define PK_X   ((long long)M_*D_/8)
#define PK_WI  ((long long)G2H*D_/8)
#define PK_WG  ((long long)G2H*H_/8)
#define PK_WO  ((long long)D_*H_/8)
__global__ void pack_all(const float* __restrict__ x, const float* __restrict__ wi,
                         const float* __restrict__ wg, const float* __restrict__ wo)
{
    long long i = (long long)blockIdx.x * blockDim.x + threadIdx.x;
    const float* s; __nv_bfloat16 *hi, *lo; long long off8;
    bool permute = false;
    if (i < PK_X) { s = x; hi = g_xh; lo = g_xl; off8 = i; }
    else if ((i -= PK_X) < PK_WI) { s = wi; hi = g_wih; lo = g_wil; off8 = i; }
    else if ((i -= PK_WI) < PK_WG) { s = wg; hi = g_wgh; lo = g_wgl; off8 = i; permute = true; }
    else if ((i -= PK_WG) < PK_WO) { s = wo; hi = g_woh; lo = g_wol; off8 = i; }
    else return;

    long long dste = off8 * 8;
    long long srce;
    if (permute) {
        long long r = dste / H_;
        long long cc = dste - r * H_;
        srce = ((r & 1) * H_ + (r >> 1)) * (long long)H_ + cc;
    } else srce = dste;

#pragma unroll
    for (int half = 0; half < 2; half++) {
        float4 f = *(const float4*)(s + srce + half * 4);
        __nv_bfloat16 h[4], l[4];
        split_bf(f.x, h[0], l[0]); split_bf(f.y, h[1], l[1]);
        split_bf(f.z, h[2], l[2]); split_bf(f.w, h[3], l[3]);
        *(uint2*)(hi + dste + half * 4) = *(uint2*)h;
        *(uint2*)(lo + dste + half * 4) = *(uint2*)l;
    }
}

// -------- scan replay with inline carry (p2 fused) --------
__global__ void scan_p3()
{
    int h = blockIdx.x * 128 + threadIdx.x;
    int c = blockIdx.y, n = blockIdx.z;
    // carry over chunks 0..c-1 (same FMA order as the old scan_p2)
    float carry = 0.f;
    for (int cc = 0; cc < c; cc++) {
        int i = (n * NC + cc) * H_ + h;
        carry = fmaf(g_cA[i], carry, g_cB[i]);
    }
    size_t base  = ((size_t)(n * T_ + c * TC)) * H_ + h;
    size_t gbase = ((size_t)(n * T_ + c * TC)) * G2H + h;
    float hp = carry;
#pragma unroll 4
    for (int t = 0; t < TC; t++) {
        float a = g_alpha[base + (size_t)t * H_];
        float x = g_xs   [base + (size_t)t * H_];
        hp = fmaf(a, hp, x);
        float g = g_gx[gbase + (size_t)t * G2H];
        float v = hp * g;
        __nv_bfloat16 hi, lo;
        split_bf(v, hi, lo);
        g_yh[base + (size_t)t * H_] = hi;
        g_yl[base + (size_t)t * H_] = lo;
    }
}

// -------- launch --------
extern "C" void kernel_launch(void* const* d_in, const int* in_sizes, int n_in,
                              void* d_out, int out_size)
{
    const float* x      = (const float*)d_in[0];
    const float* W_in   = (const float*)d_in[1];
    const float* conv_w = (const float*)d_in[2];
    const float* conv_b = (const float*)d_in[3];
    const float* W_g    = (const float*)d_in[4];
    const float* b_g    = (const float*)d_in[5];
    const float* fbase  = (const float*)d_in[6];
    const float* W_out  = (const float*)d_in[7];
    float* out = (float*)d_out;

    float *gx, *alp, *xs;
    __nv_bfloat16 *xh, *xl, *xbh, *xbl, *yh, *yl, *wih, *wil, *wgh, *wgl, *woh, *wol;
    cudaGetSymbolAddress((void**)&gx,  g_gx);
    cudaGetSymbolAddress((void**)&alp, g_alpha);
    cudaGetSymbolAddress((void**)&xs,  g_xs);
    cudaGetSymbolAddress((void**)&xh,  g_xh);
    cudaGetSymbolAddress((void**)&xl,  g_xl);
    cudaGetSymbolAddress((void**)&xbh, g_xbh);
    cudaGetSymbolAddress((void**)&xbl, g_xbl);
    cudaGetSymbolAddress((void**)&yh,  g_yh);
    cudaGetSymbolAddress((void**)&yl,  g_yl);
    cudaGetSymbolAddress((void**)&wih, g_wih);
    cudaGetSymbolAddress((void**)&wil, g_wil);
    cudaGetSymbolAddress((void**)&wgh, g_wgh);
    cudaGetSymbolAddress((void**)&wgl, g_wgl);
    cudaGetSymbolAddress((void**)&woh, g_woh);
    cudaGetSymbolAddress((void**)&wol, g_wol);

    cudaFuncSetAttribute(gemm_mma<0>, cudaFuncAttributeMaxDynamicSharedMemorySize, GEMM_SMEM);
    cudaFuncSetAttribute(gemm_mma<1>, cudaFuncAttributeMaxDynamicSharedMemorySize, GEMM_SMEM);
    cudaFuncSetAttribute(gemm_mma<2>, cudaFuncAttributeMaxDynamicSharedMemorySize, GEMM_SMEM);

    // 0) pack x + weights (single kernel)
    {
        long long total = PK_X + PK_WI + PK_WG + PK_WO;
        pack_all<<<(int)((total + 255) / 256), 256>>>(x, W_in, W_g, W_out);
    }
    // 1) gx = x @ W_in^T; gate: gelu; B-half: fused conv -> xb planes
    gemm_mma<1><<<dim3(G2H/128, M_/128), 256, GEMM_SMEM>>>(
        xh, xl, wih, wil, gx, nullptr, nullptr, nullptr, nullptr, nullptr, nullptr,
        conv_w, conv_b, xbh, xbl, D_, G2H);
    // 1b) conv boundary rows
    conv_boundary<<<((M_/128)*3*H_ + 255)/256, 256>>>(conv_w, conv_b);
    // 2) fused ew GEMM -> alpha, xs, chunk-scan reduction
    gemm_mma<2><<<dim3(G2H/128, M_/128), 256, GEMM_SMEM>>>(
        xbh, xbl, wgh, wgl, nullptr, xbh, xbl, b_g, fbase, alp, xs,
        nullptr, nullptr, nullptr, nullptr, H_, 0);
    // 3) scan replay (carry fused in)
    scan_p3<<<dim3(H_/128, NC, N_), 128>>>();
    // 4) out = (gelu(gate)*h) @ W_out^T
    gemm_mma<0><<<dim3(D_/128, M_/128), 256, GEMM_SMEM>>>(
        yh, yl, woh, wol, out, nullptr, nullptr, nullptr, nullptr, nullptr, nullptr,
        nullptr, nullptr, nullptr, nullptr, H_, D_);
}

// round 16
// speedup vs baseline: 1.5950x; 1.0194x over previous
#include <cuda_runtime.h>
#include <cuda_bf16.h>
#include <math.h>
#include <stdint.h>

#define N_  4
#define T_  4096
#define D_  1024
#define H_  1536
#define M_  (N_*T_)       // 16384 rows
#define G2H (2*H_)        // 3072
#define TC  128           // scan chunk length == GEMM M-tile
#define NC  (T_/TC)       // 32 chunks

// -------- scratch (device globals; no allocation allowed) --------
__device__ __align__(256) float g_gx  [(size_t)M_*G2H];   // gate half = gelu(gate); B-half: boundary rows only
__device__ __align__(256) float g_alpha[(size_t)M_*H_];
__device__ __align__(256) float g_xs  [(size_t)M_*H_];
__device__ __align__(256) float g_cA  [N_*NC*H_];
__device__ __align__(256) float g_cB  [N_*NC*H_];
// activation bf16 hi/lo planes
__device__ __align__(256) __nv_bfloat16 g_xh [(size_t)M_*D_];
__device__ __align__(256) __nv_bfloat16 g_xl [(size_t)M_*D_];
__device__ __align__(256) __nv_bfloat16 g_xbh[(size_t)M_*H_];
__device__ __align__(256) __nv_bfloat16 g_xbl[(size_t)M_*H_];
__device__ __align__(256) __nv_bfloat16 g_yh [(size_t)M_*H_];
__device__ __align__(256) __nv_bfloat16 g_yl [(size_t)M_*H_];
// weight bf16 hi/lo planes
__device__ __align__(256) __nv_bfloat16 g_wih[(size_t)G2H*D_];
__device__ __align__(256) __nv_bfloat16 g_wil[(size_t)G2H*D_];
__device__ __align__(256) __nv_bfloat16 g_wgh[(size_t)G2H*H_];  // rows permuted for EPI2
__device__ __align__(256) __nv_bfloat16 g_wgl[(size_t)G2H*H_];
__device__ __align__(256) __nv_bfloat16 g_woh[(size_t)D_*H_];
__device__ __align__(256) __nv_bfloat16 g_wol[(size_t)D_*H_];

// ======================= helpers =======================
__device__ __forceinline__ uint32_t smem_u32(const void* p) {
    uint32_t a;
    asm("{ .reg .u64 t; cvta.to.shared.u64 t, %1; cvt.u32.u64 %0, t; }" : "=r"(a) : "l"(p));
    return a;
}
__device__ __forceinline__ void ldmx4(uint32_t* r, uint32_t a) {
    asm volatile("ldmatrix.sync.aligned.m8n8.x4.shared.b16 {%0,%1,%2,%3}, [%4];"
        : "=r"(r[0]), "=r"(r[1]), "=r"(r[2]), "=r"(r[3]) : "r"(a));
}
__device__ __forceinline__ void mma16816(float* d, const uint32_t* a, const uint32_t* b) {
    asm volatile("mma.sync.aligned.m16n8k16.row.col.f32.bf16.bf16.f32 "
        "{%0,%1,%2,%3}, {%4,%5,%6,%7}, {%8,%9}, {%0,%1,%2,%3};"
        : "+f"(d[0]), "+f"(d[1]), "+f"(d[2]), "+f"(d[3])
        : "r"(a[0]), "r"(a[1]), "r"(a[2]), "r"(a[3]), "r"(b[0]), "r"(b[1]));
}
__device__ __forceinline__ void cpa16(uint32_t dst, const void* src) {
    asm volatile("cp.async.cg.shared.global [%0], [%1], 16;" :: "r"(dst), "l"(src));
}
#define CP_COMMIT()     asm volatile("cp.async.commit_group;" ::: "memory")
#define CP_WAIT(NN)     asm volatile("cp.async.wait_group %0;" :: "n"(NN) : "memory")
__device__ __forceinline__ float sigmoidf_(float v) { return 1.f / (1.f + expf(-v)); }
__device__ __forceinline__ void split_bf(float v, __nv_bfloat16& h, __nv_bfloat16& l) {
    h = __float2bfloat16(v);
    l = __float2bfloat16(v - __bfloat162float(h));
}

// ================== bf16x3 mma GEMM (all cp.async, 3-stage, swizzled) ==================
#define PL_A_H 0
#define PL_A_L 8192
#define PL_B_H 16384
#define PL_B_L 24576
#define BLO    (PL_B_L - PL_B_H)
#define STAGE  32768
#define GEMM_SMEM (3*STAGE)   // 98304

__device__ __forceinline__ int swz16(int row) {
    return ((row & 3) ^ ((row >> 2) & 3));
}

// persistent per-thread load pointers (hi planes only; lo = hi + delta)
struct LoadPtrs {
    const __nv_bfloat16 *a0, *a1, *b0, *b1;
    uint32_t so0, so1;
};

__device__ __forceinline__ LoadPtrs make_ptrs(int tid, int K,
    const __nv_bfloat16* Ah, const __nv_bfloat16* Bh)
{
    LoadPtrs p;
    const int col = tid & 3;
    const int r0 = tid >> 2, r1 = (tid + 256) >> 2;
    const size_t g0 = (size_t)r0 * K + col * 8;
    const size_t g1 = (size_t)r1 * K + col * 8;
    p.a0 = Ah + g0;  p.a1 = Ah + g1;
    p.b0 = Bh + g0;  p.b1 = Bh + g1;
    p.so0 = (uint32_t)(r0 * 64 + ((col ^ swz16(r0)) << 4));
    p.so1 = (uint32_t)(r1 * 64 + ((col ^ swz16(r1)) << 4));
    return p;
}

__device__ __forceinline__ void issue_chunk(uint32_t stg, LoadPtrs& p,
                                            ptrdiff_t dA, ptrdiff_t dB) {
    cpa16(stg + PL_A_H + p.so0, p.a0);
    cpa16(stg + PL_A_L + p.so0, p.a0 + dA);
    cpa16(stg + PL_B_H + p.so0, p.b0);
    cpa16(stg + PL_B_L + p.so0, p.b0 + dB);
    cpa16(stg + PL_A_H + p.so1, p.a1);
    cpa16(stg + PL_A_L + p.so1, p.a1 + dA);
    cpa16(stg + PL_B_H + p.so1, p.b1);
    cpa16(stg + PL_B_L + p.so1, p.b1 + dB);
    p.a0 += 32; p.a1 += 32; p.b0 += 32; p.b1 += 32;
}

// one MMA bundle: 4 n-tiles (ntb..ntb+3) x 2 m-tiles x 3 split-MMAs
__device__ __forceinline__ void mma_bundle(float acc[2][8][4],
    const uint32_t ah[2][4], const uint32_t al[2][4],
    const uint32_t bh[2][4], const uint32_t bl[2][4], int ntb)
{
#pragma unroll
    for (int mt = 0; mt < 2; mt++)
#pragma unroll
        for (int j = 0; j < 4; j++) {
            const uint32_t* bph = &bh[j >> 1][(j & 1) * 2];
            const uint32_t* bpl = &bl[j >> 1][(j & 1) * 2];
            mma16816(acc[mt][ntb + j], ah[mt], bph);
            mma16816(acc[mt][ntb + j], ah[mt], bpl);
            mma16816(acc[mt][ntb + j], al[mt], bph);
        }
}

// EPI: 0 = plain, 1 = GEMM1 (gate: gelu; B-half: fused conv), 2 = fused ew + chunk-scan
template<int EPI>
__global__ __launch_bounds__(256, 2)
void gemm_mma(const __nv_bfloat16* __restrict__ Ah, const __nv_bfloat16* __restrict__ Al,
              const __nv_bfloat16* __restrict__ Bh, const __nv_bfloat16* __restrict__ Bl,
              float* __restrict__ C,
              const __nv_bfloat16* __restrict__ xbh, const __nv_bfloat16* __restrict__ xbl,
              const float* __restrict__ bg, const float* __restrict__ fbase,
              float* __restrict__ alpha_o, float* __restrict__ xs_o,
              const float* __restrict__ cw_, const float* __restrict__ cb_,
              __nv_bfloat16* __restrict__ oxh, __nv_bfloat16* __restrict__ oxl,
              int K, int ldc)
{
    extern __shared__ char sm[];
    const int tid = threadIdx.x;
    const int lid = tid & 31, wid = tid >> 5;
    const int wm = wid >> 1, wn = wid & 1;
    const int bm = blockIdx.y * 128;
    const int bn = blockIdx.x * 128;

    const ptrdiff_t dA = Al - Ah;
    const ptrdiff_t dB = Bl - Bh;
    LoadPtrs lp = make_ptrs(tid, K, Ah + (size_t)bm * K, Bh + (size_t)bn * K);

    float acc[2][8][4];
#pragma unroll
    for (int i = 0; i < 2; i++)
#pragma unroll
        for (int j = 0; j < 8; j++)
#pragma unroll
            for (int q = 0; q < 4; q++) acc[i][j][q] = 0.f;

    const uint32_t sb = smem_u32(sm);
    const int arow = wm * 32 + (lid & 15);
    const int brow = wn * 64 + (lid & 7) + ((lid >> 4) & 1) * 8;
    const uint32_t ax = (uint32_t)((((lid >> 4) & 1) << 4) ^ (swz16(arow) << 4));
    const uint32_t bx = (uint32_t)((((lid >> 3) & 1) << 4) ^ (swz16(brow) << 4));
    const uint32_t aB0 = sb + (uint32_t)(arow * 64);
    const uint32_t bB0 = sb + PL_B_H + (uint32_t)(brow * 64);

    const int KT = K >> 5;
    issue_chunk(sb, lp, dA, dB);
    CP_COMMIT();
    issue_chunk(sb + STAGE, lp, dA, dB);
    CP_COMMIT();

    int stg = 0;
    for (int c = 0; c < KT; c++) {
        if (c + 1 < KT) { CP_WAIT(1); } else { CP_WAIT(0); }
        __syncthreads();
        const uint32_t so = (uint32_t)(stg * STAGE);
        const uint32_t aBs = aB0 + so, bBs = bB0 + so;

        uint32_t ah[2][4], al[2][4], ah2[2][4], al2[2][4];
        uint32_t bh[2][4], bl[2][4];
        // ---- kt0: A + B half0 ----
        ldmx4(ah[0], aBs + ax);            ldmx4(ah[1], aBs + 1024 + ax);
        ldmx4(al[0], aBs + PL_A_L + ax);   ldmx4(al[1], aBs + PL_A_L + 1024 + ax);
        ldmx4(bh[0], bBs + bx);            ldmx4(bh[1], bBs + 1024 + bx);
        ldmx4(bl[0], bBs + BLO + bx);      ldmx4(bl[1], bBs + BLO + 1024 + bx);
        mma_bundle(acc, ah, al, bh, bl, 0);
        // ---- kt0: B half1 (reuse bh/bl regs) + prefetch A-hi of kt1 ----
        ldmx4(bh[0], bBs + 2048 + bx);     ldmx4(bh[1], bBs + 3072 + bx);
        ldmx4(bl[0], bBs + BLO + 2048 + bx); ldmx4(bl[1], bBs + BLO + 3072 + bx);
        ldmx4(ah2[0], aBs + (32u ^ ax));   ldmx4(ah2[1], aBs + 1024 + (32u ^ ax));
        mma_bundle(acc, ah, al, bh, bl, 4);
        if (c + 2 < KT) {
            int ns = stg + 2; if (ns >= 3) ns -= 3;
            issue_chunk(sb + ns * STAGE, lp, dA, dB);
            CP_COMMIT();
        }
        // ---- kt1: A-lo + B half0 ----
        ldmx4(al2[0], aBs + PL_A_L + (32u ^ ax)); ldmx4(al2[1], aBs + PL_A_L + 1024 + (32u ^ ax));
        ldmx4(bh[0], bBs + (32u ^ bx));           ldmx4(bh[1], bBs + 1024 + (32u ^ bx));
        ldmx4(bl[0], bBs + BLO + (32u ^ bx));     ldmx4(bl[1], bBs + BLO + 1024 + (32u ^ bx));
        mma_bundle(acc, ah2, al2, bh, bl, 0);
        // ---- kt1: B half1 ----
        ldmx4(bh[0], bBs + 2048 + (32u ^ bx));    ldmx4(bh[1], bBs + 3072 + (32u ^ bx));
        ldmx4(bl[0], bBs + BLO + 2048 + (32u ^ bx)); ldmx4(bl[1], bBs + BLO + 3072 + (32u ^ bx));
        mma_bundle(acc, ah2, al2, bh, bl, 4);
        if (++stg == 3) stg = 0;
    }

    const int r0 = bm + wm * 32 + (lid >> 2);

    if (EPI == 2) {
        const int hloc = wn * 32 + (lid & 3);
        const int h0 = (bn >> 1);
        float sp8[8], bgf[8], bgi[8];
#pragma unroll
        for (int nt = 0; nt < 8; nt++) {
            int h = h0 + hloc + nt * 4;
            float fb = fbase[h];
            sp8[nt] = fmaxf(fb, 0.f) + log1pf(expf(-fabsf(fb)));
            bgf[nt] = bg[h]; bgi[nt] = bg[H_ + h];
        }
        const int rloc0 = wm * 32 + (lid >> 2);
#pragma unroll
        for (int mt = 0; mt < 2; mt++)
#pragma unroll
            for (int nt = 0; nt < 8; nt++)
#pragma unroll
                for (int half = 0; half < 2; half++) {
                    int rl = rloc0 + mt * 16 + half * 8;
                    float forget = acc[mt][nt][half * 2 + 0] + bgf[nt];
                    float inp    = acc[mt][nt][half * 2 + 1] + bgi[nt];
                    float a = expf(-8.f * sp8[nt] * sigmoidf_(forget));
                    float beta = sqrtf(1.f - a * a + 1e-6f);
                    size_t ix = (size_t)(bm + rl) * H_ + h0 + hloc + nt * 4;
                    float xb = __bfloat162float(xbh[ix]) + __bfloat162float(xbl[ix]);
                    acc[mt][nt][half * 2 + 0] = a;
                    acc[mt][nt][half * 2 + 1] = beta * sigmoidf_(inp) * xb;
                }
        float* st_a = (float*)sm;
        float* st_x = (float*)sm + 128 * 68;
        __syncthreads();
#pragma unroll
        for (int mt = 0; mt < 2; mt++)
#pragma unroll
            for (int nt = 0; nt < 8; nt++)
#pragma unroll
                for (int half = 0; half < 2; half++) {
                    int rl = rloc0 + mt * 16 + half * 8;
                    st_a[rl * 68 + hloc + nt * 4] = acc[mt][nt][half * 2 + 0];
                    st_x[rl * 68 + hloc + nt * 4] = acc[mt][nt][half * 2 + 1];
                }
        __syncthreads();
#pragma unroll
        for (int it = 0; it < 8; it++) {
            int idx = it * 256 + tid;
            int row = idx >> 4, cc = (idx & 15) * 4;
            float4 va = *(float4*)&st_a[row * 68 + cc];
            float4 vx = *(float4*)&st_x[row * 68 + cc];
            *(float4*)&alpha_o[(size_t)(bm + row) * H_ + h0 + cc] = va;
            *(float4*)&xs_o   [(size_t)(bm + row) * H_ + h0 + cc] = vx;
        }
        if (tid < 64) {
            float A = 1.f, Bv = 0.f;
#pragma unroll 4
            for (int t = 0; t < 128; t++) {
                float a = st_a[t * 68 + tid];
                float xv = st_x[t * 68 + tid];
                Bv = fmaf(a, Bv, xv);
                A *= a;
            }
            int n = bm >> 12;
            int cch = (bm & (T_ - 1)) >> 7;
            int ci = (n * NC + cch) * H_ + h0 + tid;
            g_cA[ci] = A;
            g_cB[ci] = Bv;
        }
        return;
    }

    if (EPI == 1 && bn >= H_) {
        float* st = (float*)sm;
        const int rl0 = wm * 32 + (lid >> 2);
        const int cl0 = wn * 64 + (lid & 3) * 2;
        __syncthreads();
#pragma unroll
        for (int mt = 0; mt < 2; mt++)
#pragma unroll
            for (int nt = 0; nt < 8; nt++)
#pragma unroll
                for (int half = 0; half < 2; half++) {
                    int rl = rl0 + mt * 16 + half * 8;
                    int cl = cl0 + nt * 8;
                    st[rl * 132 + cl]     = acc[mt][nt][half * 2 + 0];
                    st[rl * 132 + cl + 1] = acc[mt][nt][half * 2 + 1];
                }
        __syncthreads();
        const int hb = bn - H_;
        {
            int i = tid;
#pragma unroll
            for (int it = 0; it < 3; it++, i += 256) {
                int ri = i >> 7;
                int cc = i & 127;
                int row = (ri < 3) ? ri : (122 + ri);
                C[(size_t)(bm + row) * ldc + H_ + hb + cc] = st[row * 132 + cc];
            }
        }
        const int c = tid & 127;
        const int h = hb + c;
        const float w0 = cw_[h * 4 + 0], w1 = cw_[h * 4 + 1];
        const float w2 = cw_[h * 4 + 2], w3 = cw_[h * 4 + 3];
        const float bb = cb_[h];
        for (int r = 3 + (tid >> 7); r < 128; r += 2) {
            float a = bb;
            a = fmaf(w0, st[(r - 3) * 132 + c], a);
            a = fmaf(w1, st[(r - 2) * 132 + c], a);
            a = fmaf(w2, st[(r - 1) * 132 + c], a);
            a = fmaf(w3, st[(r - 0) * 132 + c], a);
            __nv_bfloat16 hi, lo;
            split_bf(a, hi, lo);
            size_t ox = (size_t)(bm + r) * H_ + h;
            oxh[ox] = hi;
            oxl[ox] = lo;
        }
        return;
    }

    const bool dg = (EPI == 1);
    const int cbase = bn + wn * 64 + (lid & 3) * 2;
#pragma unroll
    for (int mt = 0; mt < 2; mt++) {
        const int row = r0 + mt * 16;
#pragma unroll
        for (int nt = 0; nt < 8; nt++) {
            const int col = cbase + nt * 8;
            float2 v0 = make_float2(acc[mt][nt][0], acc[mt][nt][1]);
            float2 v1 = make_float2(acc[mt][nt][2], acc[mt][nt][3]);
            if (dg) {
                v0.x = 0.5f * v0.x * (1.f + erff(v0.x * 0.70710678118654752f));
                v0.y = 0.5f * v0.y * (1.f + erff(v0.y * 0.70710678118654752f));
                v1.x = 0.5f * v1.x * (1.f + erff(v1.x * 0.70710678118654752f));
                v1.y = 0.5f * v1.y * (1.f + erff(v1.y * 0.70710678118654752f));
            }
            *(float2*)(C + (size_t)row * ldc + col) = v0;
            *(float2*)(C + (size_t)(row + 8) * ldc + col) = v1;
        }
    }
}

// -------- conv boundary rows --------
__global__ void conv_boundary(const float* __restrict__ cw, const float* __restrict__ cb)
{
    int idx = blockIdx.x * blockDim.x + threadIdx.x;
    if (idx >= (M_ / 128) * 3 * H_) return;
    int h = idx % H_;
    int q = idx / H_;
    int r = q % 3;
    int tile = q / 3;
    int m = tile * 128 + r;
    int n = m / T_, t = m % T_;
    float a = cb[h];
#pragma unroll
    for (int k = 0; k < 4; k++) {
        int tt = t - 3 + k;
        if (tt >= 0)
            a = fmaf(cw[h * 4 + k], g_gx[(size_t)(n * T_ + tt) * G2H + H_ + h], a);
    }
    __nv_bfloat16 hi, lo;
    split_bf(a, hi, lo);
    g_xbh[(size_t)m * H_ + h] = hi;
    g_xbl[(size_t)m * H_ + h] = lo;
}

// -------- unified pack kernel --------
#define PK_X   ((long long)M_*D_/8)
#define PK_WI  ((long long)G2H*D_/8)
#define PK_WG  ((long long)G2H*H_/8)
#define PK_WO  ((long long)D_*H_/8)
__global__ void pack_all(const float* __restrict__ x, const float* __restrict__ wi,
                         const float* __restrict__ wg, const float* __restrict__ wo)
{
    long long i = (long long)blockIdx.x * blockDim.x + threadIdx.x;
    const float* s; __nv_bfloat16 *hi, *lo; long long off8;
    bool permute = false;
    if (i < PK_X) { s = x; hi = g_xh; lo = g_xl; off8 = i; }
    else if ((i -= PK_X) < PK_WI) { s = wi; hi = g_wih; lo = g_wil; off8 = i; }
    else if ((i -= PK_WI) < PK_WG) { s = wg; hi = g_wgh; lo = g_wgl; off8 = i; permute = true; }
    else if ((i -= PK_WG) < PK_WO) { s = wo; hi = g_woh; lo = g_wol; off8 = i; }
    else return;

    long long dste = off8 * 8;
    long long srce;
    if (permute) {
        long long r = dste / H_;
        long long cc = dste - r * H_;
        srce = ((r & 1) * H_ + (r >> 1)) * (long long)H_ + cc;
    } else srce = dste;

#pragma unroll
    for (int half = 0; half < 2; half++) {
        float4 f = *(const float4*)(s + srce + half * 4);
        __nv_bfloat16 h[4], l[4];
        split_bf(f.x, h[0], l[0]); split_bf(f.y, h[1], l[1]);
        split_bf(f.z, h[2], l[2]); split_bf(f.w, h[3], l[3]);
        *(uint2*)(hi + dste + half * 4) = *(uint2*)h;
        *(uint2*)(lo + dste + half * 4) = *(uint2*)l;
    }
}

// -------- scan replay with inline carry --------
__global__ void scan_p3()
{
    int h = blockIdx.x * 128 + threadIdx.x;
    int c = blockIdx.y, n = blockIdx.z;
    float carry = 0.f;
    for (int cc = 0; cc < c; cc++) {
        int i = (n * NC + cc) * H_ + h;
        carry = fmaf(g_cA[i], carry, g_cB[i]);
    }
    size_t base  = ((size_t)(n * T_ + c * TC)) * H_ + h;
    size_t gbase = ((size_t)(n * T_ + c * TC)) * G2H + h;
    float hp = carry;
#pragma unroll 4
    for (int t = 0; t < TC; t++) {
        float a = g_alpha[base + (size_t)t * H_];
        float x = g_xs   [base + (size_t)t * H_];
        hp = fmaf(a, hp, x);
        float g = g_gx[gbase + (size_t)t * G2H];
        float v = hp * g;
        __nv_bfloat16 hi, lo;
        split_bf(v, hi, lo);
        g_yh[base + (size_t)t * H_] = hi;
        g_yl[base + (size_t)t * H_] = lo;
    }
}

// -------- launch --------
extern "C" void kernel_launch(void* const* d_in, const int* in_sizes, int n_in,
                              void* d_out, int out_size)
{
    const float* x      = (const float*)d_in[0];
    const float* W_in   = (const float*)d_in[1];
    const float* conv_w = (const float*)d_in[2];
    const float* conv_b = (const float*)d_in[3];
    const float* W_g    = (const float*)d_in[4];
    const float* b_g    = (const float*)d_in[5];
    const float* fbase  = (const float*)d_in[6];
    const float* W_out  = (const float*)d_in[7];
    float* out = (float*)d_out;

    float *gx, *alp, *xs;
    __nv_bfloat16 *xh, *xl, *xbh, *xbl, *yh, *yl, *wih, *wil, *wgh, *wgl, *woh, *wol;
    cudaGetSymbolAddress((void**)&gx,  g_gx);
    cudaGetSymbolAddress((void**)&alp, g_alpha);
    cudaGetSymbolAddress((void**)&xs,  g_xs);
    cudaGetSymbolAddress((void**)&xh,  g_xh);
    cudaGetSymbolAddress((void**)&xl,  g_xl);
    cudaGetSymbolAddress((void**)&xbh, g_xbh);
    cudaGetSymbolAddress((void**)&xbl, g_xbl);
    cudaGetSymbolAddress((void**)&yh,  g_yh);
    cudaGetSymbolAddress((void**)&yl,  g_yl);
    cudaGetSymbolAddress((void**)&wih, g_wih);
    cudaGetSymbolAddress((void**)&wil, g_wil);
    cudaGetSymbolAddress((void**)&wgh, g_wgh);
    cudaGetSymbolAddress((void**)&wgl, g_wgl);
    cudaGetSymbolAddress((void**)&woh, g_woh);
    cudaGetSymbolAddress((void**)&wol, g_wol);

    cudaFuncSetAttribute(gemm_mma<0>, cudaFuncAttributeMaxDynamicSharedMemorySize, GEMM_SMEM);
    cudaFuncSetAttribute(gemm_mma<1>, cudaFuncAttributeMaxDynamicSharedMemorySize, GEMM_SMEM);
    cudaFuncSetAttribute(gemm_mma<2>, cudaFuncAttributeMaxDynamicSharedMemorySize, GEMM_SMEM);

    // 0) pack x + weights (single kernel)
    {
        long long total = PK_X + PK_WI + PK_WG + PK_WO;
        pack_all<<<(int)((total + 255) / 256), 256>>>(x, W_in, W_g, W_out);
    }
    // 1) gx = x @ W_in^T; gate: gelu; B-half: fused conv -> xb planes
    gemm_mma<1><<<dim3(G2H/128, M_/128), 256, GEMM_SMEM>>>(
        xh, xl, wih, wil, gx, nullptr, nullptr, nullptr, nullptr, nullptr, nullptr,
        conv_w, conv_b, xbh, xbl, D_, G2H);
    // 1b) conv boundary rows
    conv_boundary<<<((M_/128)*3*H_ + 255)/256, 256>>>(conv_w, conv_b);
    // 2) fused ew GEMM -> alpha, xs, chunk-scan reduction
    gemm_mma<2><<<dim3(G2H/128, M_/128), 256, GEMM_SMEM>>>(
        xbh, xbl, wgh, wgl, nullptr, xbh, xbl, b_g, fbase, alp, xs,
        nullptr, nullptr, nullptr, nullptr, H_, 0);
    // 3) scan replay (carry fused in)
    scan_p3<<<dim3(H_/128, NC, N_), 128>>>();
    // 4) out = (gelu(gate)*h) @ W_out^T
    gemm_mma<0><<<dim3(D_/128, M_/128), 256, GEMM_SMEM>>>(
        yh, yl, woh, wol, out, nullptr, nullptr, nullptr, nullptr, nullptr, nullptr,
        nullptr, nullptr, nullptr, nullptr, H_, D_);
}